// round 1
// baseline (speedup 1.0000x reference)
#include <cuda_runtime.h>
#include <math.h>

#define FULLMASK 0xffffffffu

constexpr int NAG  = 8;
constexpr int B    = 16384;
constexpr int SD   = 64;
constexpr int AD   = 16;
constexpr int KSA  = 80;     // SD + AD
constexpr int HID  = 128;
constexpr int HEADS= 4;
constexpr int D    = 32;
constexpr float EPS = 1e-5f;

// -------- scratch (device globals; no runtime allocation allowed) --------
__device__ __align__(16) float g_mean[NAG * KSA];
__device__ __align__(16) float g_rstd[NAG * KSA];
__device__ __align__(16) float g_e  [(size_t)NAG * B * HID];
__device__ __align__(16) float g_se [(size_t)NAG * B * HID];
__device__ __align__(16) float g_key[(size_t)NAG * B * HID];
__device__ __align__(16) float g_val[(size_t)NAG * B * HID];
__device__ __align__(16) float g_sel[(size_t)NAG * B * HID];
__device__ __align__(16) float g_oth[(size_t)NAG * B * HID];

__device__ __forceinline__ float lrelu(float x) { return x > 0.f ? x : 0.01f * x; }
__device__ __forceinline__ float4 lrelu4(float4 v) {
    return make_float4(lrelu(v.x), lrelu(v.y), lrelu(v.z), lrelu(v.w));
}
__device__ __forceinline__ void fma4(float4& acc, float s, const float4 w) {
    acc.x += s * w.x; acc.y += s * w.y; acc.z += s * w.z; acc.w += s * w.w;
}
__device__ __forceinline__ float4 add4(float4 a, float4 b) {
    return make_float4(a.x + b.x, a.y + b.y, a.z + b.z, a.w + b.w);
}

// ============================================================
// K1: BatchNorm stats per (agent, feature) over batch axis.
// grid (KSA, NAG), block 256
// ============================================================
__global__ void k_stats(const float* __restrict__ s, const float* __restrict__ a)
{
    const int f = blockIdx.x;
    const int n = blockIdx.y;
    const float* base;
    int stride;
    if (f < SD) { base = s + (size_t)n * B * SD + f;        stride = SD; }
    else        { base = a + (size_t)n * B * AD + (f - SD); stride = AD; }

    float sum = 0.f, sq = 0.f;
    for (int b = threadIdx.x; b < B; b += 256) {
        float x = base[(size_t)b * stride];
        sum += x; sq += x * x;
    }
    __shared__ float s1[256], s2[256];
    s1[threadIdx.x] = sum; s2[threadIdx.x] = sq;
    __syncthreads();
    for (int o = 128; o > 0; o >>= 1) {
        if (threadIdx.x < o) {
            s1[threadIdx.x] += s1[threadIdx.x + o];
            s2[threadIdx.x] += s2[threadIdx.x + o];
        }
        __syncthreads();
    }
    if (threadIdx.x == 0) {
        float m = s1[0] * (1.f / B);
        float v = s2[0] * (1.f / B) - m * m;
        g_mean[n * KSA + f] = m;
        g_rstd[n * KSA + f] = rsqrtf(v + EPS);
    }
}

// ============================================================
// K2a: encoders  e = lrelu(bn(sa) @ W_sa + b_sa),  se = lrelu(bn(s) @ W_se + b_se)
// grid (B/256, NAG), block 512 (16 warps x 4 rows x 4 groups = 256 rows/block)
// ============================================================
constexpr int ENC_WARPS = 16, ENC_R = 4, ENC_G = 4;
constexpr int ENC_ROWS  = ENC_WARPS * ENC_R * ENC_G;           // 256
constexpr int SMEM_ENC  = (KSA*HID + SD*HID + HID + HID + KSA + KSA
                           + ENC_WARPS*ENC_R*KSA) * 4;

__global__ void __launch_bounds__(512, 1)
k_enc(const float* __restrict__ s, const float* __restrict__ a,
      const float* __restrict__ Wsa, const float* __restrict__ Bsa,
      const float* __restrict__ Wse, const float* __restrict__ Bse)
{
    extern __shared__ float sm[];
    float* wsa = sm;                    // 80*128
    float* wse = wsa + KSA * HID;       // 64*128
    float* bsa = wse + SD * HID;        // 128
    float* bse = bsa + HID;             // 128
    float* mn  = bse + HID;             // 80
    float* rs  = mn + KSA;              // 80
    float* rows= rs + KSA;              // 16*4*80

    const int n = blockIdx.y, tid = threadIdx.x;
    for (int i = tid; i < KSA * HID; i += blockDim.x) wsa[i] = Wsa[n * KSA * HID + i];
    for (int i = tid; i < SD * HID;  i += blockDim.x) wse[i] = Wse[n * SD * HID + i];
    if (tid < HID) { bsa[tid] = Bsa[n * HID + tid]; bse[tid] = Bse[n * HID + tid]; }
    if (tid >= HID && tid < HID + KSA) {
        int f = tid - HID;
        mn[f] = g_mean[n * KSA + f];
        rs[f] = g_rstd[n * KSA + f];
    }
    __syncthreads();

    const int warp = tid >> 5, lane = tid & 31;
    float* rb = rows + warp * (ENC_R * KSA);
    const float4* wsa4 = (const float4*)wsa;
    const float4* wse4 = (const float4*)wse;
    const float4  bsa4 = ((const float4*)bsa)[lane];
    const float4  bse4 = ((const float4*)bse)[lane];

    for (int g = 0; g < ENC_G; g++) {
        const int b0 = blockIdx.x * ENC_ROWS + g * (ENC_WARPS * ENC_R) + warp * ENC_R;
        __syncwarp();
        #pragma unroll
        for (int r = 0; r < ENC_R; r++) {
            int b = b0 + r;
            for (int idx = lane; idx < KSA; idx += 32) {
                float x = (idx < SD) ? s[((size_t)n * B + b) * SD + idx]
                                     : a[((size_t)n * B + b) * AD + (idx - SD)];
                rb[r * KSA + idx] = (x - mn[idx]) * rs[idx];
            }
        }
        __syncwarp();

        float4 ae[ENC_R], as_[ENC_R];
        #pragma unroll
        for (int r = 0; r < ENC_R; r++) { ae[r] = make_float4(0,0,0,0); as_[r] = make_float4(0,0,0,0); }

        for (int k = 0; k < SD; k++) {
            float4 w1 = wsa4[k * 32 + lane];
            float4 w2 = wse4[k * 32 + lane];
            #pragma unroll
            for (int r = 0; r < ENC_R; r++) {
                float xk = rb[r * KSA + k];
                fma4(ae[r], xk, w1);
                fma4(as_[r], xk, w2);
            }
        }
        for (int k = SD; k < KSA; k++) {
            float4 w1 = wsa4[k * 32 + lane];
            #pragma unroll
            for (int r = 0; r < ENC_R; r++) fma4(ae[r], rb[r * KSA + k], w1);
        }
        #pragma unroll
        for (int r = 0; r < ENC_R; r++) {
            size_t row = (size_t)n * B + (b0 + r);
            ((float4*)g_e )[row * 32 + lane] = lrelu4(add4(ae[r],  bsa4));
            ((float4*)g_se)[row * 32 + lane] = lrelu4(add4(as_[r], bse4));
        }
    }
}

// ============================================================
// K2b: projections  key = e@WkAll, val = lrelu(e@WvAll + bv), sel = se@WselAll
// weights shared across agents -> rows flattened over (n,b)
// grid 1024, block 256 (8 warps x 4 rows x 4 groups = 128 rows/block)
// ============================================================
constexpr int PRJ_WARPS = 8, PRJ_R = 4, PRJ_G = 4;
constexpr int PRJ_ROWS  = PRJ_WARPS * PRJ_R * PRJ_G;           // 128
constexpr int SMEM_PRJ  = (3 * HID * HID + HID + PRJ_WARPS * PRJ_R * 2 * HID) * 4;

__global__ void __launch_bounds__(256, 1)
k_proj(const float* __restrict__ Wk, const float* __restrict__ Wsel,
       const float* __restrict__ Wv, const float* __restrict__ bv)
{
    extern __shared__ float sm[];
    float* wk  = sm;                    // [h][p*32+d]  128x128
    float* wv  = wk  + HID * HID;
    float* wsl = wv  + HID * HID;
    float* bvv = wsl + HID * HID;       // 128
    float* rows= bvv + HID;             // 8 warps * 4 rows * 256

    const int tid = threadIdx.x;
    // reorganize [p][h][d] -> [h][p*32+d]
    for (int i = tid; i < HEADS * HID * D; i += blockDim.x) {
        int p = i >> 12;          // /(HID*D)
        int h = (i >> 5) & 127;
        int d = i & 31;
        int dst = h * HID + p * D + d;
        wk [dst] = Wk  [i];
        wv [dst] = Wv  [i];
        wsl[dst] = Wsel[i];
    }
    if (tid < HID) bvv[tid] = bv[tid];
    __syncthreads();

    const int warp = tid >> 5, lane = tid & 31;
    float* erow = rows + warp * (PRJ_R * 2 * HID);   // [r][e(128) | se(128)]
    const float4* wk4 = (const float4*)wk;
    const float4* wv4 = (const float4*)wv;
    const float4* ws4 = (const float4*)wsl;
    const float4  bv4 = ((const float4*)bvv)[lane];

    for (int g = 0; g < PRJ_G; g++) {
        const size_t row0 = (size_t)blockIdx.x * PRJ_ROWS + g * (PRJ_WARPS * PRJ_R) + warp * PRJ_R;
        __syncwarp();
        #pragma unroll
        for (int r = 0; r < PRJ_R; r++) {
            ((float4*)(erow + r * 2 * HID      ))[lane] = ((const float4*)g_e )[(row0 + r) * 32 + lane];
            ((float4*)(erow + r * 2 * HID + HID))[lane] = ((const float4*)g_se)[(row0 + r) * 32 + lane];
        }
        __syncwarp();

        float4 ak[PRJ_R], av[PRJ_R], asl[PRJ_R];
        #pragma unroll
        for (int r = 0; r < PRJ_R; r++) {
            ak[r] = make_float4(0,0,0,0); av[r] = make_float4(0,0,0,0); asl[r] = make_float4(0,0,0,0);
        }
        for (int k = 0; k < HID; k++) {
            float4 w1 = wk4[k * 32 + lane];
            float4 w2 = wv4[k * 32 + lane];
            float4 w3 = ws4[k * 32 + lane];
            #pragma unroll
            for (int r = 0; r < PRJ_R; r++) {
                float xe = erow[r * 2 * HID + k];
                float xs = erow[r * 2 * HID + HID + k];
                fma4(ak[r],  xe, w1);
                fma4(av[r],  xe, w2);
                fma4(asl[r], xs, w3);
            }
        }
        #pragma unroll
        for (int r = 0; r < PRJ_R; r++) {
            ((float4*)g_key)[(row0 + r) * 32 + lane] = ak[r];
            ((float4*)g_val)[(row0 + r) * 32 + lane] = lrelu4(add4(av[r], bv4));
            ((float4*)g_sel)[(row0 + r) * 32 + lane] = asl[r];
        }
    }
}

// ============================================================
// K3: attention — one warp per (head p, batch b); 8x8 agent softmax
// grid HEADS*B/8 = 8192, block 256
// ============================================================
__global__ void __launch_bounds__(256, 4)
k_attn()
{
    __shared__ float smem[8][3 * 8 * 33 + 64];
    const int tid = threadIdx.x, warp = tid >> 5, lane = tid & 31;
    const int gid = blockIdx.x * 8 + warp;
    const int b = gid >> 2;
    const int p = gid & 3;

    float* selS = smem[warp];
    float* keyS = selS + 8 * 33;
    float* valS = keyS + 8 * 33;
    float* wS   = valS + 8 * 33;
    const float scale = 0.17677669529663687f;   // 1/sqrt(32)

    #pragma unroll
    for (int i = 0; i < 8; i++) {
        size_t base = ((size_t)i * B + b) * HID + p * D + lane;
        selS[i * 33 + lane] = g_sel[base];
        keyS[i * 33 + lane] = g_key[base];
        valS[i * 33 + lane] = g_val[base];
    }
    __syncwarp();

    const int i0 = lane >> 3, j = lane & 7, i1 = i0 + 4;
    float acc0 = 0.f, acc1 = 0.f;
    #pragma unroll
    for (int d = 0; d < 32; d++) {
        float kv = keyS[j * 33 + d];
        acc0 += selS[i0 * 33 + d] * kv;
        acc1 += selS[i1 * 33 + d] * kv;
    }
    acc0 *= scale; acc1 *= scale;
    if (i0 == j) acc0 = -1e9f;
    if (i1 == j) acc1 = -1e9f;

    float m0 = acc0, m1 = acc1;
    #pragma unroll
    for (int o = 1; o < 8; o <<= 1) {
        m0 = fmaxf(m0, __shfl_xor_sync(FULLMASK, m0, o));
        m1 = fmaxf(m1, __shfl_xor_sync(FULLMASK, m1, o));
    }
    float e0 = expf(acc0 - m0), e1 = expf(acc1 - m1);
    float s0 = e0, s1 = e1;
    #pragma unroll
    for (int o = 1; o < 8; o <<= 1) {
        s0 += __shfl_xor_sync(FULLMASK, s0, o);
        s1 += __shfl_xor_sync(FULLMASK, s1, o);
    }
    wS[lane]      = e0 / s0;
    wS[lane + 32] = e1 / s1;
    __syncwarp();

    float out[8];
    #pragma unroll
    for (int ii = 0; ii < 8; ii++) out[ii] = 0.f;
    #pragma unroll
    for (int jj = 0; jj < 8; jj++) {
        float v = valS[jj * 33 + lane];
        #pragma unroll
        for (int ii = 0; ii < 8; ii++) out[ii] += wS[ii * 8 + jj] * v;
    }
    #pragma unroll
    for (int ii = 0; ii < 8; ii++)
        g_oth[((size_t)ii * B + b) * HID + p * D + lane] = out[ii];
}

// ============================================================
// K4: critic + argmax gather
// grid (B/128, NAG), block 512 (16 warps x 4 rows x 2 groups)
// ============================================================
constexpr int CR_WARPS = 16, CR_R = 4, CR_G = 2;
constexpr int CR_ROWS  = CR_WARPS * CR_R * CR_G;               // 128
constexpr int SMEM_CR  = (2*HID*HID + HID*AD + HID + 16 + CR_WARPS*CR_R*2*HID) * 4;

__global__ void __launch_bounds__(512, 1)
k_crit(const float* __restrict__ a,
       const float* __restrict__ Wc1, const float* __restrict__ Bc1,
       const float* __restrict__ Wc2, const float* __restrict__ Bc2,
       float* __restrict__ out)
{
    extern __shared__ float sm[];
    float* w1  = sm;                    // 256*128
    float* w2  = w1 + 2 * HID * HID;    // 128*16
    float* b1  = w2 + HID * AD;         // 128
    float* b2  = b1 + HID;              // 16
    float* rows= b2 + 16;               // 16 warps * 4 rows * 256 (reused for h)

    const int n = blockIdx.y, tid = threadIdx.x;
    for (int i = tid; i < 2 * HID * HID; i += blockDim.x) w1[i] = Wc1[(size_t)n * 2 * HID * HID + i];
    for (int i = tid; i < HID * AD;      i += blockDim.x) w2[i] = Wc2[n * HID * AD + i];
    if (tid < HID) b1[tid] = Bc1[n * HID + tid];
    if (tid >= HID && tid < HID + AD) b2[tid - HID] = Bc2[n * AD + (tid - HID)];
    __syncthreads();

    const int warp = tid >> 5, lane = tid & 31;
    float* rb = rows + warp * (CR_R * 2 * HID);
    const float4* w14 = (const float4*)w1;
    const float4  b14 = ((const float4*)b1)[lane];

    for (int g = 0; g < CR_G; g++) {
        const int b0 = blockIdx.x * CR_ROWS + g * (CR_WARPS * CR_R) + warp * CR_R;
        __syncwarp();
        #pragma unroll
        for (int r = 0; r < CR_R; r++) {
            size_t row = (size_t)n * B + (b0 + r);
            ((float4*)(rb + r * 2 * HID      ))[lane] = ((const float4*)g_se )[row * 32 + lane];
            ((float4*)(rb + r * 2 * HID + HID))[lane] = ((const float4*)g_oth)[row * 32 + lane];
        }
        __syncwarp();

        float4 acc[CR_R];
        #pragma unroll
        for (int r = 0; r < CR_R; r++) acc[r] = make_float4(0,0,0,0);
        for (int k = 0; k < 2 * HID; k++) {
            float4 w = w14[k * 32 + lane];
            #pragma unroll
            for (int r = 0; r < CR_R; r++) fma4(acc[r], rb[r * 2 * HID + k], w);
        }
        __syncwarp();
        // write h into first 128 floats of each row buffer (reuse)
        #pragma unroll
        for (int r = 0; r < CR_R; r++)
            ((float4*)(rb + r * 2 * HID))[lane] = lrelu4(add4(acc[r], b14));
        __syncwarp();

        #pragma unroll
        for (int r = 0; r < CR_R; r++) {
            const int b = b0 + r;
            const float* hr = rb + r * 2 * HID;
            const int o = lane & 15, half = lane >> 4;
            float q = 0.f;
            const int kb = half * 64;
            for (int k = kb; k < kb + 64; k++)
                q += hr[k] * w2[k * AD + o];
            q += __shfl_xor_sync(FULLMASK, q, 16);
            q += b2[o];

            // argmax over a[n,b,:16] (first occurrence on ties)
            float av = (lane < AD) ? a[((size_t)n * B + b) * AD + lane] : -1e30f;
            int   ai = (lane < AD) ? lane : 1000;
            float bestv = av; int besti = ai;
            #pragma unroll
            for (int off = 16; off > 0; off >>= 1) {
                float ov = __shfl_xor_sync(FULLMASK, bestv, off);
                int   oi = __shfl_xor_sync(FULLMASK, besti, off);
                if (ov > bestv || (ov == bestv && oi < besti)) { bestv = ov; besti = oi; }
            }
            float qsel = __shfl_sync(FULLMASK, q, besti);   // lane 'besti' (<16) holds output besti
            if (lane == 0) out[(size_t)n * B + b] = qsel;
        }
    }
}

// ============================================================
extern "C" void kernel_launch(void* const* d_in, const int* in_sizes, int n_in,
                              void* d_out, int out_size)
{
    const float* s    = (const float*)d_in[0];
    const float* a    = (const float*)d_in[1];
    const float* Wsa  = (const float*)d_in[2];
    const float* Bsa  = (const float*)d_in[3];
    const float* Wse  = (const float*)d_in[4];
    const float* Bse  = (const float*)d_in[5];
    const float* Wk   = (const float*)d_in[6];
    const float* Wsel = (const float*)d_in[7];
    const float* Wv   = (const float*)d_in[8];
    const float* bv   = (const float*)d_in[9];
    const float* Wc1  = (const float*)d_in[10];
    const float* Bc1  = (const float*)d_in[11];
    const float* Wc2  = (const float*)d_in[12];
    const float* Bc2  = (const float*)d_in[13];
    float* out = (float*)d_out;

    cudaFuncSetAttribute(k_enc,  cudaFuncAttributeMaxDynamicSharedMemorySize, SMEM_ENC);
    cudaFuncSetAttribute(k_proj, cudaFuncAttributeMaxDynamicSharedMemorySize, SMEM_PRJ);
    cudaFuncSetAttribute(k_crit, cudaFuncAttributeMaxDynamicSharedMemorySize, SMEM_CR);

    k_stats<<<dim3(KSA, NAG), 256>>>(s, a);
    k_enc  <<<dim3(B / ENC_ROWS, NAG), 512, SMEM_ENC>>>(s, a, Wsa, Bsa, Wse, Bse);
    k_proj <<<dim3((NAG * B) / PRJ_ROWS), 256, SMEM_PRJ>>>(Wk, Wsel, Wv, bv);
    k_attn <<<dim3((HEADS * B) / 8), 256>>>();
    k_crit <<<dim3(B / CR_ROWS, NAG), 512, SMEM_CR>>>(a, Wc1, Bc1, Wc2, Bc2, out);
}

// round 3
// speedup vs baseline: 1.3801x; 1.3801x over previous
#include <cuda_runtime.h>
#include <math.h>
#include <stdint.h>

#define FULLMASK 0xffffffffu

constexpr int NAG  = 8;
constexpr int B    = 16384;
constexpr int SD   = 64;
constexpr int AD   = 16;
constexpr int KSA  = 80;     // SD + AD
constexpr int HID  = 128;
constexpr int HEADS= 4;
constexpr int D    = 32;
constexpr float EPS = 1e-5f;

// -------- scratch (device globals; no runtime allocation allowed) --------
__device__ __align__(16) float g_mean[NAG * KSA];
__device__ __align__(16) float g_rstd[NAG * KSA];
__device__ __align__(16) float g_e  [(size_t)NAG * B * HID];
__device__ __align__(16) float g_se [(size_t)NAG * B * HID];
__device__ __align__(16) float g_key[(size_t)NAG * B * HID];
__device__ __align__(16) float g_val[(size_t)NAG * B * HID];
__device__ __align__(16) float g_sel[(size_t)NAG * B * HID];
__device__ __align__(16) float g_oth[(size_t)NAG * B * HID];

__device__ __forceinline__ float lrelu(float x) { return x > 0.f ? x : 0.01f * x; }
__device__ __forceinline__ float4 lrelu4(float4 v) {
    return make_float4(lrelu(v.x), lrelu(v.y), lrelu(v.z), lrelu(v.w));
}
__device__ __forceinline__ void fma4(float4& acc, float s, const float4 w) {
    acc.x += s * w.x; acc.y += s * w.y; acc.z += s * w.z; acc.w += s * w.w;
}
__device__ __forceinline__ float4 add4(float4 a, float4 b) {
    return make_float4(a.x + b.x, a.y + b.y, a.z + b.z, a.w + b.w);
}

// ================= tf32 mma.sync helpers (arch-neutral PTX, sm_80+) =================
__device__ __forceinline__ uint32_t tf32rn(float x) {
    uint32_t u; asm("cvt.rna.tf32.f32 %0, %1;" : "=r"(u) : "f"(x)); return u;
}
// D(16x8) += A(16x8,row) * B(8x8,col);  A 4 regs, B 2 regs, D 4 f32
__device__ __forceinline__ void mma8(float4& d, const uint4 a, const uint2 b) {
    asm volatile(
        "mma.sync.aligned.m16n8k8.row.col.f32.tf32.tf32.f32 "
        "{%0,%1,%2,%3}, {%4,%5,%6,%7}, {%8,%9}, {%0,%1,%2,%3};"
        : "+f"(d.x), "+f"(d.y), "+f"(d.z), "+f"(d.w)
        : "r"(a.x), "r"(a.y), "r"(a.z), "r"(a.w), "r"(b.x), "r"(b.y));
}

// A fragments for a 128-row x 128-col tile (16 k-steps of 8).
// Af[((g16*16 + ks)*32 + lane)] : uint4 = {A[r][c], A[r+8][c], A[r][c+4], A[r+8][c+4]}
// with r = g16*16 + (lane>>2), c = ks*8 + (lane&3).  src: row-major, stride 128.
__device__ __forceinline__ void fill_Afrag(uint4* Af, const float* __restrict__ src,
                                           size_t row0, int tid) {
    for (int i = tid; i < 8 * 16 * 32; i += 512) {
        int lane = i & 31;
        int ks   = (i >> 5) & 15;
        int g16  = i >> 9;
        int g = lane >> 2, tig = lane & 3;
        const float* p0 = src + (row0 + g16 * 16 + g) * 128;
        const float* p1 = p0 + 8 * 128;
        int c = ks * 8 + tig;
        Af[i] = make_uint4(tf32rn(p0[c]), tf32rn(p1[c]),
                           tf32rn(p0[c + 4]), tf32rn(p1[c + 4]));
    }
}

// B fragments for 128 outs x 128 K from proj weight layout [p][h][d] (p=out>>5, d=out&31, k=h).
// Bf[((n8*16 + ks)*32 + lane)] : uint2 = {W'[n][k], W'[n][k+4]},
// n = n8*8 + (lane>>2), k = ks*8 + (lane&3).
__device__ __forceinline__ void fill_Wfrag_proj(uint2* Bf, const float* __restrict__ W, int tid) {
    for (int i = tid; i < 16 * 16 * 32; i += 512) {
        int lane = i & 31;
        int ks   = (i >> 5) & 15;
        int n8   = i >> 9;
        int g = lane >> 2, tig = lane & 3;
        int n = n8 * 8 + g, k = ks * 8 + tig;
        const float* base = W + (n >> 5) * (HID * D) + (n & 31);
        Bf[i] = make_uint2(tf32rn(base[k * 32]), tf32rn(base[(k + 4) * 32]));
    }
}

// B fragments for critic W1: source [k][o] row-major (o stride 1, 128 outs), k offset kofs.
__device__ __forceinline__ void fill_Wfrag_crit(uint2* Bf, const float* __restrict__ W,
                                                int kofs, int tid) {
    for (int i = tid; i < 16 * 16 * 32; i += 512) {
        int lane = i & 31;
        int ks   = (i >> 5) & 15;
        int n8   = i >> 9;
        int g = lane >> 2, tig = lane & 3;
        int n = n8 * 8 + g, k = kofs + ks * 8 + tig;
        Bf[i] = make_uint2(tf32rn(W[k * 128 + n]), tf32rn(W[(k + 4) * 128 + n]));
    }
}

// ============================================================
// K1: BatchNorm stats per (agent, feature) over batch axis.
// ============================================================
__global__ void k_stats(const float* __restrict__ s, const float* __restrict__ a)
{
    const int f = blockIdx.x;
    const int n = blockIdx.y;
    const float* base;
    int stride;
    if (f < SD) { base = s + (size_t)n * B * SD + f;        stride = SD; }
    else        { base = a + (size_t)n * B * AD + (f - SD); stride = AD; }

    float sum = 0.f, sq = 0.f;
    for (int b = threadIdx.x; b < B; b += 256) {
        float x = base[(size_t)b * stride];
        sum += x; sq += x * x;
    }
    __shared__ float s1[256], s2[256];
    s1[threadIdx.x] = sum; s2[threadIdx.x] = sq;
    __syncthreads();
    for (int o = 128; o > 0; o >>= 1) {
        if (threadIdx.x < o) {
            s1[threadIdx.x] += s1[threadIdx.x + o];
            s2[threadIdx.x] += s2[threadIdx.x + o];
        }
        __syncthreads();
    }
    if (threadIdx.x == 0) {
        float m = s1[0] * (1.f / B);
        float v = s2[0] * (1.f / B) - m * m;
        g_mean[n * KSA + f] = m;
        g_rstd[n * KSA + f] = rsqrtf(v + EPS);
    }
}

// ============================================================
// K2a: encoders (scalar FFMA, unchanged this round)
// ============================================================
constexpr int ENC_WARPS = 16, ENC_R = 4, ENC_G = 4;
constexpr int ENC_ROWS  = ENC_WARPS * ENC_R * ENC_G;           // 256
constexpr int SMEM_ENC  = (KSA*HID + SD*HID + HID + HID + KSA + KSA
                           + ENC_WARPS*ENC_R*KSA) * 4;

__global__ void __launch_bounds__(512, 1)
k_enc(const float* __restrict__ s, const float* __restrict__ a,
      const float* __restrict__ Wsa, const float* __restrict__ Bsa,
      const float* __restrict__ Wse, const float* __restrict__ Bse)
{
    extern __shared__ float sm[];
    float* wsa = sm;
    float* wse = wsa + KSA * HID;
    float* bsa = wse + SD * HID;
    float* bse = bsa + HID;
    float* mn  = bse + HID;
    float* rs  = mn + KSA;
    float* rows= rs + KSA;

    const int n = blockIdx.y, tid = threadIdx.x;
    for (int i = tid; i < KSA * HID; i += blockDim.x) wsa[i] = Wsa[n * KSA * HID + i];
    for (int i = tid; i < SD * HID;  i += blockDim.x) wse[i] = Wse[n * SD * HID + i];
    if (tid < HID) { bsa[tid] = Bsa[n * HID + tid]; bse[tid] = Bse[n * HID + tid]; }
    if (tid >= HID && tid < HID + KSA) {
        int f = tid - HID;
        mn[f] = g_mean[n * KSA + f];
        rs[f] = g_rstd[n * KSA + f];
    }
    __syncthreads();

    const int warp = tid >> 5, lane = tid & 31;
    float* rb = rows + warp * (ENC_R * KSA);
    const float4* wsa4 = (const float4*)wsa;
    const float4* wse4 = (const float4*)wse;
    const float4  bsa4 = ((const float4*)bsa)[lane];
    const float4  bse4 = ((const float4*)bse)[lane];

    for (int g = 0; g < ENC_G; g++) {
        const int b0 = blockIdx.x * ENC_ROWS + g * (ENC_WARPS * ENC_R) + warp * ENC_R;
        __syncwarp();
        #pragma unroll
        for (int r = 0; r < ENC_R; r++) {
            int b = b0 + r;
            for (int idx = lane; idx < KSA; idx += 32) {
                float x = (idx < SD) ? s[((size_t)n * B + b) * SD + idx]
                                     : a[((size_t)n * B + b) * AD + (idx - SD)];
                rb[r * KSA + idx] = (x - mn[idx]) * rs[idx];
            }
        }
        __syncwarp();

        float4 ae[ENC_R], as_[ENC_R];
        #pragma unroll
        for (int r = 0; r < ENC_R; r++) { ae[r] = make_float4(0,0,0,0); as_[r] = make_float4(0,0,0,0); }

        for (int k = 0; k < SD; k++) {
            float4 w1 = wsa4[k * 32 + lane];
            float4 w2 = wse4[k * 32 + lane];
            #pragma unroll
            for (int r = 0; r < ENC_R; r++) {
                float xk = rb[r * KSA + k];
                fma4(ae[r], xk, w1);
                fma4(as_[r], xk, w2);
            }
        }
        for (int k = SD; k < KSA; k++) {
            float4 w1 = wsa4[k * 32 + lane];
            #pragma unroll
            for (int r = 0; r < ENC_R; r++) fma4(ae[r], rb[r * KSA + k], w1);
        }
        #pragma unroll
        for (int r = 0; r < ENC_R; r++) {
            size_t row = (size_t)n * B + (b0 + r);
            ((float4*)g_e )[row * 32 + lane] = lrelu4(add4(ae[r],  bsa4));
            ((float4*)g_se)[row * 32 + lane] = lrelu4(add4(as_[r], bse4));
        }
    }
}

// ============================================================
// K2b: projections on tf32 mma.sync
// projkv : key = e@Wk', val = lrelu(e@Wv' + bv)  (shared A tile)
// projsel: sel = se@Wsel'
// Block = 512 threads (16 warps), 128 rows per block.
// ============================================================
constexpr int SMEM_PKV  = 3 * 65536 + 512;
constexpr int SMEM_PSEL = 2 * 65536;

__global__ void __launch_bounds__(512, 1)
k_projkv(const float* __restrict__ Wk, const float* __restrict__ Wv,
         const float* __restrict__ bv)
{
    extern __shared__ char smc[];
    uint4* Af = (uint4*)smc;                    // 64KB
    uint2* BK = (uint2*)(smc + 65536);          // 64KB
    uint2* BV = (uint2*)(smc + 131072);         // 64KB
    float* bvs = (float*)(smc + 196608);        // 512B

    const int tid = threadIdx.x, w = tid >> 5, lane = tid & 31;
    const size_t row0 = (size_t)blockIdx.x * 128;

    fill_Afrag(Af, g_e, row0, tid);
    fill_Wfrag_proj(BK, Wk, tid);
    fill_Wfrag_proj(BV, Wv, tid);
    if (tid < 128) bvs[tid] = bv[tid];
    __syncthreads();

    const int rs = w & 3;          // 32-row strip: g16 = 2*rs, 2*rs+1
    const int t0 = w >> 2;         // 32-col tile (0..3) in both key and val

    float4 ack[2][4], acv[2][4];
    #pragma unroll
    for (int mi = 0; mi < 2; mi++)
        #pragma unroll
        for (int j = 0; j < 4; j++) {
            ack[mi][j] = make_float4(0,0,0,0);
            acv[mi][j] = make_float4(0,0,0,0);
        }

    for (int ks = 0; ks < 16; ks++) {
        uint4 a0 = Af[((2 * rs)     * 16 + ks) * 32 + lane];
        uint4 a1 = Af[((2 * rs + 1) * 16 + ks) * 32 + lane];
        #pragma unroll
        for (int j = 0; j < 4; j++) {
            int bi = ((t0 * 4 + j) * 16 + ks) * 32 + lane;
            uint2 bk = BK[bi];
            uint2 bw = BV[bi];
            mma8(ack[0][j], a0, bk); mma8(ack[1][j], a1, bk);
            mma8(acv[0][j], a0, bw); mma8(acv[1][j], a1, bw);
        }
    }

    const int g = lane >> 2, tig = lane & 3;
    #pragma unroll
    for (int mi = 0; mi < 2; mi++) {
        #pragma unroll
        for (int j = 0; j < 4; j++) {
            size_t r = row0 + rs * 32 + mi * 16 + g;
            int c = t0 * 32 + j * 8 + 2 * tig;
            float2* pk0 = (float2*)&g_key[r * 128 + c];
            float2* pk1 = (float2*)&g_key[(r + 8) * 128 + c];
            *pk0 = make_float2(ack[mi][j].x, ack[mi][j].y);
            *pk1 = make_float2(ack[mi][j].z, ack[mi][j].w);
            float bb0 = bvs[c], bb1 = bvs[c + 1];
            float2* pv0 = (float2*)&g_val[r * 128 + c];
            float2* pv1 = (float2*)&g_val[(r + 8) * 128 + c];
            *pv0 = make_float2(lrelu(acv[mi][j].x + bb0), lrelu(acv[mi][j].y + bb1));
            *pv1 = make_float2(lrelu(acv[mi][j].z + bb0), lrelu(acv[mi][j].w + bb1));
        }
    }
}

__global__ void __launch_bounds__(512, 1)
k_projsel(const float* __restrict__ Wsel)
{
    extern __shared__ char smc[];
    uint4* Af = (uint4*)smc;                    // 64KB
    uint2* BS = (uint2*)(smc + 65536);          // 64KB

    const int tid = threadIdx.x, w = tid >> 5, lane = tid & 31;
    const size_t row0 = (size_t)blockIdx.x * 128;

    fill_Afrag(Af, g_se, row0, tid);
    fill_Wfrag_proj(BS, Wsel, tid);
    __syncthreads();

    const int rs = w & 3;
    const int t0 = w >> 2;

    float4 acc[2][4];
    #pragma unroll
    for (int mi = 0; mi < 2; mi++)
        #pragma unroll
        for (int j = 0; j < 4; j++) acc[mi][j] = make_float4(0,0,0,0);

    for (int ks = 0; ks < 16; ks++) {
        uint4 a0 = Af[((2 * rs)     * 16 + ks) * 32 + lane];
        uint4 a1 = Af[((2 * rs + 1) * 16 + ks) * 32 + lane];
        #pragma unroll
        for (int j = 0; j < 4; j++) {
            uint2 bs_ = BS[((t0 * 4 + j) * 16 + ks) * 32 + lane];
            mma8(acc[0][j], a0, bs_); mma8(acc[1][j], a1, bs_);
        }
    }

    const int g = lane >> 2, tig = lane & 3;
    #pragma unroll
    for (int mi = 0; mi < 2; mi++) {
        #pragma unroll
        for (int j = 0; j < 4; j++) {
            size_t r = row0 + rs * 32 + mi * 16 + g;
            int c = t0 * 32 + j * 8 + 2 * tig;
            *(float2*)&g_sel[r * 128 + c]       = make_float2(acc[mi][j].x, acc[mi][j].y);
            *(float2*)&g_sel[(r + 8) * 128 + c] = make_float2(acc[mi][j].z, acc[mi][j].w);
        }
    }
}

// ============================================================
// K3: attention — one warp per (head p, batch b); 8x8 agent softmax
// ============================================================
__global__ void __launch_bounds__(256, 4)
k_attn()
{
    __shared__ float smem[8][3 * 8 * 33 + 64];
    const int tid = threadIdx.x, warp = tid >> 5, lane = tid & 31;
    const int gid = blockIdx.x * 8 + warp;
    const int b = gid >> 2;
    const int p = gid & 3;

    float* selS = smem[warp];
    float* keyS = selS + 8 * 33;
    float* valS = keyS + 8 * 33;
    float* wS   = valS + 8 * 33;
    const float scale = 0.17677669529663687f;   // 1/sqrt(32)

    #pragma unroll
    for (int i = 0; i < 8; i++) {
        size_t base = ((size_t)i * B + b) * HID + p * D + lane;
        selS[i * 33 + lane] = g_sel[base];
        keyS[i * 33 + lane] = g_key[base];
        valS[i * 33 + lane] = g_val[base];
    }
    __syncwarp();

    const int i0 = lane >> 3, j = lane & 7, i1 = i0 + 4;
    float acc0 = 0.f, acc1 = 0.f;
    #pragma unroll
    for (int d = 0; d < 32; d++) {
        float kv = keyS[j * 33 + d];
        acc0 += selS[i0 * 33 + d] * kv;
        acc1 += selS[i1 * 33 + d] * kv;
    }
    acc0 *= scale; acc1 *= scale;
    if (i0 == j) acc0 = -1e9f;
    if (i1 == j) acc1 = -1e9f;

    float m0 = acc0, m1 = acc1;
    #pragma unroll
    for (int o = 1; o < 8; o <<= 1) {
        m0 = fmaxf(m0, __shfl_xor_sync(FULLMASK, m0, o));
        m1 = fmaxf(m1, __shfl_xor_sync(FULLMASK, m1, o));
    }
    float e0 = expf(acc0 - m0), e1 = expf(acc1 - m1);
    float s0 = e0, s1 = e1;
    #pragma unroll
    for (int o = 1; o < 8; o <<= 1) {
        s0 += __shfl_xor_sync(FULLMASK, s0, o);
        s1 += __shfl_xor_sync(FULLMASK, s1, o);
    }
    wS[lane]      = e0 / s0;
    wS[lane + 32] = e1 / s1;
    __syncwarp();

    float out[8];
    #pragma unroll
    for (int ii = 0; ii < 8; ii++) out[ii] = 0.f;
    #pragma unroll
    for (int jj = 0; jj < 8; jj++) {
        float v = valS[jj * 33 + lane];
        #pragma unroll
        for (int ii = 0; ii < 8; ii++) out[ii] += wS[ii * 8 + jj] * v;
    }
    #pragma unroll
    for (int ii = 0; ii < 8; ii++)
        g_oth[((size_t)ii * B + b) * HID + p * D + lane] = out[ii];
}

// ============================================================
// K4: critic on tf32 mma.sync (W1 GEMM) + scalar layer2 + argmax
// Block 512 threads, 128 rows; K=256 handled in two phases of 128.
// ============================================================
constexpr int HSTR = 132;                               // padded h row stride (floats)
constexpr int OFF_AF  = 0;                              // 64KB A fragments
constexpr int OFF_B1  = 65536;                          // 64KB W1 fragments
constexpr int OFF_H   = 131072;                         // 128*132*4 = 67584
constexpr int OFF_W2  = OFF_H + 128 * HSTR * 4;         // 16*132*4 = 8448
constexpr int OFF_B1S = OFF_W2 + 16 * HSTR * 4;         // 512
constexpr int OFF_B2S = OFF_B1S + 512;                  // 64
constexpr int SMEM_CRIT = OFF_B2S + 64;

__global__ void __launch_bounds__(512, 1)
k_crit(const float* __restrict__ a,
       const float* __restrict__ Wc1, const float* __restrict__ Bc1,
       const float* __restrict__ Wc2, const float* __restrict__ Bc2,
       float* __restrict__ out)
{
    extern __shared__ char smc[];
    uint4* Af  = (uint4*)(smc + OFF_AF);
    uint2* B1  = (uint2*)(smc + OFF_B1);
    float* h   = (float*)(smc + OFF_H);
    float* w2t = (float*)(smc + OFF_W2);
    float* b1s = (float*)(smc + OFF_B1S);
    float* b2s = (float*)(smc + OFF_B2S);

    const int n = blockIdx.y, tid = threadIdx.x;
    const int w = tid >> 5, lane = tid & 31;
    const size_t row0 = (size_t)n * B + (size_t)blockIdx.x * 128;
    const float* W1 = Wc1 + (size_t)n * 2 * HID * HID;

    // small fills (once)
    for (int i = tid; i < HID * AD; i += 512) {
        int k = i >> 4, o = i & 15;
        w2t[o * HSTR + k] = Wc2[n * HID * AD + k * AD + o];
    }
    if (tid < HID) b1s[tid] = Bc1[n * HID + tid];
    if (tid >= HID && tid < HID + AD) b2s[tid - HID] = Bc2[n * AD + (tid - HID)];

    const int rs = w & 3;          // 32-row strip
    const int cq = w >> 2;         // 32-col quarter

    float4 acc[2][4];
    #pragma unroll
    for (int mi = 0; mi < 2; mi++)
        #pragma unroll
        for (int j = 0; j < 4; j++) acc[mi][j] = make_float4(0,0,0,0);

    // phase 0: K 0..127 (se), phase 1: K 128..255 (oth)
    #pragma unroll 1
    for (int ph = 0; ph < 2; ph++) {
        fill_Afrag(Af, ph == 0 ? g_se : g_oth, row0, tid);
        fill_Wfrag_crit(B1, W1, ph * 128, tid);
        __syncthreads();
        for (int ks = 0; ks < 16; ks++) {
            uint4 a0 = Af[((2 * rs)     * 16 + ks) * 32 + lane];
            uint4 a1 = Af[((2 * rs + 1) * 16 + ks) * 32 + lane];
            #pragma unroll
            for (int j = 0; j < 4; j++) {
                uint2 bb = B1[((cq * 4 + j) * 16 + ks) * 32 + lane];
                mma8(acc[0][j], a0, bb); mma8(acc[1][j], a1, bb);
            }
        }
        __syncthreads();
    }

    // h = lrelu(acc + b1) into padded smem
    const int g = lane >> 2, tig = lane & 3;
    #pragma unroll
    for (int mi = 0; mi < 2; mi++) {
        #pragma unroll
        for (int j = 0; j < 4; j++) {
            int r = rs * 32 + mi * 16 + g;
            int c = cq * 32 + j * 8 + 2 * tig;
            float bb0 = b1s[c], bb1 = b1s[c + 1];
            h[r * HSTR + c]           = lrelu(acc[mi][j].x + bb0);
            h[r * HSTR + c + 1]       = lrelu(acc[mi][j].y + bb1);
            h[(r + 8) * HSTR + c]     = lrelu(acc[mi][j].z + bb0);
            h[(r + 8) * HSTR + c + 1] = lrelu(acc[mi][j].w + bb1);
        }
    }
    __syncthreads();

    // layer2 + argmax: warp w handles rows w*8 .. w*8+7
    const int o = lane & 15, half = lane >> 4;
    for (int rr = 0; rr < 8; rr++) {
        const int r = w * 8 + rr;
        const int bidx = blockIdx.x * 128 + r;
        const float4* hr4 = (const float4*)(h + r * HSTR + half * 64);
        const float4* w4  = (const float4*)(w2t + o * HSTR + half * 64);
        float q = 0.f;
        #pragma unroll
        for (int i = 0; i < 16; i++) {
            float4 hv = hr4[i], wv = w4[i];
            q += hv.x * wv.x + hv.y * wv.y + hv.z * wv.z + hv.w * wv.w;
        }
        q += __shfl_xor_sync(FULLMASK, q, 16);
        q += b2s[o];

        float av = (lane < AD) ? a[((size_t)n * B + bidx) * AD + lane] : -1e30f;
        int   ai = (lane < AD) ? lane : 1000;
        float bestv = av; int besti = ai;
        #pragma unroll
        for (int off = 16; off > 0; off >>= 1) {
            float ov = __shfl_xor_sync(FULLMASK, bestv, off);
            int   oi = __shfl_xor_sync(FULLMASK, besti, off);
            if (ov > bestv || (ov == bestv && oi < besti)) { bestv = ov; besti = oi; }
        }
        float qsel = __shfl_sync(FULLMASK, q, besti);   // lane besti (<16) has o==besti
        if (lane == 0) out[(size_t)n * B + bidx] = qsel;
    }
}

// ============================================================
extern "C" void kernel_launch(void* const* d_in, const int* in_sizes, int n_in,
                              void* d_out, int out_size)
{
    const float* s    = (const float*)d_in[0];
    const float* a    = (const float*)d_in[1];
    const float* Wsa  = (const float*)d_in[2];
    const float* Bsa  = (const float*)d_in[3];
    const float* Wse  = (const float*)d_in[4];
    const float* Bse  = (const float*)d_in[5];
    const float* Wk   = (const float*)d_in[6];
    const float* Wsel = (const float*)d_in[7];
    const float* Wv   = (const float*)d_in[8];
    const float* bv   = (const float*)d_in[9];
    const float* Wc1  = (const float*)d_in[10];
    const float* Bc1  = (const float*)d_in[11];
    const float* Wc2  = (const float*)d_in[12];
    const float* Bc2  = (const float*)d_in[13];
    float* out = (float*)d_out;

    cudaFuncSetAttribute(k_enc,     cudaFuncAttributeMaxDynamicSharedMemorySize, SMEM_ENC);
    cudaFuncSetAttribute(k_projkv,  cudaFuncAttributeMaxDynamicSharedMemorySize, SMEM_PKV);
    cudaFuncSetAttribute(k_projsel, cudaFuncAttributeMaxDynamicSharedMemorySize, SMEM_PSEL);
    cudaFuncSetAttribute(k_crit,    cudaFuncAttributeMaxDynamicSharedMemorySize, SMEM_CRIT);

    k_stats  <<<dim3(KSA, NAG), 256>>>(s, a);
    k_enc    <<<dim3(B / ENC_ROWS, NAG), 512, SMEM_ENC>>>(s, a, Wsa, Bsa, Wse, Bse);
    k_projkv <<<dim3((NAG * B) / 128), 512, SMEM_PKV>>>(Wk, Wv, bv);
    k_projsel<<<dim3((NAG * B) / 128), 512, SMEM_PSEL>>>(Wsel);
    k_attn   <<<dim3((HEADS * B) / 8), 256>>>();
    k_crit   <<<dim3(B / 128, NAG), 512, SMEM_CRIT>>>(a, Wc1, Bc1, Wc2, Bc2, out);
}

// round 4
// speedup vs baseline: 1.9002x; 1.3769x over previous
#include <cuda_runtime.h>
#include <math.h>
#include <stdint.h>

#define FULLMASK 0xffffffffu

constexpr int NAG  = 8;
constexpr int B    = 16384;
constexpr int SD   = 64;
constexpr int AD   = 16;
constexpr int KSA  = 80;     // SD + AD
constexpr int HID  = 128;
constexpr int HEADS= 4;
constexpr int D    = 32;
constexpr float EPS = 1e-5f;

// -------- scratch (device globals; no runtime allocation allowed) --------
__device__ __align__(16) float g_mean[NAG * KSA];
__device__ __align__(16) float g_rstd[NAG * KSA];
__device__ __align__(16) float g_part [NAG * 16 * KSA];   // per-chunk partial sums
__device__ __align__(16) float g_partq[NAG * 16 * KSA];   // per-chunk partial sumsq
__device__ __align__(16) float g_e  [(size_t)NAG * B * HID];
__device__ __align__(16) float g_se [(size_t)NAG * B * HID];
__device__ __align__(16) float g_key[(size_t)NAG * B * HID];
__device__ __align__(16) float g_val[(size_t)NAG * B * HID];
__device__ __align__(16) float g_sel[(size_t)NAG * B * HID];
__device__ __align__(16) float g_oth[(size_t)NAG * B * HID];

// fragment-order tf32 weights (filled once per launch by k_prep)
__device__ __align__(16) uint2 pWk  [16 * 16 * 32];          // 8192
__device__ __align__(16) uint2 pWv  [16 * 16 * 32];
__device__ __align__(16) uint2 pWsel[16 * 16 * 32];
__device__ __align__(16) uint2 pWsa [NAG][16 * 10 * 32];     // 5120 per agent
__device__ __align__(16) uint2 pWse [NAG][16 * 8 * 32];      // 4096 per agent
__device__ __align__(16) uint2 pWc1 [NAG][16 * 32 * 32];     // 16384 per agent

__device__ __forceinline__ float lrelu(float x) { return x > 0.f ? x : 0.01f * x; }

// ================= tf32 mma.sync helpers (arch-neutral PTX, sm_80+) =================
__device__ __forceinline__ uint32_t tf32rn(float x) {
    uint32_t u; asm("cvt.rna.tf32.f32 %0, %1;" : "=r"(u) : "f"(x)); return u;
}
__device__ __forceinline__ void mma8(float4& d, const uint4 a, const uint2 b) {
    asm volatile(
        "mma.sync.aligned.m16n8k8.row.col.f32.tf32.tf32.f32 "
        "{%0,%1,%2,%3}, {%4,%5,%6,%7}, {%8,%9}, {%0,%1,%2,%3};"
        : "+f"(d.x), "+f"(d.y), "+f"(d.z), "+f"(d.w)
        : "r"(a.x), "r"(a.y), "r"(a.z), "r"(a.w), "r"(b.x), "r"(b.y));
}

// ============================================================
// K0: precompute all weight fragments (fragment order, tf32)
// B-frag element ((n8*NKS + ks)*32 + lane) = {W'[n][k], W'[n][k+4]},
// n = n8*8 + (lane>>2), k = ks*8 + (lane&3).
// ============================================================
__global__ void __launch_bounds__(512)
k_prep(const float* __restrict__ Wk, const float* __restrict__ Wv,
       const float* __restrict__ Wsel, const float* __restrict__ Wsa,
       const float* __restrict__ Wse, const float* __restrict__ Wc1)
{
    int i = blockIdx.x * 512 + threadIdx.x;              // 0 .. 229375
    if (i < 24576) {                                     // proj weights [p][h][d]
        int which = i >> 13;                             // 0:k 1:v 2:sel
        int j = i & 8191;
        int n8 = j >> 9, ks = (j >> 5) & 15, lane = j & 31;
        int g = lane >> 2, tig = lane & 3;
        int n = n8 * 8 + g, k = ks * 8 + tig;
        const float* W = which == 0 ? Wk : (which == 1 ? Wv : Wsel);
        const float* base = W + (n >> 5) * (HID * D) + (n & 31);
        uint2 v = make_uint2(tf32rn(base[k * 32]), tf32rn(base[(k + 4) * 32]));
        (which == 0 ? pWk : which == 1 ? pWv : pWsel)[j] = v;
        return;
    }
    int i2 = i - 24576;
    if (i2 < NAG * 5120) {                               // Wsa [k][h], NKS=10
        int n = i2 / 5120, j = i2 % 5120;
        int lane = j & 31, ks = (j >> 5) % 10, n8 = j / 320;
        int g = lane >> 2, tig = lane & 3;
        int nn = n8 * 8 + g, k = ks * 8 + tig;
        const float* W = Wsa + n * KSA * HID;
        pWsa[n][j] = make_uint2(tf32rn(W[k * HID + nn]), tf32rn(W[(k + 4) * HID + nn]));
        return;
    }
    int i3 = i2 - NAG * 5120;
    if (i3 < NAG * 4096) {                               // Wse [k][h], NKS=8
        int n = i3 >> 12, j = i3 & 4095;
        int lane = j & 31, ks = (j >> 5) & 7, n8 = j >> 8;
        int g = lane >> 2, tig = lane & 3;
        int nn = n8 * 8 + g, k = ks * 8 + tig;
        const float* W = Wse + n * SD * HID;
        pWse[n][j] = make_uint2(tf32rn(W[k * HID + nn]), tf32rn(W[(k + 4) * HID + nn]));
        return;
    }
    int i4 = i3 - NAG * 4096;
    if (i4 < NAG * 16384) {                              // Wc1 [k][o], NKS=32
        int n = i4 >> 14, j = i4 & 16383;
        int lane = j & 31, ks = (j >> 5) & 31, n8 = j >> 10;
        int g = lane >> 2, tig = lane & 3;
        int nn = n8 * 8 + g, k = ks * 8 + tig;
        const float* W = Wc1 + (size_t)n * 2 * HID * HID;
        pWc1[n][j] = make_uint2(tf32rn(W[k * HID + nn]), tf32rn(W[(k + 4) * HID + nn]));
    }
}

// ============================================================
// K1: BN stats, coalesced partials.  grid (16, NAG), block 512
// ============================================================
__global__ void __launch_bounds__(512)
k_stats1(const float* __restrict__ s, const float* __restrict__ a)
{
    __shared__ float r1[512], r2[512];
    const int n = blockIdx.y, tid = threadIdx.x;
    const size_t row0 = (size_t)n * B + blockIdx.x * 1024;
    float* part  = g_part  + (n * 16 + blockIdx.x) * KSA;
    float* partq = g_partq + (n * 16 + blockIdx.x) * KSA;

    // --- s: feature f = tid&63, row group tid>>6 (8 rows/step, 128 steps)
    {
        const int f = tid & 63, r0 = tid >> 6;
        float sum = 0.f, sq = 0.f;
        const float* p = s + (row0 + r0) * SD + f;
        #pragma unroll 4
        for (int st = 0; st < 128; st++) {
            float x = p[(size_t)st * 8 * SD];
            sum += x; sq += x * x;
        }
        r1[tid] = sum; r2[tid] = sq;
        __syncthreads();
        #pragma unroll
        for (int o = 4; o > 0; o >>= 1) {
            if (tid < o * 64) { r1[tid] += r1[tid + o * 64]; r2[tid] += r2[tid + o * 64]; }
            __syncthreads();
        }
        if (tid < 64) { part[tid] = r1[tid]; partq[tid] = r2[tid]; }
        __syncthreads();
    }
    // --- a: feature f = tid&15, row group tid>>4 (32 rows/step, 32 steps)
    {
        const int f = tid & 15, r0 = tid >> 4;
        float sum = 0.f, sq = 0.f;
        const float* p = a + (row0 + r0) * AD + f;
        #pragma unroll 4
        for (int st = 0; st < 32; st++) {
            float x = p[(size_t)st * 32 * AD];
            sum += x; sq += x * x;
        }
        r1[tid] = sum; r2[tid] = sq;
        __syncthreads();
        #pragma unroll
        for (int o = 16; o > 0; o >>= 1) {
            if (tid < o * 16) { r1[tid] += r1[tid + o * 16]; r2[tid] += r2[tid + o * 16]; }
            __syncthreads();
        }
        if (tid < 16) { part[64 + tid] = r1[tid]; partq[64 + tid] = r2[tid]; }
    }
}

__global__ void k_stats2()
{
    int i = threadIdx.x;                                  // 0..639 = n*80+f
    if (i >= NAG * KSA) return;
    int n = i / KSA, f = i % KSA;
    float sum = 0.f, sq = 0.f;
    for (int c = 0; c < 16; c++) {
        sum += g_part [(n * 16 + c) * KSA + f];
        sq  += g_partq[(n * 16 + c) * KSA + f];
    }
    float m = sum * (1.f / B);
    float v = sq * (1.f / B) - m * m;
    g_mean[i] = m;
    g_rstd[i] = rsqrtf(v + EPS);
}

// ============================================================
// K2: encoders on tf32 mma.  grid (B/128, NAG), 512 threads.
// A tile: 128 rows x 80 cols (bn applied), padded stride 84 (conflict-free).
// e = A(0..79)@Wsa ; se = A(0..63)@Wse  (shared A).
// ============================================================
constexpr int PADE = 84;
constexpr int ENC_OFF_A   = 0;                            // 128*84*4 = 43008
constexpr int ENC_OFF_BSA = 43008;                        // 5120*8 = 40960
constexpr int ENC_OFF_BSE = 83968;                        // 4096*8 = 32768
constexpr int ENC_OFF_BS  = 116736;                       // 128+128 floats
constexpr int ENC_OFF_MN  = 117760;                       // 80+80 floats
constexpr int SMEM_ENC    = 118400;

__global__ void __launch_bounds__(512, 1)
k_enc(const float* __restrict__ s, const float* __restrict__ a,
      const float* __restrict__ Bsa, const float* __restrict__ Bse)
{
    extern __shared__ char smc[];
    uint32_t* uA  = (uint32_t*)(smc + ENC_OFF_A);
    uint2*    bSA = (uint2*)(smc + ENC_OFF_BSA);
    uint2*    bSE = (uint2*)(smc + ENC_OFF_BSE);
    float*    bsa = (float*)(smc + ENC_OFF_BS);
    float*    bse = bsa + 128;
    float*    mn  = (float*)(smc + ENC_OFF_MN);
    float*    rsd = mn + 80;

    const int n = blockIdx.y, tid = threadIdx.x;
    const int b0 = blockIdx.x * 128;

    if (tid < 128) { bsa[tid] = Bsa[n * HID + tid]; bse[tid] = Bse[n * HID + tid]; }
    if (tid >= 128 && tid < 128 + 80) {
        int f = tid - 128;
        mn[f] = g_mean[n * KSA + f]; rsd[f] = g_rstd[n * KSA + f];
    }
    for (int i = tid; i < 5120; i += 512) bSA[i] = pWsa[n][i];
    for (int i = tid; i < 4096; i += 512) bSE[i] = pWse[n][i];
    __syncthreads();   // mn/rsd ready before A fill uses them

    // A fill: 128 rows x 20 float4
    for (int i = tid; i < 128 * 20; i += 512) {
        int r = i / 20, c4 = i - r * 20;
        size_t row = (size_t)n * B + b0 + r;
        float4 v;
        if (c4 < 16) v = ((const float4*)s)[row * 16 + c4];
        else         v = ((const float4*)a)[row * 4 + (c4 - 16)];
        int c = c4 * 4;
        uint4 t = make_uint4(tf32rn((v.x - mn[c])     * rsd[c]),
                             tf32rn((v.y - mn[c + 1]) * rsd[c + 1]),
                             tf32rn((v.z - mn[c + 2]) * rsd[c + 2]),
                             tf32rn((v.w - mn[c + 3]) * rsd[c + 3]));
        *(uint4*)(uA + r * PADE + c4 * 4) = t;
    }
    __syncthreads();

    const int w = tid >> 5, lane = tid & 31;
    const int rs_ = w & 3, t0 = w >> 2;
    const int g = lane >> 2, tig = lane & 3;

    float4 ae[2][4], as_[2][4];
    #pragma unroll
    for (int mi = 0; mi < 2; mi++)
        #pragma unroll
        for (int j = 0; j < 4; j++) { ae[mi][j] = make_float4(0,0,0,0); as_[mi][j] = make_float4(0,0,0,0); }

    const uint32_t* A0 = uA + (rs_ * 32 + g) * PADE + tig;
    const uint32_t* A1 = A0 + 16 * PADE;

    #pragma unroll
    for (int ks = 0; ks < 10; ks++) {
        uint4 fa[2];
        fa[0] = make_uint4(A0[ks*8], A0[ks*8 + 8*PADE], A0[ks*8 + 4], A0[ks*8 + 8*PADE + 4]);
        fa[1] = make_uint4(A1[ks*8], A1[ks*8 + 8*PADE], A1[ks*8 + 4], A1[ks*8 + 8*PADE + 4]);
        #pragma unroll
        for (int j = 0; j < 4; j++) {
            uint2 bb = bSA[((t0 * 4 + j) * 10 + ks) * 32 + lane];
            mma8(ae[0][j], fa[0], bb); mma8(ae[1][j], fa[1], bb);
        }
        if (ks < 8) {
            #pragma unroll
            for (int j = 0; j < 4; j++) {
                uint2 bb = bSE[((t0 * 4 + j) * 8 + ks) * 32 + lane];
                mma8(as_[0][j], fa[0], bb); mma8(as_[1][j], fa[1], bb);
            }
        }
    }

    #pragma unroll
    for (int mi = 0; mi < 2; mi++) {
        #pragma unroll
        for (int j = 0; j < 4; j++) {
            size_t r = (size_t)n * B + b0 + rs_ * 32 + mi * 16 + g;
            int c = t0 * 32 + j * 8 + 2 * tig;
            float b0e = bsa[c], b1e = bsa[c + 1];
            float b0s = bse[c], b1s = bse[c + 1];
            *(float2*)&g_e[r * 128 + c]        = make_float2(lrelu(ae[mi][j].x + b0e), lrelu(ae[mi][j].y + b1e));
            *(float2*)&g_e[(r + 8) * 128 + c]  = make_float2(lrelu(ae[mi][j].z + b0e), lrelu(ae[mi][j].w + b1e));
            *(float2*)&g_se[r * 128 + c]       = make_float2(lrelu(as_[mi][j].x + b0s), lrelu(as_[mi][j].y + b1s));
            *(float2*)&g_se[(r + 8) * 128 + c] = make_float2(lrelu(as_[mi][j].z + b0s), lrelu(as_[mi][j].w + b1s));
        }
    }
}

// ============================================================
// K3: projections.  A tile padded stride 132; weights staged from
// precomputed fragments (coalesced).
// ============================================================
constexpr int PAD = 132;
__device__ __forceinline__ void fill_Atile(uint32_t* uA, const float* __restrict__ src,
                                           size_t row0, int tid) {
    const float4* s4 = (const float4*)src;
    for (int i = tid; i < 128 * 32; i += 512) {
        int r = i >> 5, c4 = i & 31;
        float4 v = s4[(row0 + r) * 32 + c4];
        *(uint4*)(uA + r * PAD + c4 * 4) =
            make_uint4(tf32rn(v.x), tf32rn(v.y), tf32rn(v.z), tf32rn(v.w));
    }
}

constexpr int PKV_OFF_A  = 0;                             // 128*132*4 = 67584
constexpr int PKV_OFF_BK = 67584;
constexpr int PKV_OFF_BV = 133120;
constexpr int PKV_OFF_BVS= 198656;
constexpr int SMEM_PKV   = 199168;

__global__ void __launch_bounds__(512, 1)
k_projkv(const float* __restrict__ bv)
{
    extern __shared__ char smc[];
    uint32_t* uA = (uint32_t*)(smc + PKV_OFF_A);
    uint2*    BK = (uint2*)(smc + PKV_OFF_BK);
    uint2*    BV = (uint2*)(smc + PKV_OFF_BV);
    float*   bvs = (float*)(smc + PKV_OFF_BVS);

    const int tid = threadIdx.x, w = tid >> 5, lane = tid & 31;
    const size_t row0 = (size_t)blockIdx.x * 128;

    fill_Atile(uA, g_e, row0, tid);
    for (int i = tid; i < 8192; i += 512) { BK[i] = pWk[i]; BV[i] = pWv[i]; }
    if (tid < 128) bvs[tid] = bv[tid];
    __syncthreads();

    const int rs_ = w & 3, t0 = w >> 2;
    const int g = lane >> 2, tig = lane & 3;

    float4 ack[2][4], acv[2][4];
    #pragma unroll
    for (int mi = 0; mi < 2; mi++)
        #pragma unroll
        for (int j = 0; j < 4; j++) { ack[mi][j] = make_float4(0,0,0,0); acv[mi][j] = make_float4(0,0,0,0); }

    const uint32_t* A0 = uA + (rs_ * 32 + g) * PAD + tig;
    const uint32_t* A1 = A0 + 16 * PAD;

    #pragma unroll
    for (int ks = 0; ks < 16; ks++) {
        uint4 fa[2];
        fa[0] = make_uint4(A0[ks*8], A0[ks*8 + 8*PAD], A0[ks*8 + 4], A0[ks*8 + 8*PAD + 4]);
        fa[1] = make_uint4(A1[ks*8], A1[ks*8 + 8*PAD], A1[ks*8 + 4], A1[ks*8 + 8*PAD + 4]);
        #pragma unroll
        for (int j = 0; j < 4; j++) {
            int bi = ((t0 * 4 + j) * 16 + ks) * 32 + lane;
            uint2 bk = BK[bi], bw = BV[bi];
            mma8(ack[0][j], fa[0], bk); mma8(ack[1][j], fa[1], bk);
            mma8(acv[0][j], fa[0], bw); mma8(acv[1][j], fa[1], bw);
        }
    }

    #pragma unroll
    for (int mi = 0; mi < 2; mi++) {
        #pragma unroll
        for (int j = 0; j < 4; j++) {
            size_t r = row0 + rs_ * 32 + mi * 16 + g;
            int c = t0 * 32 + j * 8 + 2 * tig;
            *(float2*)&g_key[r * 128 + c]       = make_float2(ack[mi][j].x, ack[mi][j].y);
            *(float2*)&g_key[(r + 8) * 128 + c] = make_float2(ack[mi][j].z, ack[mi][j].w);
            float bb0 = bvs[c], bb1 = bvs[c + 1];
            *(float2*)&g_val[r * 128 + c]       = make_float2(lrelu(acv[mi][j].x + bb0), lrelu(acv[mi][j].y + bb1));
            *(float2*)&g_val[(r + 8) * 128 + c] = make_float2(lrelu(acv[mi][j].z + bb0), lrelu(acv[mi][j].w + bb1));
        }
    }
}

constexpr int SMEM_PSEL = 67584 + 65536;

__global__ void __launch_bounds__(512, 1)
k_projsel()
{
    extern __shared__ char smc[];
    uint32_t* uA = (uint32_t*)smc;
    uint2*    BS = (uint2*)(smc + 67584);

    const int tid = threadIdx.x, w = tid >> 5, lane = tid & 31;
    const size_t row0 = (size_t)blockIdx.x * 128;

    fill_Atile(uA, g_se, row0, tid);
    for (int i = tid; i < 8192; i += 512) BS[i] = pWsel[i];
    __syncthreads();

    const int rs_ = w & 3, t0 = w >> 2;
    const int g = lane >> 2, tig = lane & 3;

    float4 acc[2][4];
    #pragma unroll
    for (int mi = 0; mi < 2; mi++)
        #pragma unroll
        for (int j = 0; j < 4; j++) acc[mi][j] = make_float4(0,0,0,0);

    const uint32_t* A0 = uA + (rs_ * 32 + g) * PAD + tig;
    const uint32_t* A1 = A0 + 16 * PAD;

    #pragma unroll
    for (int ks = 0; ks < 16; ks++) {
        uint4 fa[2];
        fa[0] = make_uint4(A0[ks*8], A0[ks*8 + 8*PAD], A0[ks*8 + 4], A0[ks*8 + 8*PAD + 4]);
        fa[1] = make_uint4(A1[ks*8], A1[ks*8 + 8*PAD], A1[ks*8 + 4], A1[ks*8 + 8*PAD + 4]);
        #pragma unroll
        for (int j = 0; j < 4; j++) {
            uint2 bb = BS[((t0 * 4 + j) * 16 + ks) * 32 + lane];
            mma8(acc[0][j], fa[0], bb); mma8(acc[1][j], fa[1], bb);
        }
    }

    #pragma unroll
    for (int mi = 0; mi < 2; mi++) {
        #pragma unroll
        for (int j = 0; j < 4; j++) {
            size_t r = row0 + rs_ * 32 + mi * 16 + g;
            int c = t0 * 32 + j * 8 + 2 * tig;
            *(float2*)&g_sel[r * 128 + c]       = make_float2(acc[mi][j].x, acc[mi][j].y);
            *(float2*)&g_sel[(r + 8) * 128 + c] = make_float2(acc[mi][j].z, acc[mi][j].w);
        }
    }
}

// ============================================================
// K4: attention — one warp per (head p, batch b); 8x8 agent softmax
// ============================================================
__global__ void __launch_bounds__(256, 4)
k_attn()
{
    __shared__ float smem[8][3 * 8 * 33 + 64];
    const int tid = threadIdx.x, warp = tid >> 5, lane = tid & 31;
    const int gid = blockIdx.x * 8 + warp;
    const int b = gid >> 2;
    const int p = gid & 3;

    float* selS = smem[warp];
    float* keyS = selS + 8 * 33;
    float* valS = keyS + 8 * 33;
    float* wS   = valS + 8 * 33;
    const float scale = 0.17677669529663687f;

    #pragma unroll
    for (int i = 0; i < 8; i++) {
        size_t base = ((size_t)i * B + b) * HID + p * D + lane;
        selS[i * 33 + lane] = g_sel[base];
        keyS[i * 33 + lane] = g_key[base];
        valS[i * 33 + lane] = g_val[base];
    }
    __syncwarp();

    const int i0 = lane >> 3, j = lane & 7, i1 = i0 + 4;
    float acc0 = 0.f, acc1 = 0.f;
    #pragma unroll
    for (int d = 0; d < 32; d++) {
        float kv = keyS[j * 33 + d];
        acc0 += selS[i0 * 33 + d] * kv;
        acc1 += selS[i1 * 33 + d] * kv;
    }
    acc0 *= scale; acc1 *= scale;
    if (i0 == j) acc0 = -1e9f;
    if (i1 == j) acc1 = -1e9f;

    float m0 = acc0, m1 = acc1;
    #pragma unroll
    for (int o = 1; o < 8; o <<= 1) {
        m0 = fmaxf(m0, __shfl_xor_sync(FULLMASK, m0, o));
        m1 = fmaxf(m1, __shfl_xor_sync(FULLMASK, m1, o));
    }
    float e0 = expf(acc0 - m0), e1 = expf(acc1 - m1);
    float s0 = e0, s1 = e1;
    #pragma unroll
    for (int o = 1; o < 8; o <<= 1) {
        s0 += __shfl_xor_sync(FULLMASK, s0, o);
        s1 += __shfl_xor_sync(FULLMASK, s1, o);
    }
    wS[lane]      = e0 / s0;
    wS[lane + 32] = e1 / s1;
    __syncwarp();

    float out[8];
    #pragma unroll
    for (int ii = 0; ii < 8; ii++) out[ii] = 0.f;
    #pragma unroll
    for (int jj = 0; jj < 8; jj++) {
        float v = valS[jj * 33 + lane];
        #pragma unroll
        for (int ii = 0; ii < 8; ii++) out[ii] += wS[ii * 8 + jj] * v;
    }
    #pragma unroll
    for (int ii = 0; ii < 8; ii++)
        g_oth[((size_t)ii * B + b) * HID + p * D + lane] = out[ii];
}

// ============================================================
// K5: critic (W1 mma, K=256 two phases) + scalar layer2 + argmax
// ============================================================
constexpr int HSTR = 132;
constexpr int CR_OFF_A   = 0;                             // 67584
constexpr int CR_OFF_B1  = 67584;                         // 65536
constexpr int CR_OFF_H   = 133120;                        // 67584
constexpr int CR_OFF_W2  = 200704;                        // 8448
constexpr int CR_OFF_B1S = 209152;                        // 512
constexpr int CR_OFF_B2S = 209664;                        // 64
constexpr int SMEM_CRIT  = 209728;

__global__ void __launch_bounds__(512, 1)
k_crit(const float* __restrict__ a,
       const float* __restrict__ Bc1,
       const float* __restrict__ Wc2, const float* __restrict__ Bc2,
       float* __restrict__ out)
{
    extern __shared__ char smc[];
    uint32_t* uA = (uint32_t*)(smc + CR_OFF_A);
    uint2*    B1 = (uint2*)(smc + CR_OFF_B1);
    float*    h  = (float*)(smc + CR_OFF_H);
    float*   w2t = (float*)(smc + CR_OFF_W2);
    float*   b1s = (float*)(smc + CR_OFF_B1S);
    float*   b2s = (float*)(smc + CR_OFF_B2S);

    const int n = blockIdx.y, tid = threadIdx.x;
    const int w = tid >> 5, lane = tid & 31;
    const size_t row0 = (size_t)n * B + (size_t)blockIdx.x * 128;

    for (int i = tid; i < HID * AD; i += 512) {
        int k = i >> 4, o = i & 15;
        w2t[o * HSTR + k] = Wc2[n * HID * AD + k * AD + o];
    }
    if (tid < HID) b1s[tid] = Bc1[n * HID + tid];
    if (tid >= HID && tid < HID + AD) b2s[tid - HID] = Bc2[n * AD + (tid - HID)];

    const int rs_ = w & 3, cq = w >> 2;
    const int g = lane >> 2, tig = lane & 3;

    float4 acc[2][4];
    #pragma unroll
    for (int mi = 0; mi < 2; mi++)
        #pragma unroll
        for (int j = 0; j < 4; j++) acc[mi][j] = make_float4(0,0,0,0);

    const uint32_t* A0 = uA + (rs_ * 32 + g) * PAD + tig;
    const uint32_t* A1 = A0 + 16 * PAD;

    #pragma unroll 1
    for (int ph = 0; ph < 2; ph++) {
        fill_Atile(uA, ph == 0 ? g_se : g_oth, row0, tid);
        // stage this phase's 16 k-steps of W1 fragments (coalesced inner stride)
        for (int i = tid; i < 8192; i += 512) {
            int n8 = i >> 9, ksl = (i >> 5) & 15, ln = i & 31;
            B1[i] = pWc1[n][((n8 * 32) + ph * 16 + ksl) * 32 + ln];
        }
        __syncthreads();
        #pragma unroll
        for (int ks = 0; ks < 16; ks++) {
            uint4 fa[2];
            fa[0] = make_uint4(A0[ks*8], A0[ks*8 + 8*PAD], A0[ks*8 + 4], A0[ks*8 + 8*PAD + 4]);
            fa[1] = make_uint4(A1[ks*8], A1[ks*8 + 8*PAD], A1[ks*8 + 4], A1[ks*8 + 8*PAD + 4]);
            #pragma unroll
            for (int j = 0; j < 4; j++) {
                uint2 bb = B1[((cq * 4 + j) * 16 + ks) * 32 + lane];
                mma8(acc[0][j], fa[0], bb); mma8(acc[1][j], fa[1], bb);
            }
        }
        __syncthreads();
    }

    #pragma unroll
    for (int mi = 0; mi < 2; mi++) {
        #pragma unroll
        for (int j = 0; j < 4; j++) {
            int r = rs_ * 32 + mi * 16 + g;
            int c = cq * 32 + j * 8 + 2 * tig;
            float bb0 = b1s[c], bb1 = b1s[c + 1];
            h[r * HSTR + c]           = lrelu(acc[mi][j].x + bb0);
            h[r * HSTR + c + 1]       = lrelu(acc[mi][j].y + bb1);
            h[(r + 8) * HSTR + c]     = lrelu(acc[mi][j].z + bb0);
            h[(r + 8) * HSTR + c + 1] = lrelu(acc[mi][j].w + bb1);
        }
    }
    __syncthreads();

    const int o = lane & 15, half = lane >> 4;
    for (int rr = 0; rr < 8; rr++) {
        const int r = w * 8 + rr;
        const int bidx = blockIdx.x * 128 + r;
        const float4* hr4 = (const float4*)(h + r * HSTR + half * 64);
        const float4* w4  = (const float4*)(w2t + o * HSTR + half * 64);
        float q = 0.f;
        #pragma unroll
        for (int i = 0; i < 16; i++) {
            float4 hv = hr4[i], wv = w4[i];
            q += hv.x * wv.x + hv.y * wv.y + hv.z * wv.z + hv.w * wv.w;
        }
        q += __shfl_xor_sync(FULLMASK, q, 16);
        q += b2s[o];

        float av = (lane < AD) ? a[((size_t)n * B + bidx) * AD + lane] : -1e30f;
        int   ai = (lane < AD) ? lane : 1000;
        float bestv = av; int besti = ai;
        #pragma unroll
        for (int off = 16; off > 0; off >>= 1) {
            float ov = __shfl_xor_sync(FULLMASK, bestv, off);
            int   oi = __shfl_xor_sync(FULLMASK, besti, off);
            if (ov > bestv || (ov == bestv && oi < besti)) { bestv = ov; besti = oi; }
        }
        float qsel = __shfl_sync(FULLMASK, q, besti);
        if (lane == 0) out[(size_t)n * B + bidx] = qsel;
    }
}

// ============================================================
extern "C" void kernel_launch(void* const* d_in, const int* in_sizes, int n_in,
                              void* d_out, int out_size)
{
    const float* s    = (const float*)d_in[0];
    const float* a    = (const float*)d_in[1];
    const float* Wsa  = (const float*)d_in[2];
    const float* Bsa  = (const float*)d_in[3];
    const float* Wse  = (const float*)d_in[4];
    const float* Bse  = (const float*)d_in[5];
    const float* Wk   = (const float*)d_in[6];
    const float* Wsel = (const float*)d_in[7];
    const float* Wv   = (const float*)d_in[8];
    const float* bv   = (const float*)d_in[9];
    const float* Wc1  = (const float*)d_in[10];
    const float* Bc1  = (const float*)d_in[11];
    const float* Wc2  = (const float*)d_in[12];
    const float* Bc2  = (const float*)d_in[13];
    float* out = (float*)d_out;

    cudaFuncSetAttribute(k_enc,     cudaFuncAttributeMaxDynamicSharedMemorySize, SMEM_ENC);
    cudaFuncSetAttribute(k_projkv,  cudaFuncAttributeMaxDynamicSharedMemorySize, SMEM_PKV);
    cudaFuncSetAttribute(k_projsel, cudaFuncAttributeMaxDynamicSharedMemorySize, SMEM_PSEL);
    cudaFuncSetAttribute(k_crit,    cudaFuncAttributeMaxDynamicSharedMemorySize, SMEM_CRIT);

    k_prep   <<<448, 512>>>(Wk, Wv, Wsel, Wsa, Wse, Wc1);
    k_stats1 <<<dim3(16, NAG), 512>>>(s, a);
    k_stats2 <<<1, 640>>>();
    k_enc    <<<dim3(B / 128, NAG), 512, SMEM_ENC>>>(s, a, Bsa, Bse);
    k_projkv <<<dim3((NAG * B) / 128), 512, SMEM_PKV>>>(bv);
    k_projsel<<<dim3((NAG * B) / 128), 512, SMEM_PSEL>>>();
    k_attn   <<<dim3((HEADS * B) / 8), 256>>>();
    k_crit   <<<dim3(B / 128, NAG), 512, SMEM_CRIT>>>(a, Bc1, Wc2, Bc2, out);
}

// round 5
// speedup vs baseline: 2.1992x; 1.1573x over previous
#include <cuda_runtime.h>
#include <math.h>
#include <stdint.h>

#define FULLMASK 0xffffffffu

constexpr int NAG  = 8;
constexpr int B    = 16384;
constexpr int SD   = 64;
constexpr int AD   = 16;
constexpr int KSA  = 80;     // SD + AD
constexpr int HID  = 128;
constexpr int HEADS= 4;
constexpr int D    = 32;
constexpr float EPS = 1e-5f;

// -------- scratch (device globals; no runtime allocation allowed) --------
__device__ __align__(16) float g_mean[NAG * KSA];
__device__ __align__(16) float g_rstd[NAG * KSA];
__device__ __align__(16) float g_part [NAG * 16 * KSA];
__device__ __align__(16) float g_partq[NAG * 16 * KSA];
__device__ __align__(16) float g_se [(size_t)NAG * B * HID];
__device__ __align__(16) float g_key[(size_t)NAG * B * HID];
__device__ __align__(16) float g_val[(size_t)NAG * B * HID];
__device__ __align__(16) float g_sel[(size_t)NAG * B * HID];
__device__ __align__(16) float g_oth[(size_t)NAG * B * HID];

// fragment-order tf32 weights (filled once per launch by k_prep)
__device__ __align__(16) uint2 pWk  [16 * 16 * 32];          // 8192
__device__ __align__(16) uint2 pWv  [16 * 16 * 32];
__device__ __align__(16) uint2 pWsel[16 * 16 * 32];
__device__ __align__(16) uint2 pWsa [NAG][16 * 10 * 32];     // 5120 per agent
__device__ __align__(16) uint2 pWse [NAG][16 * 8 * 32];      // 4096 per agent
__device__ __align__(16) uint2 pWc1 [NAG][16 * 32 * 32];     // 16384 per agent

__device__ __forceinline__ float lrelu(float x) { return x > 0.f ? x : 0.01f * x; }

// ================= tf32 mma.sync helpers =================
__device__ __forceinline__ uint32_t tf32rn(float x) {
    uint32_t u; asm("cvt.rna.tf32.f32 %0, %1;" : "=r"(u) : "f"(x)); return u;
}
__device__ __forceinline__ void mma8(float4& d, const uint4 a, const uint2 b) {
    asm volatile(
        "mma.sync.aligned.m16n8k8.row.col.f32.tf32.tf32.f32 "
        "{%0,%1,%2,%3}, {%4,%5,%6,%7}, {%8,%9}, {%0,%1,%2,%3};"
        : "+f"(d.x), "+f"(d.y), "+f"(d.z), "+f"(d.w)
        : "r"(a.x), "r"(a.y), "r"(a.z), "r"(a.w), "r"(b.x), "r"(b.y));
}

// ============================================================
// K0: precompute all weight fragments (fragment order, tf32)
// ============================================================
__global__ void __launch_bounds__(512)
k_prep(const float* __restrict__ Wk, const float* __restrict__ Wv,
       const float* __restrict__ Wsel, const float* __restrict__ Wsa,
       const float* __restrict__ Wse, const float* __restrict__ Wc1)
{
    int i = blockIdx.x * 512 + threadIdx.x;              // 0 .. 229375
    if (i < 24576) {                                     // proj weights [p][h][d]
        int which = i >> 13;
        int j = i & 8191;
        int n8 = j >> 9, ks = (j >> 5) & 15, lane = j & 31;
        int g = lane >> 2, tig = lane & 3;
        int n = n8 * 8 + g, k = ks * 8 + tig;
        const float* W = which == 0 ? Wk : (which == 1 ? Wv : Wsel);
        const float* base = W + (n >> 5) * (HID * D) + (n & 31);
        uint2 v = make_uint2(tf32rn(base[k * 32]), tf32rn(base[(k + 4) * 32]));
        (which == 0 ? pWk : which == 1 ? pWv : pWsel)[j] = v;
        return;
    }
    int i2 = i - 24576;
    if (i2 < NAG * 5120) {                               // Wsa [k][h], NKS=10
        int n = i2 / 5120, j = i2 % 5120;
        int lane = j & 31, ks = (j >> 5) % 10, n8 = j / 320;
        int g = lane >> 2, tig = lane & 3;
        int nn = n8 * 8 + g, k = ks * 8 + tig;
        const float* W = Wsa + n * KSA * HID;
        pWsa[n][j] = make_uint2(tf32rn(W[k * HID + nn]), tf32rn(W[(k + 4) * HID + nn]));
        return;
    }
    int i3 = i2 - NAG * 5120;
    if (i3 < NAG * 4096) {                               // Wse [k][h], NKS=8
        int n = i3 >> 12, j = i3 & 4095;
        int lane = j & 31, ks = (j >> 5) & 7, n8 = j >> 8;
        int g = lane >> 2, tig = lane & 3;
        int nn = n8 * 8 + g, k = ks * 8 + tig;
        const float* W = Wse + n * SD * HID;
        pWse[n][j] = make_uint2(tf32rn(W[k * HID + nn]), tf32rn(W[(k + 4) * HID + nn]));
        return;
    }
    int i4 = i3 - NAG * 4096;
    if (i4 < NAG * 16384) {                              // Wc1 [k][o], NKS=32
        int n = i4 >> 14, j = i4 & 16383;
        int lane = j & 31, ks = (j >> 5) & 31, n8 = j >> 10;
        int g = lane >> 2, tig = lane & 3;
        int nn = n8 * 8 + g, k = ks * 8 + tig;
        const float* W = Wc1 + (size_t)n * 2 * HID * HID;
        pWc1[n][j] = make_uint2(tf32rn(W[k * HID + nn]), tf32rn(W[(k + 4) * HID + nn]));
    }
}

// ============================================================
// K1: BN stats, coalesced partials.  grid (16, NAG), block 512
// ============================================================
__global__ void __launch_bounds__(512)
k_stats1(const float* __restrict__ s, const float* __restrict__ a)
{
    __shared__ float r1[512], r2[512];
    const int n = blockIdx.y, tid = threadIdx.x;
    const size_t row0 = (size_t)n * B + blockIdx.x * 1024;
    float* part  = g_part  + (n * 16 + blockIdx.x) * KSA;
    float* partq = g_partq + (n * 16 + blockIdx.x) * KSA;

    {
        const int f = tid & 63, r0 = tid >> 6;
        float sum = 0.f, sq = 0.f;
        const float* p = s + (row0 + r0) * SD + f;
        #pragma unroll 4
        for (int st = 0; st < 128; st++) {
            float x = p[(size_t)st * 8 * SD];
            sum += x; sq += x * x;
        }
        r1[tid] = sum; r2[tid] = sq;
        __syncthreads();
        #pragma unroll
        for (int o = 4; o > 0; o >>= 1) {
            if (tid < o * 64) { r1[tid] += r1[tid + o * 64]; r2[tid] += r2[tid + o * 64]; }
            __syncthreads();
        }
        if (tid < 64) { part[tid] = r1[tid]; partq[tid] = r2[tid]; }
        __syncthreads();
    }
    {
        const int f = tid & 15, r0 = tid >> 4;
        float sum = 0.f, sq = 0.f;
        const float* p = a + (row0 + r0) * AD + f;
        #pragma unroll 4
        for (int st = 0; st < 32; st++) {
            float x = p[(size_t)st * 32 * AD];
            sum += x; sq += x * x;
        }
        r1[tid] = sum; r2[tid] = sq;
        __syncthreads();
        #pragma unroll
        for (int o = 16; o > 0; o >>= 1) {
            if (tid < o * 16) { r1[tid] += r1[tid + o * 16]; r2[tid] += r2[tid + o * 16]; }
            __syncthreads();
        }
        if (tid < 16) { part[64 + tid] = r1[tid]; partq[64 + tid] = r2[tid]; }
    }
}

__global__ void k_stats2()
{
    int i = threadIdx.x;
    if (i >= NAG * KSA) return;
    int n = i / KSA, f = i % KSA;
    float sum = 0.f, sq = 0.f;
    for (int c = 0; c < 16; c++) {
        sum += g_part [(n * 16 + c) * KSA + f];
        sq  += g_partq[(n * 16 + c) * KSA + f];
    }
    float m = sum * (1.f / B);
    float v = sq * (1.f / B) - m * m;
    g_mean[i] = m;
    g_rstd[i] = rsqrtf(v + EPS);
}

// ============================================================
// K2: FUSED front: enc (e,se) -> sel -> key/val, tile-resident.
// grid (B/128, NAG), 512 threads.
// ============================================================
constexpr int PAD = 132;
constexpr int FR_OFF_A    = 0;                            // 128*132*4 = 67584
constexpr int FR_OFF_W    = 67584;                        // 2 x 65536
constexpr int FR_OFF_MISC = 198656;                       // 544 floats
constexpr int SMEM_FRONT  = 200832;

__global__ void __launch_bounds__(512, 1)
k_front(const float* __restrict__ s, const float* __restrict__ a,
        const float* __restrict__ Bsa, const float* __restrict__ Bse,
        const float* __restrict__ bv)
{
    extern __shared__ char smc[];
    uint32_t* uA = (uint32_t*)(smc + FR_OFF_A);
    uint2*    W0 = (uint2*)(smc + FR_OFF_W);               // 8192 uint2
    uint2*    W1 = (uint2*)(smc + FR_OFF_W + 65536);       // 8192 uint2
    float*   bsa = (float*)(smc + FR_OFF_MISC);
    float*   bse = bsa + 128;
    float*   bvv = bse + 128;
    float*   mn  = bvv + 128;
    float*   rsd = mn + 80;

    const int n = blockIdx.y, tid = threadIdx.x;
    const size_t gr0 = (size_t)n * B + (size_t)blockIdx.x * 128;

    if (tid < 128)      bsa[tid]       = Bsa[n * HID + tid];
    else if (tid < 256) bse[tid - 128] = Bse[n * HID + tid - 128];
    else if (tid < 384) bvv[tid - 256] = bv[tid - 256];
    else if (tid < 464) mn [tid - 384] = g_mean[n * KSA + tid - 384];
    else if (tid < 512) rsd[tid - 464] = g_rstd[n * KSA + tid - 464];
    if (tid < 32)       rsd[48 + tid]  = g_rstd[n * KSA + 48 + tid];
    // stage enc weights: Wsa (5120) then Wse (4096) in W0 region
    for (int i = tid; i < 5120; i += 512) W0[i] = pWsa[n][i];
    for (int i = tid; i < 4096; i += 512) W0[5120 + i] = pWse[n][i];
    __syncthreads();

    // ---- A fill: BN'd [128 x 80] tile, stride PAD ----
    for (int i = tid; i < 128 * 20; i += 512) {
        int r = i / 20, c4 = i - r * 20;
        size_t row = gr0 + r;
        float4 v = (c4 < 16) ? ((const float4*)s)[row * 16 + c4]
                             : ((const float4*)a)[row * 4 + (c4 - 16)];
        int c = c4 * 4;
        *(uint4*)(uA + r * PAD + c) =
            make_uint4(tf32rn((v.x - mn[c])     * rsd[c]),
                       tf32rn((v.y - mn[c + 1]) * rsd[c + 1]),
                       tf32rn((v.z - mn[c + 2]) * rsd[c + 2]),
                       tf32rn((v.w - mn[c + 3]) * rsd[c + 3]));
    }
    __syncthreads();

    const int w = tid >> 5, lane = tid & 31;
    const int rs_ = w & 3, t0 = w >> 2;
    const int g = lane >> 2, tig = lane & 3;
    const uint32_t* A0 = uA + (rs_ * 32 + g) * PAD + tig;
    const uint32_t* A1 = A0 + 16 * PAD;

    // ---- Phase 1: enc mma ----
    float4 ae[2][4], as_[2][4];
    #pragma unroll
    for (int mi = 0; mi < 2; mi++)
        #pragma unroll
        for (int j = 0; j < 4; j++) { ae[mi][j] = make_float4(0,0,0,0); as_[mi][j] = make_float4(0,0,0,0); }

    #pragma unroll
    for (int ks = 0; ks < 10; ks++) {
        uint4 fa0 = make_uint4(A0[ks*8], A0[ks*8 + 8*PAD], A0[ks*8 + 4], A0[ks*8 + 8*PAD + 4]);
        uint4 fa1 = make_uint4(A1[ks*8], A1[ks*8 + 8*PAD], A1[ks*8 + 4], A1[ks*8 + 8*PAD + 4]);
        #pragma unroll
        for (int j = 0; j < 4; j++) {
            uint2 bb = W0[((t0 * 4 + j) * 10 + ks) * 32 + lane];
            mma8(ae[0][j], fa0, bb); mma8(ae[1][j], fa1, bb);
        }
        if (ks < 8) {
            #pragma unroll
            for (int j = 0; j < 4; j++) {
                uint2 bb = W0[5120 + ((t0 * 4 + j) * 8 + ks) * 32 + lane];
                mma8(as_[0][j], fa0, bb); mma8(as_[1][j], fa1, bb);
            }
        }
    }

    // bias + lrelu in place; write g_se
    #pragma unroll
    for (int mi = 0; mi < 2; mi++) {
        #pragma unroll
        for (int j = 0; j < 4; j++) {
            int c = t0 * 32 + j * 8 + 2 * tig;
            float b0e = bsa[c], b1e = bsa[c + 1];
            float b0s = bse[c], b1s = bse[c + 1];
            ae[mi][j]  = make_float4(lrelu(ae[mi][j].x + b0e), lrelu(ae[mi][j].y + b1e),
                                     lrelu(ae[mi][j].z + b0e), lrelu(ae[mi][j].w + b1e));
            as_[mi][j] = make_float4(lrelu(as_[mi][j].x + b0s), lrelu(as_[mi][j].y + b1s),
                                     lrelu(as_[mi][j].z + b0s), lrelu(as_[mi][j].w + b1s));
            size_t r = gr0 + rs_ * 32 + mi * 16 + g;
            *(float2*)&g_se[r * 128 + c]       = make_float2(as_[mi][j].x, as_[mi][j].y);
            *(float2*)&g_se[(r + 8) * 128 + c] = make_float2(as_[mi][j].z, as_[mi][j].w);
        }
    }

    // ---- Phase 2: sel = se @ Wsel ----
    __syncthreads();    // everyone done reading A / enc weights
    #pragma unroll
    for (int mi = 0; mi < 2; mi++) {
        #pragma unroll
        for (int j = 0; j < 4; j++) {
            int r = rs_ * 32 + mi * 16 + g;
            int c = t0 * 32 + j * 8 + 2 * tig;
            *(uint2*)(uA + r * PAD + c)       = make_uint2(tf32rn(as_[mi][j].x), tf32rn(as_[mi][j].y));
            *(uint2*)(uA + (r + 8) * PAD + c) = make_uint2(tf32rn(as_[mi][j].z), tf32rn(as_[mi][j].w));
        }
    }
    for (int i = tid; i < 8192; i += 512) W0[i] = pWsel[i];
    __syncthreads();

    float4 ac1[2][4];
    #pragma unroll
    for (int mi = 0; mi < 2; mi++)
        #pragma unroll
        for (int j = 0; j < 4; j++) ac1[mi][j] = make_float4(0,0,0,0);

    #pragma unroll
    for (int ks = 0; ks < 16; ks++) {
        uint4 fa0 = make_uint4(A0[ks*8], A0[ks*8 + 8*PAD], A0[ks*8 + 4], A0[ks*8 + 8*PAD + 4]);
        uint4 fa1 = make_uint4(A1[ks*8], A1[ks*8 + 8*PAD], A1[ks*8 + 4], A1[ks*8 + 8*PAD + 4]);
        #pragma unroll
        for (int j = 0; j < 4; j++) {
            uint2 bb = W0[((t0 * 4 + j) * 16 + ks) * 32 + lane];
            mma8(ac1[0][j], fa0, bb); mma8(ac1[1][j], fa1, bb);
        }
    }
    #pragma unroll
    for (int mi = 0; mi < 2; mi++) {
        #pragma unroll
        for (int j = 0; j < 4; j++) {
            size_t r = gr0 + rs_ * 32 + mi * 16 + g;
            int c = t0 * 32 + j * 8 + 2 * tig;
            *(float2*)&g_sel[r * 128 + c]       = make_float2(ac1[mi][j].x, ac1[mi][j].y);
            *(float2*)&g_sel[(r + 8) * 128 + c] = make_float2(ac1[mi][j].z, ac1[mi][j].w);
        }
    }

    // ---- Phase 3: key/val = e @ {Wk,Wv} ----
    __syncthreads();
    #pragma unroll
    for (int mi = 0; mi < 2; mi++) {
        #pragma unroll
        for (int j = 0; j < 4; j++) {
            int r = rs_ * 32 + mi * 16 + g;
            int c = t0 * 32 + j * 8 + 2 * tig;
            *(uint2*)(uA + r * PAD + c)       = make_uint2(tf32rn(ae[mi][j].x), tf32rn(ae[mi][j].y));
            *(uint2*)(uA + (r + 8) * PAD + c) = make_uint2(tf32rn(ae[mi][j].z), tf32rn(ae[mi][j].w));
        }
    }
    for (int i = tid; i < 8192; i += 512) { W0[i] = pWk[i]; W1[i] = pWv[i]; }
    __syncthreads();

    float4 ac2[2][4];
    #pragma unroll
    for (int mi = 0; mi < 2; mi++)
        #pragma unroll
        for (int j = 0; j < 4; j++) { ac1[mi][j] = make_float4(0,0,0,0); ac2[mi][j] = make_float4(0,0,0,0); }

    #pragma unroll
    for (int ks = 0; ks < 16; ks++) {
        uint4 fa0 = make_uint4(A0[ks*8], A0[ks*8 + 8*PAD], A0[ks*8 + 4], A0[ks*8 + 8*PAD + 4]);
        uint4 fa1 = make_uint4(A1[ks*8], A1[ks*8 + 8*PAD], A1[ks*8 + 4], A1[ks*8 + 8*PAD + 4]);
        #pragma unroll
        for (int j = 0; j < 4; j++) {
            int bi = ((t0 * 4 + j) * 16 + ks) * 32 + lane;
            uint2 bk = W0[bi], bw = W1[bi];
            mma8(ac1[0][j], fa0, bk); mma8(ac1[1][j], fa1, bk);
            mma8(ac2[0][j], fa0, bw); mma8(ac2[1][j], fa1, bw);
        }
    }
    #pragma unroll
    for (int mi = 0; mi < 2; mi++) {
        #pragma unroll
        for (int j = 0; j < 4; j++) {
            size_t r = gr0 + rs_ * 32 + mi * 16 + g;
            int c = t0 * 32 + j * 8 + 2 * tig;
            *(float2*)&g_key[r * 128 + c]       = make_float2(ac1[mi][j].x, ac1[mi][j].y);
            *(float2*)&g_key[(r + 8) * 128 + c] = make_float2(ac1[mi][j].z, ac1[mi][j].w);
            float bb0 = bvv[c], bb1 = bvv[c + 1];
            *(float2*)&g_val[r * 128 + c]       = make_float2(lrelu(ac2[mi][j].x + bb0), lrelu(ac2[mi][j].y + bb1));
            *(float2*)&g_val[(r + 8) * 128 + c] = make_float2(lrelu(ac2[mi][j].z + bb0), lrelu(ac2[mi][j].w + bb1));
        }
    }
}

// ============================================================
// K3: attention — one warp per (head p, batch b); 8x8 agent softmax
// ============================================================
__global__ void __launch_bounds__(256, 4)
k_attn()
{
    __shared__ float smem[8][3 * 8 * 33 + 64];
    const int tid = threadIdx.x, warp = tid >> 5, lane = tid & 31;
    const int gid = blockIdx.x * 8 + warp;
    const int b = gid >> 2;
    const int p = gid & 3;

    float* selS = smem[warp];
    float* keyS = selS + 8 * 33;
    float* valS = keyS + 8 * 33;
    float* wS   = valS + 8 * 33;
    const float scale = 0.17677669529663687f;

    #pragma unroll
    for (int i = 0; i < 8; i++) {
        size_t base = ((size_t)i * B + b) * HID + p * D + lane;
        selS[i * 33 + lane] = g_sel[base];
        keyS[i * 33 + lane] = g_key[base];
        valS[i * 33 + lane] = g_val[base];
    }
    __syncwarp();

    const int i0 = lane >> 3, j = lane & 7, i1 = i0 + 4;
    float acc0 = 0.f, acc1 = 0.f;
    #pragma unroll
    for (int d = 0; d < 32; d++) {
        float kv = keyS[j * 33 + d];
        acc0 += selS[i0 * 33 + d] * kv;
        acc1 += selS[i1 * 33 + d] * kv;
    }
    acc0 *= scale; acc1 *= scale;
    if (i0 == j) acc0 = -1e9f;
    if (i1 == j) acc1 = -1e9f;

    float m0 = acc0, m1 = acc1;
    #pragma unroll
    for (int o = 1; o < 8; o <<= 1) {
        m0 = fmaxf(m0, __shfl_xor_sync(FULLMASK, m0, o));
        m1 = fmaxf(m1, __shfl_xor_sync(FULLMASK, m1, o));
    }
    float e0 = expf(acc0 - m0), e1 = expf(acc1 - m1);
    float s0 = e0, s1 = e1;
    #pragma unroll
    for (int o = 1; o < 8; o <<= 1) {
        s0 += __shfl_xor_sync(FULLMASK, s0, o);
        s1 += __shfl_xor_sync(FULLMASK, s1, o);
    }
    wS[lane]      = e0 / s0;
    wS[lane + 32] = e1 / s1;
    __syncwarp();

    float out[8];
    #pragma unroll
    for (int ii = 0; ii < 8; ii++) out[ii] = 0.f;
    #pragma unroll
    for (int jj = 0; jj < 8; jj++) {
        float v = valS[jj * 33 + lane];
        #pragma unroll
        for (int ii = 0; ii < 8; ii++) out[ii] += wS[ii * 8 + jj] * v;
    }
    #pragma unroll
    for (int ii = 0; ii < 8; ii++)
        g_oth[((size_t)ii * B + b) * HID + p * D + lane] = out[ii];
}

// ============================================================
// K4: critic (W1 mma, K=256 two phases) + scalar layer2 + argmax
// ============================================================
constexpr int HSTR = 132;
constexpr int CR_OFF_A   = 0;                             // 67584
constexpr int CR_OFF_B1  = 67584;                         // 65536
constexpr int CR_OFF_H   = 133120;                        // 67584
constexpr int CR_OFF_W2  = 200704;                        // 8448
constexpr int CR_OFF_B1S = 209152;                        // 512
constexpr int CR_OFF_B2S = 209664;                        // 64
constexpr int SMEM_CRIT  = 209728;

__global__ void __launch_bounds__(512, 1)
k_crit(const float* __restrict__ a,
       const float* __restrict__ Bc1,
       const float* __restrict__ Wc2, const float* __restrict__ Bc2,
       float* __restrict__ out)
{
    extern __shared__ char smc[];
    uint32_t* uA = (uint32_t*)(smc + CR_OFF_A);
    uint2*    B1 = (uint2*)(smc + CR_OFF_B1);
    float*    h  = (float*)(smc + CR_OFF_H);
    float*   w2t = (float*)(smc + CR_OFF_W2);
    float*   b1s = (float*)(smc + CR_OFF_B1S);
    float*   b2s = (float*)(smc + CR_OFF_B2S);

    const int n = blockIdx.y, tid = threadIdx.x;
    const int w = tid >> 5, lane = tid & 31;
    const size_t row0 = (size_t)n * B + (size_t)blockIdx.x * 128;

    for (int i = tid; i < HID * AD; i += 512) {
        int k = i >> 4, o = i & 15;
        w2t[o * HSTR + k] = Wc2[n * HID * AD + k * AD + o];
    }
    if (tid < HID) b1s[tid] = Bc1[n * HID + tid];
    if (tid >= HID && tid < HID + AD) b2s[tid - HID] = Bc2[n * AD + (tid - HID)];

    const int rs_ = w & 3, cq = w >> 2;
    const int g = lane >> 2, tig = lane & 3;

    float4 acc[2][4];
    #pragma unroll
    for (int mi = 0; mi < 2; mi++)
        #pragma unroll
        for (int j = 0; j < 4; j++) acc[mi][j] = make_float4(0,0,0,0);

    const uint32_t* A0 = uA + (rs_ * 32 + g) * PAD + tig;
    const uint32_t* A1 = A0 + 16 * PAD;

    #pragma unroll 1
    for (int ph = 0; ph < 2; ph++) {
        {   // A fill
            const float* src = ph == 0 ? g_se : g_oth;
            const float4* s4 = (const float4*)src;
            for (int i = tid; i < 128 * 32; i += 512) {
                int r = i >> 5, c4 = i & 31;
                float4 v = s4[(row0 + r) * 32 + c4];
                *(uint4*)(uA + r * PAD + c4 * 4) =
                    make_uint4(tf32rn(v.x), tf32rn(v.y), tf32rn(v.z), tf32rn(v.w));
            }
        }
        for (int i = tid; i < 8192; i += 512) {
            int n8 = i >> 9, ksl = (i >> 5) & 15, ln = i & 31;
            B1[i] = pWc1[n][((n8 * 32) + ph * 16 + ksl) * 32 + ln];
        }
        __syncthreads();
        #pragma unroll
        for (int ks = 0; ks < 16; ks++) {
            uint4 fa0 = make_uint4(A0[ks*8], A0[ks*8 + 8*PAD], A0[ks*8 + 4], A0[ks*8 + 8*PAD + 4]);
            uint4 fa1 = make_uint4(A1[ks*8], A1[ks*8 + 8*PAD], A1[ks*8 + 4], A1[ks*8 + 8*PAD + 4]);
            #pragma unroll
            for (int j = 0; j < 4; j++) {
                uint2 bb = B1[((cq * 4 + j) * 16 + ks) * 32 + lane];
                mma8(acc[0][j], fa0, bb); mma8(acc[1][j], fa1, bb);
            }
        }
        __syncthreads();
    }

    #pragma unroll
    for (int mi = 0; mi < 2; mi++) {
        #pragma unroll
        for (int j = 0; j < 4; j++) {
            int r = rs_ * 32 + mi * 16 + g;
            int c = cq * 32 + j * 8 + 2 * tig;
            float bb0 = b1s[c], bb1 = b1s[c + 1];
            h[r * HSTR + c]           = lrelu(acc[mi][j].x + bb0);
            h[r * HSTR + c + 1]       = lrelu(acc[mi][j].y + bb1);
            h[(r + 8) * HSTR + c]     = lrelu(acc[mi][j].z + bb0);
            h[(r + 8) * HSTR + c + 1] = lrelu(acc[mi][j].w + bb1);
        }
    }
    __syncthreads();

    const int o = lane & 15, half = lane >> 4;
    for (int rr = 0; rr < 8; rr++) {
        const int r = w * 8 + rr;
        const int bidx = blockIdx.x * 128 + r;
        const float4* hr4 = (const float4*)(h + r * HSTR + half * 64);
        const float4* w4  = (const float4*)(w2t + o * HSTR + half * 64);
        float q = 0.f;
        #pragma unroll
        for (int i = 0; i < 16; i++) {
            float4 hv = hr4[i], wv = w4[i];
            q += hv.x * wv.x + hv.y * wv.y + hv.z * wv.z + hv.w * wv.w;
        }
        q += __shfl_xor_sync(FULLMASK, q, 16);
        q += b2s[o];

        float av = (lane < AD) ? a[((size_t)n * B + bidx) * AD + lane] : -1e30f;
        int   ai = (lane < AD) ? lane : 1000;
        float bestv = av; int besti = ai;
        #pragma unroll
        for (int off = 16; off > 0; off >>= 1) {
            float ov = __shfl_xor_sync(FULLMASK, bestv, off);
            int   oi = __shfl_xor_sync(FULLMASK, besti, off);
            if (ov > bestv || (ov == bestv && oi < besti)) { bestv = ov; besti = oi; }
        }
        float qsel = __shfl_sync(FULLMASK, q, besti);
        if (lane == 0) out[(size_t)n * B + bidx] = qsel;
    }
}

// ============================================================
extern "C" void kernel_launch(void* const* d_in, const int* in_sizes, int n_in,
                              void* d_out, int out_size)
{
    const float* s    = (const float*)d_in[0];
    const float* a    = (const float*)d_in[1];
    const float* Wsa  = (const float*)d_in[2];
    const float* Bsa  = (const float*)d_in[3];
    const float* Wse  = (const float*)d_in[4];
    const float* Bse  = (const float*)d_in[5];
    const float* Wk   = (const float*)d_in[6];
    const float* Wsel = (const float*)d_in[7];
    const float* Wv   = (const float*)d_in[8];
    const float* bv   = (const float*)d_in[9];
    const float* Wc1  = (const float*)d_in[10];
    const float* Bc1  = (const float*)d_in[11];
    const float* Wc2  = (const float*)d_in[12];
    const float* Bc2  = (const float*)d_in[13];
    float* out = (float*)d_out;

    cudaFuncSetAttribute(k_front, cudaFuncAttributeMaxDynamicSharedMemorySize, SMEM_FRONT);
    cudaFuncSetAttribute(k_crit,  cudaFuncAttributeMaxDynamicSharedMemorySize, SMEM_CRIT);

    k_prep   <<<448, 512>>>(Wk, Wv, Wsel, Wsa, Wse, Wc1);
    k_stats1 <<<dim3(16, NAG), 512>>>(s, a);
    k_stats2 <<<1, 640>>>();
    k_front  <<<dim3(B / 128, NAG), 512, SMEM_FRONT>>>(s, a, Bsa, Bse, bv);
    k_attn   <<<dim3((HEADS * B) / 8), 256>>>();
    k_crit   <<<dim3(B / 128, NAG), 512, SMEM_CRIT>>>(a, Bc1, Wc2, Bc2, out);
}

// round 6
// speedup vs baseline: 2.7869x; 1.2672x over previous
#include <cuda_runtime.h>
#include <math.h>
#include <stdint.h>

#define FULLMASK 0xffffffffu

constexpr int NAG  = 8;
constexpr int B    = 16384;
constexpr int SD   = 64;
constexpr int AD   = 16;
constexpr int KSA  = 80;
constexpr int HID  = 128;
constexpr int HEADS= 4;
constexpr int D    = 32;
constexpr float EPS = 1e-5f;

// -------- scratch --------
__device__ __align__(16) float g_mean[NAG * KSA];
__device__ __align__(16) float g_rstd[NAG * KSA];
__device__ __align__(16) float g_part [NAG * 16 * KSA];
__device__ __align__(16) float g_partq[NAG * 16 * KSA];
__device__ __align__(16) float g_se [(size_t)NAG * B * HID];
__device__ __align__(16) float g_key[(size_t)NAG * B * HID];
__device__ __align__(16) float g_val[(size_t)NAG * B * HID];
__device__ __align__(16) float g_sel[(size_t)NAG * B * HID];
__device__ __align__(16) float g_oth[(size_t)NAG * B * HID];

// fragment-order tf32 weights (filled once per launch by k_prep)
__device__ __align__(16) uint2 pWk  [16 * 16 * 32];
__device__ __align__(16) uint2 pWv  [16 * 16 * 32];
__device__ __align__(16) uint2 pWsel[16 * 16 * 32];
__device__ __align__(16) uint2 pWsa [NAG][16 * 10 * 32];
__device__ __align__(16) uint2 pWse [NAG][16 * 8 * 32];
__device__ __align__(16) uint2 pWc1 [NAG][16 * 32 * 32];

__device__ __forceinline__ float lrelu(float x) { return x > 0.f ? x : 0.01f * x; }

__device__ __forceinline__ uint32_t tf32rn(float x) {
    uint32_t u; asm("cvt.rna.tf32.f32 %0, %1;" : "=r"(u) : "f"(x)); return u;
}
__device__ __forceinline__ void mma8(float4& d, const uint4 a, const uint2 b) {
    asm volatile(
        "mma.sync.aligned.m16n8k8.row.col.f32.tf32.tf32.f32 "
        "{%0,%1,%2,%3}, {%4,%5,%6,%7}, {%8,%9}, {%0,%1,%2,%3};"
        : "+f"(d.x), "+f"(d.y), "+f"(d.z), "+f"(d.w)
        : "r"(a.x), "r"(a.y), "r"(a.z), "r"(a.w), "r"(b.x), "r"(b.y));
}
__device__ __forceinline__ void cp16(void* smem_dst, const void* gsrc) {
    uint32_t sa = (uint32_t)__cvta_generic_to_shared(smem_dst);
    asm volatile("cp.async.cg.shared.global [%0], [%1], 16;" :: "r"(sa), "l"(gsrc));
}
#define CP_COMMIT() asm volatile("cp.async.commit_group;")
#define CP_WAIT0()  asm volatile("cp.async.wait_group 0;" ::: "memory")

// ============================================================
// K0: precompute weight fragments
// ============================================================
__global__ void __launch_bounds__(512)
k_prep(const float* __restrict__ Wk, const float* __restrict__ Wv,
       const float* __restrict__ Wsel, const float* __restrict__ Wsa,
       const float* __restrict__ Wse, const float* __restrict__ Wc1)
{
    int i = blockIdx.x * 512 + threadIdx.x;
    if (i < 24576) {
        int which = i >> 13;
        int j = i & 8191;
        int n8 = j >> 9, ks = (j >> 5) & 15, lane = j & 31;
        int g = lane >> 2, tig = lane & 3;
        int n = n8 * 8 + g, k = ks * 8 + tig;
        const float* W = which == 0 ? Wk : (which == 1 ? Wv : Wsel);
        const float* base = W + (n >> 5) * (HID * D) + (n & 31);
        uint2 v = make_uint2(tf32rn(base[k * 32]), tf32rn(base[(k + 4) * 32]));
        (which == 0 ? pWk : which == 1 ? pWv : pWsel)[j] = v;
        return;
    }
    int i2 = i - 24576;
    if (i2 < NAG * 5120) {
        int n = i2 / 5120, j = i2 % 5120;
        int lane = j & 31, ks = (j >> 5) % 10, n8 = j / 320;
        int g = lane >> 2, tig = lane & 3;
        int nn = n8 * 8 + g, k = ks * 8 + tig;
        const float* W = Wsa + n * KSA * HID;
        pWsa[n][j] = make_uint2(tf32rn(W[k * HID + nn]), tf32rn(W[(k + 4) * HID + nn]));
        return;
    }
    int i3 = i2 - NAG * 5120;
    if (i3 < NAG * 4096) {
        int n = i3 >> 12, j = i3 & 4095;
        int lane = j & 31, ks = (j >> 5) & 7, n8 = j >> 8;
        int g = lane >> 2, tig = lane & 3;
        int nn = n8 * 8 + g, k = ks * 8 + tig;
        const float* W = Wse + n * SD * HID;
        pWse[n][j] = make_uint2(tf32rn(W[k * HID + nn]), tf32rn(W[(k + 4) * HID + nn]));
        return;
    }
    int i4 = i3 - NAG * 4096;
    if (i4 < NAG * 16384) {
        int n = i4 >> 14, j = i4 & 16383;
        int lane = j & 31, ks = (j >> 5) & 31, n8 = j >> 10;
        int g = lane >> 2, tig = lane & 3;
        int nn = n8 * 8 + g, k = ks * 8 + tig;
        const float* W = Wc1 + (size_t)n * 2 * HID * HID;
        pWc1[n][j] = make_uint2(tf32rn(W[k * HID + nn]), tf32rn(W[(k + 4) * HID + nn]));
    }
}

// ============================================================
// K1: BN stats
// ============================================================
__global__ void __launch_bounds__(512)
k_stats1(const float* __restrict__ s, const float* __restrict__ a)
{
    __shared__ float r1[512], r2[512];
    const int n = blockIdx.y, tid = threadIdx.x;
    const size_t row0 = (size_t)n * B + blockIdx.x * 1024;
    float* part  = g_part  + (n * 16 + blockIdx.x) * KSA;
    float* partq = g_partq + (n * 16 + blockIdx.x) * KSA;

    {
        const int f = tid & 63, r0 = tid >> 6;
        float sum = 0.f, sq = 0.f;
        const float* p = s + (row0 + r0) * SD + f;
        #pragma unroll 4
        for (int st = 0; st < 128; st++) {
            float x = p[(size_t)st * 8 * SD];
            sum += x; sq += x * x;
        }
        r1[tid] = sum; r2[tid] = sq;
        __syncthreads();
        #pragma unroll
        for (int o = 4; o > 0; o >>= 1) {
            if (tid < o * 64) { r1[tid] += r1[tid + o * 64]; r2[tid] += r2[tid + o * 64]; }
            __syncthreads();
        }
        if (tid < 64) { part[tid] = r1[tid]; partq[tid] = r2[tid]; }
        __syncthreads();
    }
    {
        const int f = tid & 15, r0 = tid >> 4;
        float sum = 0.f, sq = 0.f;
        const float* p = a + (row0 + r0) * AD + f;
        #pragma unroll 4
        for (int st = 0; st < 32; st++) {
            float x = p[(size_t)st * 32 * AD];
            sum += x; sq += x * x;
        }
        r1[tid] = sum; r2[tid] = sq;
        __syncthreads();
        #pragma unroll
        for (int o = 16; o > 0; o >>= 1) {
            if (tid < o * 16) { r1[tid] += r1[tid + o * 16]; r2[tid] += r2[tid + o * 16]; }
            __syncthreads();
        }
        if (tid < 16) { part[64 + tid] = r1[tid]; partq[64 + tid] = r2[tid]; }
    }
}

__global__ void k_stats2()
{
    int i = threadIdx.x;
    if (i >= NAG * KSA) return;
    int n = i / KSA, f = i % KSA;
    float sum = 0.f, sq = 0.f;
    for (int c = 0; c < 16; c++) {
        sum += g_part [(n * 16 + c) * KSA + f];
        sq  += g_partq[(n * 16 + c) * KSA + f];
    }
    float m = sum * (1.f / B);
    float v = sq * (1.f / B) - m * m;
    g_mean[i] = m;
    g_rstd[i] = rsqrtf(v + EPS);
}

// ============================================================
// K2: FUSED front, 64-row tiles, 256 thr, 2 blocks/SM, cp.async weights
// phases: enc -> sel -> key -> val  (single W buffer, prefetch overlapped)
// ============================================================
constexpr int PAD = 132;
constexpr int FR_OFF_A    = 0;                            // 64*132*4 = 33792
constexpr int FR_OFF_W    = 33792;                        // 9216 uint2 = 73728
constexpr int FR_OFF_MISC = 107520;                       // 544 floats
constexpr int SMEM_FRONT  = 109696;

__global__ void __launch_bounds__(256, 2)
k_front(const float* __restrict__ s, const float* __restrict__ a,
        const float* __restrict__ Bsa, const float* __restrict__ Bse,
        const float* __restrict__ bv)
{
    extern __shared__ char smc[];
    uint32_t* uA = (uint32_t*)(smc + FR_OFF_A);
    uint2*    W  = (uint2*)(smc + FR_OFF_W);
    char*     Wc = smc + FR_OFF_W;
    float*   bsa = (float*)(smc + FR_OFF_MISC);
    float*   bse = bsa + 128;
    float*   bvv = bse + 128;
    float*   mn  = bvv + 128;
    float*   rsd = mn + 80;

    const int n = blockIdx.y, tid = threadIdx.x;
    const size_t gr0 = (size_t)n * B + (size_t)blockIdx.x * 64;

    // prefetch enc weights: Wsa (40960B) ++ Wse (32768B) = 4608 16B chunks
    for (int c = tid; c < 4608; c += 256) {
        const char* src = (c < 2560) ? (const char*)pWsa[n] + c * 16
                                     : (const char*)pWse[n] + (c - 2560) * 16;
        cp16(Wc + c * 16, src);
    }
    CP_COMMIT();

    for (int i = tid; i < 128; i += 256) {
        bsa[i] = Bsa[n * HID + i];
        bse[i] = Bse[n * HID + i];
        bvv[i] = bv[i];
    }
    for (int i = tid; i < 80; i += 256) {
        mn[i]  = g_mean[n * KSA + i];
        rsd[i] = g_rstd[n * KSA + i];
    }
    __syncthreads();   // mn/rsd visible

    // A fill: BN'd [64 x 80] tile
    for (int i = tid; i < 64 * 20; i += 256) {
        int r = i / 20, c4 = i - r * 20;
        size_t row = gr0 + r;
        float4 v = (c4 < 16) ? ((const float4*)s)[row * 16 + c4]
                             : ((const float4*)a)[row * 4 + (c4 - 16)];
        int c = c4 * 4;
        *(uint4*)(uA + r * PAD + c) =
            make_uint4(tf32rn((v.x - mn[c])     * rsd[c]),
                       tf32rn((v.y - mn[c + 1]) * rsd[c + 1]),
                       tf32rn((v.z - mn[c + 2]) * rsd[c + 2]),
                       tf32rn((v.w - mn[c + 3]) * rsd[c + 3]));
    }
    CP_WAIT0();
    __syncthreads();

    const int w = tid >> 5, lane = tid & 31;
    const int rs_ = w & 1, t0 = w >> 1;
    const int g = lane >> 2, tig = lane & 3;
    const uint32_t* A0 = uA + (rs_ * 32 + g) * PAD + tig;
    const uint32_t* A1 = A0 + 16 * PAD;

    // ---- Phase 1: enc ----
    float4 ae[2][4], as_[2][4];
    #pragma unroll
    for (int mi = 0; mi < 2; mi++)
        #pragma unroll
        for (int j = 0; j < 4; j++) { ae[mi][j] = make_float4(0,0,0,0); as_[mi][j] = make_float4(0,0,0,0); }

    #pragma unroll
    for (int ks = 0; ks < 10; ks++) {
        uint4 fa0 = make_uint4(A0[ks*8], A0[ks*8 + 8*PAD], A0[ks*8 + 4], A0[ks*8 + 8*PAD + 4]);
        uint4 fa1 = make_uint4(A1[ks*8], A1[ks*8 + 8*PAD], A1[ks*8 + 4], A1[ks*8 + 8*PAD + 4]);
        #pragma unroll
        for (int j = 0; j < 4; j++) {
            uint2 bb = W[((t0 * 4 + j) * 10 + ks) * 32 + lane];
            mma8(ae[0][j], fa0, bb); mma8(ae[1][j], fa1, bb);
        }
        if (ks < 8) {
            #pragma unroll
            for (int j = 0; j < 4; j++) {
                uint2 bb = W[5120 + ((t0 * 4 + j) * 8 + ks) * 32 + lane];
                mma8(as_[0][j], fa0, bb); mma8(as_[1][j], fa1, bb);
            }
        }
    }
    __syncthreads();                            // all reads of A & W done

    // prefetch Wsel while doing epilogue
    for (int c = tid; c < 4096; c += 256) cp16(Wc + c * 16, (const char*)pWsel + c * 16);
    CP_COMMIT();

    // bias+lrelu; write g_se; restage A = se
    #pragma unroll
    for (int mi = 0; mi < 2; mi++) {
        #pragma unroll
        for (int j = 0; j < 4; j++) {
            int c = t0 * 32 + j * 8 + 2 * tig;
            float b0e = bsa[c], b1e = bsa[c + 1];
            float b0s = bse[c], b1s = bse[c + 1];
            ae[mi][j]  = make_float4(lrelu(ae[mi][j].x + b0e), lrelu(ae[mi][j].y + b1e),
                                     lrelu(ae[mi][j].z + b0e), lrelu(ae[mi][j].w + b1e));
            as_[mi][j] = make_float4(lrelu(as_[mi][j].x + b0s), lrelu(as_[mi][j].y + b1s),
                                     lrelu(as_[mi][j].z + b0s), lrelu(as_[mi][j].w + b1s));
            int r = rs_ * 32 + mi * 16 + g;
            size_t gr = gr0 + r;
            *(float2*)&g_se[gr * 128 + c]       = make_float2(as_[mi][j].x, as_[mi][j].y);
            *(float2*)&g_se[(gr + 8) * 128 + c] = make_float2(as_[mi][j].z, as_[mi][j].w);
            *(uint2*)(uA + r * PAD + c)       = make_uint2(tf32rn(as_[mi][j].x), tf32rn(as_[mi][j].y));
            *(uint2*)(uA + (r + 8) * PAD + c) = make_uint2(tf32rn(as_[mi][j].z), tf32rn(as_[mi][j].w));
        }
    }
    CP_WAIT0();
    __syncthreads();

    // ---- Phase 2: sel ----
    float4 ac[2][4];
    #pragma unroll
    for (int mi = 0; mi < 2; mi++)
        #pragma unroll
        for (int j = 0; j < 4; j++) ac[mi][j] = make_float4(0,0,0,0);

    #pragma unroll
    for (int ks = 0; ks < 16; ks++) {
        uint4 fa0 = make_uint4(A0[ks*8], A0[ks*8 + 8*PAD], A0[ks*8 + 4], A0[ks*8 + 8*PAD + 4]);
        uint4 fa1 = make_uint4(A1[ks*8], A1[ks*8 + 8*PAD], A1[ks*8 + 4], A1[ks*8 + 8*PAD + 4]);
        #pragma unroll
        for (int j = 0; j < 4; j++) {
            uint2 bb = W[((t0 * 4 + j) * 16 + ks) * 32 + lane];
            mma8(ac[0][j], fa0, bb); mma8(ac[1][j], fa1, bb);
        }
    }
    __syncthreads();

    for (int c = tid; c < 4096; c += 256) cp16(Wc + c * 16, (const char*)pWk + c * 16);
    CP_COMMIT();

    #pragma unroll
    for (int mi = 0; mi < 2; mi++) {
        #pragma unroll
        for (int j = 0; j < 4; j++) {
            int r = rs_ * 32 + mi * 16 + g;
            int c = t0 * 32 + j * 8 + 2 * tig;
            size_t gr = gr0 + r;
            *(float2*)&g_sel[gr * 128 + c]       = make_float2(ac[mi][j].x, ac[mi][j].y);
            *(float2*)&g_sel[(gr + 8) * 128 + c] = make_float2(ac[mi][j].z, ac[mi][j].w);
            *(uint2*)(uA + r * PAD + c)       = make_uint2(tf32rn(ae[mi][j].x), tf32rn(ae[mi][j].y));
            *(uint2*)(uA + (r + 8) * PAD + c) = make_uint2(tf32rn(ae[mi][j].z), tf32rn(ae[mi][j].w));
        }
    }
    CP_WAIT0();
    __syncthreads();

    // ---- Phase 3: key ----
    #pragma unroll
    for (int mi = 0; mi < 2; mi++)
        #pragma unroll
        for (int j = 0; j < 4; j++) ac[mi][j] = make_float4(0,0,0,0);

    #pragma unroll
    for (int ks = 0; ks < 16; ks++) {
        uint4 fa0 = make_uint4(A0[ks*8], A0[ks*8 + 8*PAD], A0[ks*8 + 4], A0[ks*8 + 8*PAD + 4]);
        uint4 fa1 = make_uint4(A1[ks*8], A1[ks*8 + 8*PAD], A1[ks*8 + 4], A1[ks*8 + 8*PAD + 4]);
        #pragma unroll
        for (int j = 0; j < 4; j++) {
            uint2 bb = W[((t0 * 4 + j) * 16 + ks) * 32 + lane];
            mma8(ac[0][j], fa0, bb); mma8(ac[1][j], fa1, bb);
        }
    }
    __syncthreads();

    for (int c = tid; c < 4096; c += 256) cp16(Wc + c * 16, (const char*)pWv + c * 16);
    CP_COMMIT();

    #pragma unroll
    for (int mi = 0; mi < 2; mi++) {
        #pragma unroll
        for (int j = 0; j < 4; j++) {
            size_t gr = gr0 + rs_ * 32 + mi * 16 + g;
            int c = t0 * 32 + j * 8 + 2 * tig;
            *(float2*)&g_key[gr * 128 + c]       = make_float2(ac[mi][j].x, ac[mi][j].y);
            *(float2*)&g_key[(gr + 8) * 128 + c] = make_float2(ac[mi][j].z, ac[mi][j].w);
        }
    }
    CP_WAIT0();
    __syncthreads();

    // ---- Phase 4: val (A unchanged = e) ----
    #pragma unroll
    for (int mi = 0; mi < 2; mi++)
        #pragma unroll
        for (int j = 0; j < 4; j++) ac[mi][j] = make_float4(0,0,0,0);

    #pragma unroll
    for (int ks = 0; ks < 16; ks++) {
        uint4 fa0 = make_uint4(A0[ks*8], A0[ks*8 + 8*PAD], A0[ks*8 + 4], A0[ks*8 + 8*PAD + 4]);
        uint4 fa1 = make_uint4(A1[ks*8], A1[ks*8 + 8*PAD], A1[ks*8 + 4], A1[ks*8 + 8*PAD + 4]);
        #pragma unroll
        for (int j = 0; j < 4; j++) {
            uint2 bb = W[((t0 * 4 + j) * 16 + ks) * 32 + lane];
            mma8(ac[0][j], fa0, bb); mma8(ac[1][j], fa1, bb);
        }
    }
    #pragma unroll
    for (int mi = 0; mi < 2; mi++) {
        #pragma unroll
        for (int j = 0; j < 4; j++) {
            size_t gr = gr0 + rs_ * 32 + mi * 16 + g;
            int c = t0 * 32 + j * 8 + 2 * tig;
            float bb0 = bvv[c], bb1 = bvv[c + 1];
            *(float2*)&g_val[gr * 128 + c]       = make_float2(lrelu(ac[mi][j].x + bb0), lrelu(ac[mi][j].y + bb1));
            *(float2*)&g_val[(gr + 8) * 128 + c] = make_float2(lrelu(ac[mi][j].z + bb0), lrelu(ac[mi][j].w + bb1));
        }
    }
}

// ============================================================
// K3: attention
// ============================================================
__global__ void __launch_bounds__(256, 4)
k_attn()
{
    __shared__ float smem[8][3 * 8 * 33 + 64];
    const int tid = threadIdx.x, warp = tid >> 5, lane = tid & 31;
    const int gid = blockIdx.x * 8 + warp;
    const int b = gid >> 2;
    const int p = gid & 3;

    float* selS = smem[warp];
    float* keyS = selS + 8 * 33;
    float* valS = keyS + 8 * 33;
    float* wS   = valS + 8 * 33;
    const float scale = 0.17677669529663687f;

    #pragma unroll
    for (int i = 0; i < 8; i++) {
        size_t base = ((size_t)i * B + b) * HID + p * D + lane;
        selS[i * 33 + lane] = g_sel[base];
        keyS[i * 33 + lane] = g_key[base];
        valS[i * 33 + lane] = g_val[base];
    }
    __syncwarp();

    const int i0 = lane >> 3, j = lane & 7, i1 = i0 + 4;
    float acc0 = 0.f, acc1 = 0.f;
    #pragma unroll
    for (int d = 0; d < 32; d++) {
        float kv = keyS[j * 33 + d];
        acc0 += selS[i0 * 33 + d] * kv;
        acc1 += selS[i1 * 33 + d] * kv;
    }
    acc0 *= scale; acc1 *= scale;
    if (i0 == j) acc0 = -1e9f;
    if (i1 == j) acc1 = -1e9f;

    float m0 = acc0, m1 = acc1;
    #pragma unroll
    for (int o = 1; o < 8; o <<= 1) {
        m0 = fmaxf(m0, __shfl_xor_sync(FULLMASK, m0, o));
        m1 = fmaxf(m1, __shfl_xor_sync(FULLMASK, m1, o));
    }
    float e0 = expf(acc0 - m0), e1 = expf(acc1 - m1);
    float s0 = e0, s1 = e1;
    #pragma unroll
    for (int o = 1; o < 8; o <<= 1) {
        s0 += __shfl_xor_sync(FULLMASK, s0, o);
        s1 += __shfl_xor_sync(FULLMASK, s1, o);
    }
    wS[lane]      = e0 / s0;
    wS[lane + 32] = e1 / s1;
    __syncwarp();

    float out[8];
    #pragma unroll
    for (int ii = 0; ii < 8; ii++) out[ii] = 0.f;
    #pragma unroll
    for (int jj = 0; jj < 8; jj++) {
        float v = valS[jj * 33 + lane];
        #pragma unroll
        for (int ii = 0; ii < 8; ii++) out[ii] += wS[ii * 8 + jj] * v;
    }
    #pragma unroll
    for (int ii = 0; ii < 8; ii++)
        g_oth[((size_t)ii * B + b) * HID + p * D + lane] = out[ii];
}

// ============================================================
// K4: critic, 64-row tiles, 256 thr, 2 blocks/SM, cp.async W1
// ============================================================
constexpr int HSTR = 132;
constexpr int CR_OFF_A   = 0;                             // 64*132*4 = 33792 (h reuses)
constexpr int CR_OFF_B1  = 33792;                         // 65536
constexpr int CR_OFF_W2  = 99328;                         // 8448
constexpr int CR_OFF_B1S = 107776;                        // 512
constexpr int CR_OFF_B2S = 108288;                        // 64
constexpr int SMEM_CRIT  = 108352;

__global__ void __launch_bounds__(256, 2)
k_crit(const float* __restrict__ a,
       const float* __restrict__ Bc1,
       const float* __restrict__ Wc2, const float* __restrict__ Bc2,
       float* __restrict__ out)
{
    extern __shared__ char smc[];
    uint32_t* uA = (uint32_t*)(smc + CR_OFF_A);
    uint2*    B1 = (uint2*)(smc + CR_OFF_B1);
    char*    B1c = smc + CR_OFF_B1;
    float*    h  = (float*)(smc + CR_OFF_A);               // reuses A after mma
    float*   w2t = (float*)(smc + CR_OFF_W2);
    float*   b1s = (float*)(smc + CR_OFF_B1S);
    float*   b2s = (float*)(smc + CR_OFF_B2S);

    const int n = blockIdx.y, tid = threadIdx.x;
    const int w = tid >> 5, lane = tid & 31;
    const size_t row0 = (size_t)n * B + (size_t)blockIdx.x * 64;

    for (int i = tid; i < HID * AD; i += 256) {
        int k = i >> 4, o = i & 15;
        w2t[o * HSTR + k] = Wc2[n * HID * AD + k * AD + o];
    }
    if (tid < HID) b1s[tid] = Bc1[n * HID + tid];
    if (tid >= HID && tid < HID + AD) b2s[tid - HID] = Bc2[n * AD + (tid - HID)];

    const int rs_ = w & 1, cq = w >> 1;
    const int g = lane >> 2, tig = lane & 3;

    float4 acc[2][4];
    #pragma unroll
    for (int mi = 0; mi < 2; mi++)
        #pragma unroll
        for (int j = 0; j < 4; j++) acc[mi][j] = make_float4(0,0,0,0);

    const uint32_t* A0 = uA + (rs_ * 32 + g) * PAD + tig;
    const uint32_t* A1 = A0 + 16 * PAD;

    #pragma unroll 1
    for (int ph = 0; ph < 2; ph++) {
        // prefetch this phase's W1 fragments (16B = 2 uint2 chunks; lane pairs contiguous)
        for (int cc = tid; cc < 4096; cc += 256) {
            int ln2 = (cc & 15) * 2, ksl = (cc >> 4) & 15, n8 = cc >> 8;
            const char* src = (const char*)&pWc1[n][((n8 * 32) + ph * 16 + ksl) * 32 + ln2];
            cp16(B1c + cc * 16, src);
        }
        CP_COMMIT();
        {   // A fill
            const float* src = ph == 0 ? g_se : g_oth;
            const float4* s4 = (const float4*)src;
            for (int i = tid; i < 64 * 32; i += 256) {
                int r = i >> 5, c4 = i & 31;
                float4 v = s4[(row0 + r) * 32 + c4];
                *(uint4*)(uA + r * PAD + c4 * 4) =
                    make_uint4(tf32rn(v.x), tf32rn(v.y), tf32rn(v.z), tf32rn(v.w));
            }
        }
        CP_WAIT0();
        __syncthreads();
        #pragma unroll
        for (int ks = 0; ks < 16; ks++) {
            uint4 fa0 = make_uint4(A0[ks*8], A0[ks*8 + 8*PAD], A0[ks*8 + 4], A0[ks*8 + 8*PAD + 4]);
            uint4 fa1 = make_uint4(A1[ks*8], A1[ks*8 + 8*PAD], A1[ks*8 + 4], A1[ks*8 + 8*PAD + 4]);
            #pragma unroll
            for (int j = 0; j < 4; j++) {
                uint2 bb = B1[((cq * 4 + j) * 16 + ks) * 32 + lane];
                mma8(acc[0][j], fa0, bb); mma8(acc[1][j], fa1, bb);
            }
        }
        __syncthreads();
    }

    #pragma unroll
    for (int mi = 0; mi < 2; mi++) {
        #pragma unroll
        for (int j = 0; j < 4; j++) {
            int r = rs_ * 32 + mi * 16 + g;
            int c = cq * 32 + j * 8 + 2 * tig;
            float bb0 = b1s[c], bb1 = b1s[c + 1];
            h[r * HSTR + c]           = lrelu(acc[mi][j].x + bb0);
            h[r * HSTR + c + 1]       = lrelu(acc[mi][j].y + bb1);
            h[(r + 8) * HSTR + c]     = lrelu(acc[mi][j].z + bb0);
            h[(r + 8) * HSTR + c + 1] = lrelu(acc[mi][j].w + bb1);
        }
    }
    __syncthreads();

    const int o = lane & 15, half = lane >> 4;
    for (int rr = 0; rr < 8; rr++) {
        const int r = w * 8 + rr;
        const int bidx = blockIdx.x * 64 + r;
        const float4* hr4 = (const float4*)(h + r * HSTR + half * 64);
        const float4* w4  = (const float4*)(w2t + o * HSTR + half * 64);
        float q = 0.f;
        #pragma unroll
        for (int i = 0; i < 16; i++) {
            float4 hv = hr4[i], wv = w4[i];
            q += hv.x * wv.x + hv.y * wv.y + hv.z * wv.z + hv.w * wv.w;
        }
        q += __shfl_xor_sync(FULLMASK, q, 16);
        q += b2s[o];

        float av = (lane < AD) ? a[((size_t)n * B + bidx) * AD + lane] : -1e30f;
        int   ai = (lane < AD) ? lane : 1000;
        float bestv = av; int besti = ai;
        #pragma unroll
        for (int off = 16; off > 0; off >>= 1) {
            float ov = __shfl_xor_sync(FULLMASK, bestv, off);
            int   oi = __shfl_xor_sync(FULLMASK, besti, off);
            if (ov > bestv || (ov == bestv && oi < besti)) { bestv = ov; besti = oi; }
        }
        float qsel = __shfl_sync(FULLMASK, q, besti);
        if (lane == 0) out[(size_t)n * B + bidx] = qsel;
    }
}

// ============================================================
extern "C" void kernel_launch(void* const* d_in, const int* in_sizes, int n_in,
                              void* d_out, int out_size)
{
    const float* s    = (const float*)d_in[0];
    const float* a    = (const float*)d_in[1];
    const float* Wsa  = (const float*)d_in[2];
    const float* Bsa  = (const float*)d_in[3];
    const float* Wse  = (const float*)d_in[4];
    const float* Bse  = (const float*)d_in[5];
    const float* Wk   = (const float*)d_in[6];
    const float* Wsel = (const float*)d_in[7];
    const float* Wv   = (const float*)d_in[8];
    const float* bv   = (const float*)d_in[9];
    const float* Wc1  = (const float*)d_in[10];
    const float* Bc1  = (const float*)d_in[11];
    const float* Wc2  = (const float*)d_in[12];
    const float* Bc2  = (const float*)d_in[13];
    float* out = (float*)d_out;

    cudaFuncSetAttribute(k_front, cudaFuncAttributeMaxDynamicSharedMemorySize, SMEM_FRONT);
    cudaFuncSetAttribute(k_crit,  cudaFuncAttributeMaxDynamicSharedMemorySize, SMEM_CRIT);

    k_prep   <<<448, 512>>>(Wk, Wv, Wsel, Wsa, Wse, Wc1);
    k_stats1 <<<dim3(16, NAG), 512>>>(s, a);
    k_stats2 <<<1, 640>>>();
    k_front  <<<dim3(B / 64, NAG), 256, SMEM_FRONT>>>(s, a, Bsa, Bse, bv);
    k_attn   <<<dim3((HEADS * B) / 8), 256>>>();
    k_crit   <<<dim3(B / 64, NAG), 256, SMEM_CRIT>>>(a, Bc1, Wc2, Bc2, out);
}

// round 7
// speedup vs baseline: 2.9243x; 1.0493x over previous
#include <cuda_runtime.h>
#include <math.h>
#include <stdint.h>

#define FULLMASK 0xffffffffu

constexpr int NAG  = 8;
constexpr int B    = 16384;
constexpr int SD   = 64;
constexpr int AD   = 16;
constexpr int KSA  = 80;
constexpr int HID  = 128;
constexpr int HEADS= 4;
constexpr int D    = 32;
constexpr float EPS = 1e-5f;

// -------- scratch --------
__device__ __align__(16) float g_mean[NAG * KSA];
__device__ __align__(16) float g_rstd[NAG * KSA];
__device__ __align__(16) float g_part [NAG * 16 * KSA];
__device__ __align__(16) float g_partq[NAG * 16 * KSA];
__device__ __align__(16) float g_se [(size_t)NAG * B * HID];
__device__ __align__(16) float g_key[(size_t)NAG * B * HID];
__device__ __align__(16) float g_val[(size_t)NAG * B * HID];
__device__ __align__(16) float g_sel[(size_t)NAG * B * HID];
__device__ __align__(16) float g_oth[(size_t)NAG * B * HID];

// fragment-order tf32 weights (filled once per launch by k_prep)
__device__ __align__(16) uint2 pWk  [16 * 16 * 32];
__device__ __align__(16) uint2 pWv  [16 * 16 * 32];
__device__ __align__(16) uint2 pWsel[16 * 16 * 32];
__device__ __align__(16) uint2 pWsa [NAG][16 * 10 * 32];
__device__ __align__(16) uint2 pWse [NAG][16 * 8 * 32];
__device__ __align__(16) uint2 pWc1 [NAG][16 * 32 * 32];

__device__ __forceinline__ float lrelu(float x) { return x > 0.f ? x : 0.01f * x; }

__device__ __forceinline__ uint32_t tf32rn(float x) {
    uint32_t u; asm("cvt.rna.tf32.f32 %0, %1;" : "=r"(u) : "f"(x)); return u;
}
__device__ __forceinline__ void mma8(float4& d, const uint4 a, const uint2 b) {
    asm volatile(
        "mma.sync.aligned.m16n8k8.row.col.f32.tf32.tf32.f32 "
        "{%0,%1,%2,%3}, {%4,%5,%6,%7}, {%8,%9}, {%0,%1,%2,%3};"
        : "+f"(d.x), "+f"(d.y), "+f"(d.z), "+f"(d.w)
        : "r"(a.x), "r"(a.y), "r"(a.z), "r"(a.w), "r"(b.x), "r"(b.y));
}
__device__ __forceinline__ void cp16(void* smem_dst, const void* gsrc) {
    uint32_t sa = (uint32_t)__cvta_generic_to_shared(smem_dst);
    asm volatile("cp.async.cg.shared.global [%0], [%1], 16;" :: "r"(sa), "l"(gsrc));
}
#define CP_COMMIT() asm volatile("cp.async.commit_group;")
#define CP_WAIT0()  asm volatile("cp.async.wait_group 0;" ::: "memory")

// ============================================================
// K0: precompute weight fragments
// ============================================================
__global__ void __launch_bounds__(512)
k_prep(const float* __restrict__ Wk, const float* __restrict__ Wv,
       const float* __restrict__ Wsel, const float* __restrict__ Wsa,
       const float* __restrict__ Wse, const float* __restrict__ Wc1)
{
    int i = blockIdx.x * 512 + threadIdx.x;
    if (i < 24576) {
        int which = i >> 13;
        int j = i & 8191;
        int n8 = j >> 9, ks = (j >> 5) & 15, lane = j & 31;
        int g = lane >> 2, tig = lane & 3;
        int n = n8 * 8 + g, k = ks * 8 + tig;
        const float* W = which == 0 ? Wk : (which == 1 ? Wv : Wsel);
        const float* base = W + (n >> 5) * (HID * D) + (n & 31);
        uint2 v = make_uint2(tf32rn(base[k * 32]), tf32rn(base[(k + 4) * 32]));
        (which == 0 ? pWk : which == 1 ? pWv : pWsel)[j] = v;
        return;
    }
    int i2 = i - 24576;
    if (i2 < NAG * 5120) {
        int n = i2 / 5120, j = i2 % 5120;
        int lane = j & 31, ks = (j >> 5) % 10, n8 = j / 320;
        int g = lane >> 2, tig = lane & 3;
        int nn = n8 * 8 + g, k = ks * 8 + tig;
        const float* W = Wsa + n * KSA * HID;
        pWsa[n][j] = make_uint2(tf32rn(W[k * HID + nn]), tf32rn(W[(k + 4) * HID + nn]));
        return;
    }
    int i3 = i2 - NAG * 5120;
    if (i3 < NAG * 4096) {
        int n = i3 >> 12, j = i3 & 4095;
        int lane = j & 31, ks = (j >> 5) & 7, n8 = j >> 8;
        int g = lane >> 2, tig = lane & 3;
        int nn = n8 * 8 + g, k = ks * 8 + tig;
        const float* W = Wse + n * SD * HID;
        pWse[n][j] = make_uint2(tf32rn(W[k * HID + nn]), tf32rn(W[(k + 4) * HID + nn]));
        return;
    }
    int i4 = i3 - NAG * 4096;
    if (i4 < NAG * 16384) {
        int n = i4 >> 14, j = i4 & 16383;
        int lane = j & 31, ks = (j >> 5) & 31, n8 = j >> 10;
        int g = lane >> 2, tig = lane & 3;
        int nn = n8 * 8 + g, k = ks * 8 + tig;
        const float* W = Wc1 + (size_t)n * 2 * HID * HID;
        pWc1[n][j] = make_uint2(tf32rn(W[k * HID + nn]), tf32rn(W[(k + 4) * HID + nn]));
    }
}

// ============================================================
// K1: BN stats
// ============================================================
__global__ void __launch_bounds__(512)
k_stats1(const float* __restrict__ s, const float* __restrict__ a)
{
    __shared__ float r1[512], r2[512];
    const int n = blockIdx.y, tid = threadIdx.x;
    const size_t row0 = (size_t)n * B + blockIdx.x * 1024;
    float* part  = g_part  + (n * 16 + blockIdx.x) * KSA;
    float* partq = g_partq + (n * 16 + blockIdx.x) * KSA;

    {
        const int f = tid & 63, r0 = tid >> 6;
        float sum = 0.f, sq = 0.f;
        const float* p = s + (row0 + r0) * SD + f;
        #pragma unroll 4
        for (int st = 0; st < 128; st++) {
            float x = p[(size_t)st * 8 * SD];
            sum += x; sq += x * x;
        }
        r1[tid] = sum; r2[tid] = sq;
        __syncthreads();
        #pragma unroll
        for (int o = 4; o > 0; o >>= 1) {
            if (tid < o * 64) { r1[tid] += r1[tid + o * 64]; r2[tid] += r2[tid + o * 64]; }
            __syncthreads();
        }
        if (tid < 64) { part[tid] = r1[tid]; partq[tid] = r2[tid]; }
        __syncthreads();
    }
    {
        const int f = tid & 15, r0 = tid >> 4;
        float sum = 0.f, sq = 0.f;
        const float* p = a + (row0 + r0) * AD + f;
        #pragma unroll 4
        for (int st = 0; st < 32; st++) {
            float x = p[(size_t)st * 32 * AD];
            sum += x; sq += x * x;
        }
        r1[tid] = sum; r2[tid] = sq;
        __syncthreads();
        #pragma unroll
        for (int o = 16; o > 0; o >>= 1) {
            if (tid < o * 16) { r1[tid] += r1[tid + o * 16]; r2[tid] += r2[tid + o * 16]; }
            __syncthreads();
        }
        if (tid < 16) { part[64 + tid] = r1[tid]; partq[64 + tid] = r2[tid]; }
    }
}

__global__ void k_stats2()
{
    int i = threadIdx.x;
    if (i >= NAG * KSA) return;
    int n = i / KSA, f = i % KSA;
    float sum = 0.f, sq = 0.f;
    for (int c = 0; c < 16; c++) {
        sum += g_part [(n * 16 + c) * KSA + f];
        sq  += g_partq[(n * 16 + c) * KSA + f];
    }
    float m = sum * (1.f / B);
    float v = sq * (1.f / B) - m * m;
    g_mean[i] = m;
    g_rstd[i] = rsqrtf(v + EPS);
}

// ============================================================
// K2: FUSED front: enc -> sel -> kv (key+val in ONE A-pass, K-split W staging)
// 64-row tiles, 256 thr, 2 blocks/SM, cp.async weights
// ============================================================
constexpr int PAD = 132;
constexpr int FR_OFF_A    = 0;                            // 64*132*4 = 33792
constexpr int FR_OFF_W    = 33792;                        // 73728
constexpr int FR_OFF_MISC = 107520;                       // 544 floats
constexpr int SMEM_FRONT  = 109696;

__global__ void __launch_bounds__(256, 2)
k_front(const float* __restrict__ s, const float* __restrict__ a,
        const float* __restrict__ Bsa, const float* __restrict__ Bse,
        const float* __restrict__ bv)
{
    extern __shared__ char smc[];
    uint32_t* uA = (uint32_t*)(smc + FR_OFF_A);
    uint2*    W  = (uint2*)(smc + FR_OFF_W);
    char*     Wc = smc + FR_OFF_W;
    float*   bsa = (float*)(smc + FR_OFF_MISC);
    float*   bse = bsa + 128;
    float*   bvv = bse + 128;
    float*   mn  = bvv + 128;
    float*   rsd = mn + 80;

    const int n = blockIdx.y, tid = threadIdx.x;
    const size_t gr0 = (size_t)n * B + (size_t)blockIdx.x * 64;

    // prefetch enc weights: Wsa (40960B) ++ Wse (32768B)
    for (int c = tid; c < 4608; c += 256) {
        const char* src = (c < 2560) ? (const char*)pWsa[n] + c * 16
                                     : (const char*)pWse[n] + (c - 2560) * 16;
        cp16(Wc + c * 16, src);
    }
    CP_COMMIT();

    for (int i = tid; i < 128; i += 256) {
        bsa[i] = Bsa[n * HID + i];
        bse[i] = Bse[n * HID + i];
        bvv[i] = bv[i];
    }
    for (int i = tid; i < 80; i += 256) {
        mn[i]  = g_mean[n * KSA + i];
        rsd[i] = g_rstd[n * KSA + i];
    }
    __syncthreads();

    // A fill: BN'd [64 x 80] tile
    for (int i = tid; i < 64 * 20; i += 256) {
        int r = i / 20, c4 = i - r * 20;
        size_t row = gr0 + r;
        float4 v = (c4 < 16) ? ((const float4*)s)[row * 16 + c4]
                             : ((const float4*)a)[row * 4 + (c4 - 16)];
        int c = c4 * 4;
        *(uint4*)(uA + r * PAD + c) =
            make_uint4(tf32rn((v.x - mn[c])     * rsd[c]),
                       tf32rn((v.y - mn[c + 1]) * rsd[c + 1]),
                       tf32rn((v.z - mn[c + 2]) * rsd[c + 2]),
                       tf32rn((v.w - mn[c + 3]) * rsd[c + 3]));
    }
    CP_WAIT0();
    __syncthreads();

    const int w = tid >> 5, lane = tid & 31;
    const int rs_ = w & 1, t0 = w >> 1;
    const int g = lane >> 2, tig = lane & 3;
    const uint32_t* A0 = uA + (rs_ * 32 + g) * PAD + tig;
    const uint32_t* A1 = A0 + 16 * PAD;

    // ---- Phase 1: enc ----
    float4 ae[2][4], as_[2][4];
    #pragma unroll
    for (int mi = 0; mi < 2; mi++)
        #pragma unroll
        for (int j = 0; j < 4; j++) { ae[mi][j] = make_float4(0,0,0,0); as_[mi][j] = make_float4(0,0,0,0); }

    #pragma unroll
    for (int ks = 0; ks < 10; ks++) {
        uint4 fa0 = make_uint4(A0[ks*8], A0[ks*8 + 8*PAD], A0[ks*8 + 4], A0[ks*8 + 8*PAD + 4]);
        uint4 fa1 = make_uint4(A1[ks*8], A1[ks*8 + 8*PAD], A1[ks*8 + 4], A1[ks*8 + 8*PAD + 4]);
        #pragma unroll
        for (int j = 0; j < 4; j++) {
            uint2 bb = W[((t0 * 4 + j) * 10 + ks) * 32 + lane];
            mma8(ae[0][j], fa0, bb); mma8(ae[1][j], fa1, bb);
        }
        if (ks < 8) {
            #pragma unroll
            for (int j = 0; j < 4; j++) {
                uint2 bb = W[5120 + ((t0 * 4 + j) * 8 + ks) * 32 + lane];
                mma8(as_[0][j], fa0, bb); mma8(as_[1][j], fa1, bb);
            }
        }
    }
    __syncthreads();

    // prefetch Wsel during epilogue
    for (int c = tid; c < 4096; c += 256) cp16(Wc + c * 16, (const char*)pWsel + c * 16);
    CP_COMMIT();

    // bias+lrelu; write g_se; restage A = se
    #pragma unroll
    for (int mi = 0; mi < 2; mi++) {
        #pragma unroll
        for (int j = 0; j < 4; j++) {
            int c = t0 * 32 + j * 8 + 2 * tig;
            float b0e = bsa[c], b1e = bsa[c + 1];
            float b0s = bse[c], b1s = bse[c + 1];
            ae[mi][j]  = make_float4(lrelu(ae[mi][j].x + b0e), lrelu(ae[mi][j].y + b1e),
                                     lrelu(ae[mi][j].z + b0e), lrelu(ae[mi][j].w + b1e));
            as_[mi][j] = make_float4(lrelu(as_[mi][j].x + b0s), lrelu(as_[mi][j].y + b1s),
                                     lrelu(as_[mi][j].z + b0s), lrelu(as_[mi][j].w + b1s));
            int r = rs_ * 32 + mi * 16 + g;
            size_t gr = gr0 + r;
            *(float2*)&g_se[gr * 128 + c]       = make_float2(as_[mi][j].x, as_[mi][j].y);
            *(float2*)&g_se[(gr + 8) * 128 + c] = make_float2(as_[mi][j].z, as_[mi][j].w);
            *(uint2*)(uA + r * PAD + c)       = make_uint2(tf32rn(as_[mi][j].x), tf32rn(as_[mi][j].y));
            *(uint2*)(uA + (r + 8) * PAD + c) = make_uint2(tf32rn(as_[mi][j].z), tf32rn(as_[mi][j].w));
        }
    }
    CP_WAIT0();
    __syncthreads();

    // ---- Phase 2: sel ----
    float4 ac[2][4];
    #pragma unroll
    for (int mi = 0; mi < 2; mi++)
        #pragma unroll
        for (int j = 0; j < 4; j++) ac[mi][j] = make_float4(0,0,0,0);

    #pragma unroll
    for (int ks = 0; ks < 16; ks++) {
        uint4 fa0 = make_uint4(A0[ks*8], A0[ks*8 + 8*PAD], A0[ks*8 + 4], A0[ks*8 + 8*PAD + 4]);
        uint4 fa1 = make_uint4(A1[ks*8], A1[ks*8 + 8*PAD], A1[ks*8 + 4], A1[ks*8 + 8*PAD + 4]);
        #pragma unroll
        for (int j = 0; j < 4; j++) {
            uint2 bb = W[((t0 * 4 + j) * 16 + ks) * 32 + lane];
            mma8(ac[0][j], fa0, bb); mma8(ac[1][j], fa1, bb);
        }
    }
    __syncthreads();

    // prefetch kv half0: Wk ks0-7 ++ Wv ks0-7 (each n8 block: 2KB contiguous)
    for (int c = tid; c < 4096; c += 256) {
        int m = c & 2047;
        int n8 = m >> 7, in8 = m & 127;
        const char* base = (c < 2048) ? (const char*)pWk : (const char*)pWv;
        cp16(Wc + c * 16, base + n8 * 4096 + in8 * 16);
    }
    CP_COMMIT();

    // sel epilogue: store g_sel; restage A = e
    #pragma unroll
    for (int mi = 0; mi < 2; mi++) {
        #pragma unroll
        for (int j = 0; j < 4; j++) {
            int r = rs_ * 32 + mi * 16 + g;
            int c = t0 * 32 + j * 8 + 2 * tig;
            size_t gr = gr0 + r;
            *(float2*)&g_sel[gr * 128 + c]       = make_float2(ac[mi][j].x, ac[mi][j].y);
            *(float2*)&g_sel[(gr + 8) * 128 + c] = make_float2(ac[mi][j].z, ac[mi][j].w);
            *(uint2*)(uA + r * PAD + c)       = make_uint2(tf32rn(ae[mi][j].x), tf32rn(ae[mi][j].y));
            *(uint2*)(uA + (r + 8) * PAD + c) = make_uint2(tf32rn(ae[mi][j].z), tf32rn(ae[mi][j].w));
        }
    }
    CP_WAIT0();
    __syncthreads();

    // ---- Phase 3: key+val merged, two K halves ----
    float4 acv[2][4];
    #pragma unroll
    for (int mi = 0; mi < 2; mi++)
        #pragma unroll
        for (int j = 0; j < 4; j++) { ac[mi][j] = make_float4(0,0,0,0); acv[mi][j] = make_float4(0,0,0,0); }

    #pragma unroll 1
    for (int h = 0; h < 2; h++) {
        #pragma unroll
        for (int ksl = 0; ksl < 8; ksl++) {
            int ks = h * 8 + ksl;
            uint4 fa0 = make_uint4(A0[ks*8], A0[ks*8 + 8*PAD], A0[ks*8 + 4], A0[ks*8 + 8*PAD + 4]);
            uint4 fa1 = make_uint4(A1[ks*8], A1[ks*8 + 8*PAD], A1[ks*8 + 4], A1[ks*8 + 8*PAD + 4]);
            #pragma unroll
            for (int j = 0; j < 4; j++) {
                int bi = ((t0 * 4 + j) * 8 + ksl) * 32 + lane;
                uint2 bk = W[bi];
                uint2 bw = W[4096 + bi];
                mma8(ac[0][j],  fa0, bk); mma8(ac[1][j],  fa1, bk);
                mma8(acv[0][j], fa0, bw); mma8(acv[1][j], fa1, bw);
            }
        }
        if (h == 0) {
            __syncthreads();
            // stage half1 (ks 8..15)
            for (int c = tid; c < 4096; c += 256) {
                int m = c & 2047;
                int n8 = m >> 7, in8 = m & 127;
                const char* base = (c < 2048) ? (const char*)pWk : (const char*)pWv;
                cp16(Wc + c * 16, base + n8 * 4096 + 2048 + in8 * 16);
            }
            CP_COMMIT();
            CP_WAIT0();
            __syncthreads();
        }
    }

    // kv epilogue
    #pragma unroll
    for (int mi = 0; mi < 2; mi++) {
        #pragma unroll
        for (int j = 0; j < 4; j++) {
            size_t gr = gr0 + rs_ * 32 + mi * 16 + g;
            int c = t0 * 32 + j * 8 + 2 * tig;
            *(float2*)&g_key[gr * 128 + c]       = make_float2(ac[mi][j].x, ac[mi][j].y);
            *(float2*)&g_key[(gr + 8) * 128 + c] = make_float2(ac[mi][j].z, ac[mi][j].w);
            float bb0 = bvv[c], bb1 = bvv[c + 1];
            *(float2*)&g_val[gr * 128 + c]       = make_float2(lrelu(acv[mi][j].x + bb0), lrelu(acv[mi][j].y + bb1));
            *(float2*)&g_val[(gr + 8) * 128 + c] = make_float2(lrelu(acv[mi][j].z + bb0), lrelu(acv[mi][j].w + bb1));
        }
    }
}

// ============================================================
// K3: attention
// ============================================================
__global__ void __launch_bounds__(256, 4)
k_attn()
{
    __shared__ float smem[8][3 * 8 * 33 + 64];
    const int tid = threadIdx.x, warp = tid >> 5, lane = tid & 31;
    const int gid = blockIdx.x * 8 + warp;
    const int b = gid >> 2;
    const int p = gid & 3;

    float* selS = smem[warp];
    float* keyS = selS + 8 * 33;
    float* valS = keyS + 8 * 33;
    float* wS   = valS + 8 * 33;
    const float scale = 0.17677669529663687f;

    #pragma unroll
    for (int i = 0; i < 8; i++) {
        size_t base = ((size_t)i * B + b) * HID + p * D + lane;
        selS[i * 33 + lane] = g_sel[base];
        keyS[i * 33 + lane] = g_key[base];
        valS[i * 33 + lane] = g_val[base];
    }
    __syncwarp();

    const int i0 = lane >> 3, j = lane & 7, i1 = i0 + 4;
    float acc0 = 0.f, acc1 = 0.f;
    #pragma unroll
    for (int d = 0; d < 32; d++) {
        float kv = keyS[j * 33 + d];
        acc0 += selS[i0 * 33 + d] * kv;
        acc1 += selS[i1 * 33 + d] * kv;
    }
    acc0 *= scale; acc1 *= scale;
    if (i0 == j) acc0 = -1e9f;
    if (i1 == j) acc1 = -1e9f;

    float m0 = acc0, m1 = acc1;
    #pragma unroll
    for (int o = 1; o < 8; o <<= 1) {
        m0 = fmaxf(m0, __shfl_xor_sync(FULLMASK, m0, o));
        m1 = fmaxf(m1, __shfl_xor_sync(FULLMASK, m1, o));
    }
    float e0 = expf(acc0 - m0), e1 = expf(acc1 - m1);
    float s0 = e0, s1 = e1;
    #pragma unroll
    for (int o = 1; o < 8; o <<= 1) {
        s0 += __shfl_xor_sync(FULLMASK, s0, o);
        s1 += __shfl_xor_sync(FULLMASK, s1, o);
    }
    wS[lane]      = e0 / s0;
    wS[lane + 32] = e1 / s1;
    __syncwarp();

    float out[8];
    #pragma unroll
    for (int ii = 0; ii < 8; ii++) out[ii] = 0.f;
    #pragma unroll
    for (int jj = 0; jj < 8; jj++) {
        float v = valS[jj * 33 + lane];
        #pragma unroll
        for (int ii = 0; ii < 8; ii++) out[ii] += wS[ii * 8 + jj] * v;
    }
    #pragma unroll
    for (int ii = 0; ii < 8; ii++)
        g_oth[((size_t)ii * B + b) * HID + p * D + lane] = out[ii];
}

// ============================================================
// K4: critic, 64-row tiles, 256 thr, 2 blocks/SM, cp.async W1
// argmax precomputed per block into smem
// ============================================================
constexpr int HSTR = 132;
constexpr int CR_OFF_A   = 0;                             // 33792 (h reuses)
constexpr int CR_OFF_B1  = 33792;                         // 65536
constexpr int CR_OFF_W2  = 99328;                         // 8448
constexpr int CR_OFF_B1S = 107776;                        // 512
constexpr int CR_OFF_B2S = 108288;                        // 64
constexpr int CR_OFF_AMX = 108352;                        // 64 ints
constexpr int SMEM_CRIT  = 108608;

__global__ void __launch_bounds__(256, 2)
k_crit(const float* __restrict__ a,
       const float* __restrict__ Bc1,
       const float* __restrict__ Wc2, const float* __restrict__ Bc2,
       float* __restrict__ out)
{
    extern __shared__ char smc[];
    uint32_t* uA = (uint32_t*)(smc + CR_OFF_A);
    uint2*    B1 = (uint2*)(smc + CR_OFF_B1);
    char*    B1c = smc + CR_OFF_B1;
    float*    h  = (float*)(smc + CR_OFF_A);
    float*   w2t = (float*)(smc + CR_OFF_W2);
    float*   b1s = (float*)(smc + CR_OFF_B1S);
    float*   b2s = (float*)(smc + CR_OFF_B2S);
    int*     amx = (int*)(smc + CR_OFF_AMX);

    const int n = blockIdx.y, tid = threadIdx.x;
    const int w = tid >> 5, lane = tid & 31;
    const size_t row0 = (size_t)n * B + (size_t)blockIdx.x * 64;

    for (int i = tid; i < HID * AD; i += 256) {
        int k = i >> 4, o = i & 15;
        w2t[o * HSTR + k] = Wc2[n * HID * AD + k * AD + o];
    }
    if (tid < HID) b1s[tid] = Bc1[n * HID + tid];
    if (tid >= HID && tid < HID + AD) b2s[tid - HID] = Bc2[n * AD + (tid - HID)];

    // per-row argmax of a[n, b, 0..15] (first-max semantics)
    if (tid < 64) {
        const float4* ap = (const float4*)(a + (row0 + tid) * AD);
        float4 q0 = ap[0], q1 = ap[1], q2 = ap[2], q3 = ap[3];
        float vals[16] = {q0.x,q0.y,q0.z,q0.w, q1.x,q1.y,q1.z,q1.w,
                          q2.x,q2.y,q2.z,q2.w, q3.x,q3.y,q3.z,q3.w};
        int bi = 0; float bvv = vals[0];
        #pragma unroll
        for (int i = 1; i < 16; i++) if (vals[i] > bvv) { bvv = vals[i]; bi = i; }
        amx[tid] = bi;
    }

    const int rs_ = w & 1, cq = w >> 1;
    const int g = lane >> 2, tig = lane & 3;

    float4 acc[2][4];
    #pragma unroll
    for (int mi = 0; mi < 2; mi++)
        #pragma unroll
        for (int j = 0; j < 4; j++) acc[mi][j] = make_float4(0,0,0,0);

    const uint32_t* A0 = uA + (rs_ * 32 + g) * PAD + tig;
    const uint32_t* A1 = A0 + 16 * PAD;

    #pragma unroll 1
    for (int ph = 0; ph < 2; ph++) {
        for (int cc = tid; cc < 4096; cc += 256) {
            int ln2 = (cc & 15) * 2, ksl = (cc >> 4) & 15, n8 = cc >> 8;
            const char* src = (const char*)&pWc1[n][((n8 * 32) + ph * 16 + ksl) * 32 + ln2];
            cp16(B1c + cc * 16, src);
        }
        CP_COMMIT();
        {
            const float* src = ph == 0 ? g_se : g_oth;
            const float4* s4 = (const float4*)src;
            for (int i = tid; i < 64 * 32; i += 256) {
                int r = i >> 5, c4 = i & 31;
                float4 v = s4[(row0 + r) * 32 + c4];
                *(uint4*)(uA + r * PAD + c4 * 4) =
                    make_uint4(tf32rn(v.x), tf32rn(v.y), tf32rn(v.z), tf32rn(v.w));
            }
        }
        CP_WAIT0();
        __syncthreads();
        #pragma unroll
        for (int ks = 0; ks < 16; ks++) {
            uint4 fa0 = make_uint4(A0[ks*8], A0[ks*8 + 8*PAD], A0[ks*8 + 4], A0[ks*8 + 8*PAD + 4]);
            uint4 fa1 = make_uint4(A1[ks*8], A1[ks*8 + 8*PAD], A1[ks*8 + 4], A1[ks*8 + 8*PAD + 4]);
            #pragma unroll
            for (int j = 0; j < 4; j++) {
                uint2 bb = B1[((cq * 4 + j) * 16 + ks) * 32 + lane];
                mma8(acc[0][j], fa0, bb); mma8(acc[1][j], fa1, bb);
            }
        }
        __syncthreads();
    }

    #pragma unroll
    for (int mi = 0; mi < 2; mi++) {
        #pragma unroll
        for (int j = 0; j < 4; j++) {
            int r = rs_ * 32 + mi * 16 + g;
            int c = cq * 32 + j * 8 + 2 * tig;
            float bb0 = b1s[c], bb1 = b1s[c + 1];
            h[r * HSTR + c]           = lrelu(acc[mi][j].x + bb0);
            h[r * HSTR + c + 1]       = lrelu(acc[mi][j].y + bb1);
            h[(r + 8) * HSTR + c]     = lrelu(acc[mi][j].z + bb0);
            h[(r + 8) * HSTR + c + 1] = lrelu(acc[mi][j].w + bb1);
        }
    }
    __syncthreads();

    const int o = lane & 15, half = lane >> 4;
    #pragma unroll
    for (int rr = 0; rr < 8; rr++) {
        const int r = w * 8 + rr;
        const int bidx = blockIdx.x * 64 + r;
        const float4* hr4 = (const float4*)(h + r * HSTR + half * 64);
        const float4* w4  = (const float4*)(w2t + o * HSTR + half * 64);
        float q = 0.f;
        #pragma unroll
        for (int i = 0; i < 16; i++) {
            float4 hv = hr4[i], wv = w4[i];
            q += hv.x * wv.x + hv.y * wv.y + hv.z * wv.z + hv.w * wv.w;
        }
        q += __shfl_xor_sync(FULLMASK, q, 16);
        q += b2s[o];

        float qsel = __shfl_sync(FULLMASK, q, amx[r]);   // lane amx[r] (<16) has o==amx[r]
        if (lane == 0) out[(size_t)n * B + bidx] = qsel;
    }
}

// ============================================================
extern "C" void kernel_launch(void* const* d_in, const int* in_sizes, int n_in,
                              void* d_out, int out_size)
{
    const float* s    = (const float*)d_in[0];
    const float* a    = (const float*)d_in[1];
    const float* Wsa  = (const float*)d_in[2];
    const float* Bsa  = (const float*)d_in[3];
    const float* Wse  = (const float*)d_in[4];
    const float* Bse  = (const float*)d_in[5];
    const float* Wk   = (const float*)d_in[6];
    const float* Wsel = (const float*)d_in[7];
    const float* Wv   = (const float*)d_in[8];
    const float* bv   = (const float*)d_in[9];
    const float* Wc1  = (const float*)d_in[10];
    const float* Bc1  = (const float*)d_in[11];
    const float* Wc2  = (const float*)d_in[12];
    const float* Bc2  = (const float*)d_in[13];
    float* out = (float*)d_out;

    cudaFuncSetAttribute(k_front, cudaFuncAttributeMaxDynamicSharedMemorySize, SMEM_FRONT);
    cudaFuncSetAttribute(k_crit,  cudaFuncAttributeMaxDynamicSharedMemorySize, SMEM_CRIT);

    k_prep   <<<448, 512>>>(Wk, Wv, Wsel, Wsa, Wse, Wc1);
    k_stats1 <<<dim3(16, NAG), 512>>>(s, a);
    k_stats2 <<<1, 640>>>();
    k_front  <<<dim3(B / 64, NAG), 256, SMEM_FRONT>>>(s, a, Bsa, Bse, bv);
    k_attn   <<<dim3((HEADS * B) / 8), 256>>>();
    k_crit   <<<dim3(B / 64, NAG), 256, SMEM_CRIT>>>(a, Bc1, Wc2, Bc2, out);
}

// round 8
// speedup vs baseline: 2.9620x; 1.0129x over previous
#include <cuda_runtime.h>
#include <math.h>
#include <stdint.h>

#define FULLMASK 0xffffffffu

constexpr int NAG  = 8;
constexpr int B    = 16384;
constexpr int SD   = 64;
constexpr int AD   = 16;
constexpr int KSA  = 80;
constexpr int HID  = 128;
constexpr int HEADS= 4;
constexpr int D    = 32;
constexpr float EPS = 1e-5f;

// -------- scratch --------
__device__ __align__(16) float g_mean[NAG * KSA];
__device__ __align__(16) float g_rstd[NAG * KSA];
__device__ __align__(16) float g_part [NAG * 16 * KSA];
__device__ __align__(16) float g_partq[NAG * 16 * KSA];
__device__ __align__(16) float g_se [(size_t)NAG * B * HID];   // stored tf32-rounded
__device__ __align__(16) float g_key[(size_t)NAG * B * HID];
__device__ __align__(16) float g_val[(size_t)NAG * B * HID];
__device__ __align__(16) float g_sel[(size_t)NAG * B * HID];
__device__ __align__(16) float g_oth[(size_t)NAG * B * HID];   // stored tf32-rounded

// fragment-order tf32 weights
__device__ __align__(16) uint2 pWk  [16 * 16 * 32];
__device__ __align__(16) uint2 pWv  [16 * 16 * 32];
__device__ __align__(16) uint2 pWsel[16 * 16 * 32];
__device__ __align__(16) uint2 pWsa [NAG][16 * 10 * 32];
__device__ __align__(16) uint2 pWse [NAG][16 * 8 * 32];
__device__ __align__(16) uint2 pWc1 [NAG][16 * 32 * 32];

__device__ __forceinline__ float lrelu(float x) { return x > 0.f ? x : 0.01f * x; }

__device__ __forceinline__ uint32_t tf32rn(float x) {
    uint32_t u; asm("cvt.rna.tf32.f32 %0, %1;" : "=r"(u) : "f"(x)); return u;
}
__device__ __forceinline__ void mma8(float4& d, const uint4 a, const uint2 b) {
    asm volatile(
        "mma.sync.aligned.m16n8k8.row.col.f32.tf32.tf32.f32 "
        "{%0,%1,%2,%3}, {%4,%5,%6,%7}, {%8,%9}, {%0,%1,%2,%3};"
        : "+f"(d.x), "+f"(d.y), "+f"(d.z), "+f"(d.w)
        : "r"(a.x), "r"(a.y), "r"(a.z), "r"(a.w), "r"(b.x), "r"(b.y));
}
__device__ __forceinline__ void cp16(void* smem_dst, const void* gsrc) {
    uint32_t sa = (uint32_t)__cvta_generic_to_shared(smem_dst);
    asm volatile("cp.async.cg.shared.global [%0], [%1], 16;" :: "r"(sa), "l"(gsrc));
}
#define CP_COMMIT()  asm volatile("cp.async.commit_group;")
#define CP_WAITG(n)  asm volatile("cp.async.wait_group " #n ";" ::: "memory")

// ============================================================
// K0: prep (weight fragments) + BN partial stats, fused
// grid 576 x 512: blocks [0,448) prep, [448,576) stats
// ============================================================
__global__ void __launch_bounds__(512)
k_prep_stats(const float* __restrict__ Wk, const float* __restrict__ Wv,
             const float* __restrict__ Wsel, const float* __restrict__ Wsa,
             const float* __restrict__ Wse, const float* __restrict__ Wc1,
             const float* __restrict__ s, const float* __restrict__ a)
{
    __shared__ float r1[512], r2[512];
    const int tid = threadIdx.x;

    if (blockIdx.x < 448) {
        int i = blockIdx.x * 512 + tid;
        if (i < 24576) {
            int which = i >> 13;
            int j = i & 8191;
            int n8 = j >> 9, ks = (j >> 5) & 15, lane = j & 31;
            int g = lane >> 2, tig = lane & 3;
            int n = n8 * 8 + g, k = ks * 8 + tig;
            const float* W = which == 0 ? Wk : (which == 1 ? Wv : Wsel);
            const float* base = W + (n >> 5) * (HID * D) + (n & 31);
            uint2 v = make_uint2(tf32rn(base[k * 32]), tf32rn(base[(k + 4) * 32]));
            (which == 0 ? pWk : which == 1 ? pWv : pWsel)[j] = v;
            return;
        }
        int i2 = i - 24576;
        if (i2 < NAG * 5120) {
            int n = i2 / 5120, j = i2 % 5120;
            int lane = j & 31, ks = (j >> 5) % 10, n8 = j / 320;
            int g = lane >> 2, tig = lane & 3;
            int nn = n8 * 8 + g, k = ks * 8 + tig;
            const float* W = Wsa + n * KSA * HID;
            pWsa[n][j] = make_uint2(tf32rn(W[k * HID + nn]), tf32rn(W[(k + 4) * HID + nn]));
            return;
        }
        int i3 = i2 - NAG * 5120;
        if (i3 < NAG * 4096) {
            int n = i3 >> 12, j = i3 & 4095;
            int lane = j & 31, ks = (j >> 5) & 7, n8 = j >> 8;
            int g = lane >> 2, tig = lane & 3;
            int nn = n8 * 8 + g, k = ks * 8 + tig;
            const float* W = Wse + n * SD * HID;
            pWse[n][j] = make_uint2(tf32rn(W[k * HID + nn]), tf32rn(W[(k + 4) * HID + nn]));
            return;
        }
        int i4 = i3 - NAG * 4096;
        if (i4 < NAG * 16384) {
            int n = i4 >> 14, j = i4 & 16383;
            int lane = j & 31, ks = (j >> 5) & 31, n8 = j >> 10;
            int g = lane >> 2, tig = lane & 3;
            int nn = n8 * 8 + g, k = ks * 8 + tig;
            const float* W = Wc1 + (size_t)n * 2 * HID * HID;
            pWc1[n][j] = make_uint2(tf32rn(W[k * HID + nn]), tf32rn(W[(k + 4) * HID + nn]));
        }
        return;
    }

    // ---- stats blocks ----
    const int bx = blockIdx.x - 448;
    const int n = bx >> 4, chunk = bx & 15;
    const size_t row0 = (size_t)n * B + chunk * 1024;
    float* part  = g_part  + (n * 16 + chunk) * KSA;
    float* partq = g_partq + (n * 16 + chunk) * KSA;

    {
        const int f = tid & 63, r0 = tid >> 6;
        float sum = 0.f, sq = 0.f;
        const float* p = s + (row0 + r0) * SD + f;
        #pragma unroll 4
        for (int st = 0; st < 128; st++) {
            float x = p[(size_t)st * 8 * SD];
            sum += x; sq += x * x;
        }
        r1[tid] = sum; r2[tid] = sq;
        __syncthreads();
        #pragma unroll
        for (int o = 4; o > 0; o >>= 1) {
            if (tid < o * 64) { r1[tid] += r1[tid + o * 64]; r2[tid] += r2[tid + o * 64]; }
            __syncthreads();
        }
        if (tid < 64) { part[tid] = r1[tid]; partq[tid] = r2[tid]; }
        __syncthreads();
    }
    {
        const int f = tid & 15, r0 = tid >> 4;
        float sum = 0.f, sq = 0.f;
        const float* p = a + (row0 + r0) * AD + f;
        #pragma unroll 4
        for (int st = 0; st < 32; st++) {
            float x = p[(size_t)st * 32 * AD];
            sum += x; sq += x * x;
        }
        r1[tid] = sum; r2[tid] = sq;
        __syncthreads();
        #pragma unroll
        for (int o = 16; o > 0; o >>= 1) {
            if (tid < o * 16) { r1[tid] += r1[tid + o * 16]; r2[tid] += r2[tid + o * 16]; }
            __syncthreads();
        }
        if (tid < 16) { part[64 + tid] = r1[tid]; partq[64 + tid] = r2[tid]; }
    }
}

__global__ void k_stats2()
{
    int i = threadIdx.x;
    if (i >= NAG * KSA) return;
    int n = i / KSA, f = i % KSA;
    float sum = 0.f, sq = 0.f;
    for (int c = 0; c < 16; c++) {
        sum += g_part [(n * 16 + c) * KSA + f];
        sq  += g_partq[(n * 16 + c) * KSA + f];
    }
    float m = sum * (1.f / B);
    float v = sq * (1.f / B) - m * m;
    g_mean[i] = m;
    g_rstd[i] = rsqrtf(v + EPS);
}

// ============================================================
// K2: FUSED front: enc -> sel -> kv (4-ks chunked, double-buffered)
// ============================================================
constexpr int PAD = 132;
constexpr int FR_OFF_A    = 0;                            // 33792
constexpr int FR_OFF_W    = 33792;                        // 73728 (9216 uint2)
constexpr int FR_OFF_MISC = 107520;                       // 544 floats
constexpr int SMEM_FRONT  = 109696;

// kv chunk stage: chunk q (4 k-steps of Wk and Wv) -> W buffer at uint2 offset `buf`
__device__ __forceinline__ void stage_kv(uint2* W, int buf, int q, int tid) {
    for (int cc = tid; cc < 2048; cc += 256) {
        int lanepair = cc & 15, ksl = (cc >> 4) & 3, n8 = (cc >> 6) & 15, mat = cc >> 10;
        const uint2* src = (mat ? pWv : pWk) + ((n8 * 16 + q * 4 + ksl) * 32 + lanepair * 2);
        cp16(W + buf + mat * 2048 + (n8 * 4 + ksl) * 32 + lanepair * 2, src);
    }
}

__global__ void __launch_bounds__(256, 2)
k_front(const float* __restrict__ s, const float* __restrict__ a,
        const float* __restrict__ Bsa, const float* __restrict__ Bse,
        const float* __restrict__ bv)
{
    extern __shared__ char smc[];
    uint32_t* uA = (uint32_t*)(smc + FR_OFF_A);
    uint2*    W  = (uint2*)(smc + FR_OFF_W);
    char*     Wc = smc + FR_OFF_W;
    float*   bsa = (float*)(smc + FR_OFF_MISC);
    float*   bse = bsa + 128;
    float*   bvv = bse + 128;
    float*   mn  = bvv + 128;
    float*   rsd = mn + 80;

    const int n = blockIdx.y, tid = threadIdx.x;
    const size_t gr0 = (size_t)n * B + (size_t)blockIdx.x * 64;

    // prefetch enc weights
    for (int c = tid; c < 4608; c += 256) {
        const char* src = (c < 2560) ? (const char*)pWsa[n] + c * 16
                                     : (const char*)pWse[n] + (c - 2560) * 16;
        cp16(Wc + c * 16, src);
    }
    CP_COMMIT();

    for (int i = tid; i < 128; i += 256) {
        bsa[i] = Bsa[n * HID + i];
        bse[i] = Bse[n * HID + i];
        bvv[i] = bv[i];
    }
    for (int i = tid; i < 80; i += 256) {
        mn[i]  = g_mean[n * KSA + i];
        rsd[i] = g_rstd[n * KSA + i];
    }
    __syncthreads();

    // A fill: BN'd [64 x 80]
    for (int i = tid; i < 64 * 20; i += 256) {
        int r = i / 20, c4 = i - r * 20;
        size_t row = gr0 + r;
        float4 v = (c4 < 16) ? ((const float4*)s)[row * 16 + c4]
                             : ((const float4*)a)[row * 4 + (c4 - 16)];
        int c = c4 * 4;
        *(uint4*)(uA + r * PAD + c) =
            make_uint4(tf32rn((v.x - mn[c])     * rsd[c]),
                       tf32rn((v.y - mn[c + 1]) * rsd[c + 1]),
                       tf32rn((v.z - mn[c + 2]) * rsd[c + 2]),
                       tf32rn((v.w - mn[c + 3]) * rsd[c + 3]));
    }
    CP_WAITG(0);
    __syncthreads();

    const int w = tid >> 5, lane = tid & 31;
    const int rs_ = w & 1, t0 = w >> 1;
    const int g = lane >> 2, tig = lane & 3;
    const uint32_t* A0 = uA + (rs_ * 32 + g) * PAD + tig;
    const uint32_t* A1 = A0 + 16 * PAD;

    // ---- Phase 1: enc ----
    float4 ae[2][4], as_[2][4];
    #pragma unroll
    for (int mi = 0; mi < 2; mi++)
        #pragma unroll
        for (int j = 0; j < 4; j++) { ae[mi][j] = make_float4(0,0,0,0); as_[mi][j] = make_float4(0,0,0,0); }

    #pragma unroll
    for (int ks = 0; ks < 10; ks++) {
        uint4 fa0 = make_uint4(A0[ks*8], A0[ks*8 + 8*PAD], A0[ks*8 + 4], A0[ks*8 + 8*PAD + 4]);
        uint4 fa1 = make_uint4(A1[ks*8], A1[ks*8 + 8*PAD], A1[ks*8 + 4], A1[ks*8 + 8*PAD + 4]);
        #pragma unroll
        for (int j = 0; j < 4; j++) {
            uint2 bb = W[((t0 * 4 + j) * 10 + ks) * 32 + lane];
            mma8(ae[0][j], fa0, bb); mma8(ae[1][j], fa1, bb);
        }
        if (ks < 8) {
            #pragma unroll
            for (int j = 0; j < 4; j++) {
                uint2 bb = W[5120 + ((t0 * 4 + j) * 8 + ks) * 32 + lane];
                mma8(as_[0][j], fa0, bb); mma8(as_[1][j], fa1, bb);
            }
        }
    }
    __syncthreads();

    // prefetch Wsel during epilogue
    for (int c = tid; c < 4096; c += 256) cp16(Wc + c * 16, (const char*)pWsel + c * 16);
    CP_COMMIT();

    // bias+lrelu; write g_se (tf32-rounded); restage A = se
    #pragma unroll
    for (int mi = 0; mi < 2; mi++) {
        #pragma unroll
        for (int j = 0; j < 4; j++) {
            int c = t0 * 32 + j * 8 + 2 * tig;
            float b0e = bsa[c], b1e = bsa[c + 1];
            float b0s = bse[c], b1s = bse[c + 1];
            ae[mi][j]  = make_float4(lrelu(ae[mi][j].x + b0e), lrelu(ae[mi][j].y + b1e),
                                     lrelu(ae[mi][j].z + b0e), lrelu(ae[mi][j].w + b1e));
            as_[mi][j] = make_float4(lrelu(as_[mi][j].x + b0s), lrelu(as_[mi][j].y + b1s),
                                     lrelu(as_[mi][j].z + b0s), lrelu(as_[mi][j].w + b1s));
            int r = rs_ * 32 + mi * 16 + g;
            size_t gr = gr0 + r;
            uint2 tA = make_uint2(tf32rn(as_[mi][j].x), tf32rn(as_[mi][j].y));
            uint2 tB = make_uint2(tf32rn(as_[mi][j].z), tf32rn(as_[mi][j].w));
            *(uint2*)&g_se[gr * 128 + c]       = tA;
            *(uint2*)&g_se[(gr + 8) * 128 + c] = tB;
            *(uint2*)(uA + r * PAD + c)        = tA;
            *(uint2*)(uA + (r + 8) * PAD + c)  = tB;
        }
    }
    CP_WAITG(0);
    __syncthreads();

    // ---- Phase 2: sel ----
    float4 ac[2][4], acv[2][4];
    #pragma unroll
    for (int mi = 0; mi < 2; mi++)
        #pragma unroll
        for (int j = 0; j < 4; j++) ac[mi][j] = make_float4(0,0,0,0);

    #pragma unroll
    for (int ks = 0; ks < 16; ks++) {
        uint4 fa0 = make_uint4(A0[ks*8], A0[ks*8 + 8*PAD], A0[ks*8 + 4], A0[ks*8 + 8*PAD + 4]);
        uint4 fa1 = make_uint4(A1[ks*8], A1[ks*8 + 8*PAD], A1[ks*8 + 4], A1[ks*8 + 8*PAD + 4]);
        #pragma unroll
        for (int j = 0; j < 4; j++) {
            uint2 bb = W[((t0 * 4 + j) * 16 + ks) * 32 + lane];
            mma8(ac[0][j], fa0, bb); mma8(ac[1][j], fa1, bb);
        }
    }
    __syncthreads();    // sel weights fully read; W buffer free

    // prefetch kv chunks 0,1 (buffers 0,1)
    stage_kv(W, 0, 0, tid);    CP_COMMIT();
    stage_kv(W, 4096, 1, tid); CP_COMMIT();

    // sel epilogue: store g_sel; restage A = e
    #pragma unroll
    for (int mi = 0; mi < 2; mi++) {
        #pragma unroll
        for (int j = 0; j < 4; j++) {
            int r = rs_ * 32 + mi * 16 + g;
            int c = t0 * 32 + j * 8 + 2 * tig;
            size_t gr = gr0 + r;
            *(float2*)&g_sel[gr * 128 + c]       = make_float2(ac[mi][j].x, ac[mi][j].y);
            *(float2*)&g_sel[(gr + 8) * 128 + c] = make_float2(ac[mi][j].z, ac[mi][j].w);
            *(uint2*)(uA + r * PAD + c)       = make_uint2(tf32rn(ae[mi][j].x), tf32rn(ae[mi][j].y));
            *(uint2*)(uA + (r + 8) * PAD + c) = make_uint2(tf32rn(ae[mi][j].z), tf32rn(ae[mi][j].w));
        }
    }
    CP_WAITG(1);
    __syncthreads();

    // ---- Phase 3: key+val, 4 chunks of 4 k-steps, double-buffered ----
    #pragma unroll
    for (int mi = 0; mi < 2; mi++)
        #pragma unroll
        for (int j = 0; j < 4; j++) { ac[mi][j] = make_float4(0,0,0,0); acv[mi][j] = make_float4(0,0,0,0); }

    #pragma unroll 1
    for (int q = 0; q < 4; q++) {
        const int buf = (q & 1) << 12;
        #pragma unroll
        for (int ksl = 0; ksl < 4; ksl++) {
            const int ks = q * 4 + ksl;
            uint4 fa0 = make_uint4(A0[ks*8], A0[ks*8 + 8*PAD], A0[ks*8 + 4], A0[ks*8 + 8*PAD + 4]);
            uint4 fa1 = make_uint4(A1[ks*8], A1[ks*8 + 8*PAD], A1[ks*8 + 4], A1[ks*8 + 8*PAD + 4]);
            #pragma unroll
            for (int j = 0; j < 4; j++) {
                int bi = buf + ((t0 * 4 + j) * 4 + ksl) * 32 + lane;
                uint2 bk = W[bi], bw = W[bi + 2048];
                mma8(ac[0][j],  fa0, bk); mma8(ac[1][j],  fa1, bk);
                mma8(acv[0][j], fa0, bw); mma8(acv[1][j], fa1, bw);
            }
        }
        if (q == 3) break;
        __syncthreads();                         // everyone done reading buf
        if (q < 2) {
            stage_kv(W, buf, q + 2, tid);        // refill same buffer
            CP_COMMIT();
            CP_WAITG(1);
        } else {
            CP_WAITG(0);
        }
        __syncthreads();
    }

    // kv epilogue
    #pragma unroll
    for (int mi = 0; mi < 2; mi++) {
        #pragma unroll
        for (int j = 0; j < 4; j++) {
            size_t gr = gr0 + rs_ * 32 + mi * 16 + g;
            int c = t0 * 32 + j * 8 + 2 * tig;
            *(float2*)&g_key[gr * 128 + c]       = make_float2(ac[mi][j].x, ac[mi][j].y);
            *(float2*)&g_key[(gr + 8) * 128 + c] = make_float2(ac[mi][j].z, ac[mi][j].w);
            float bb0 = bvv[c], bb1 = bvv[c + 1];
            *(float2*)&g_val[gr * 128 + c]       = make_float2(lrelu(acv[mi][j].x + bb0), lrelu(acv[mi][j].y + bb1));
            *(float2*)&g_val[(gr + 8) * 128 + c] = make_float2(lrelu(acv[mi][j].z + bb0), lrelu(acv[mi][j].w + bb1));
        }
    }
}

// ============================================================
// K3: attention (g_oth written tf32-rounded)
// ============================================================
__global__ void __launch_bounds__(256, 4)
k_attn()
{
    __shared__ float smem[8][3 * 8 * 33 + 64];
    const int tid = threadIdx.x, warp = tid >> 5, lane = tid & 31;
    const int gid = blockIdx.x * 8 + warp;
    const int b = gid >> 2;
    const int p = gid & 3;

    float* selS = smem[warp];
    float* keyS = selS + 8 * 33;
    float* valS = keyS + 8 * 33;
    float* wS   = valS + 8 * 33;
    const float scale = 0.17677669529663687f;

    #pragma unroll
    for (int i = 0; i < 8; i++) {
        size_t base = ((size_t)i * B + b) * HID + p * D + lane;
        selS[i * 33 + lane] = g_sel[base];
        keyS[i * 33 + lane] = g_key[base];
        valS[i * 33 + lane] = g_val[base];
    }
    __syncwarp();

    const int i0 = lane >> 3, j = lane & 7, i1 = i0 + 4;
    float acc0 = 0.f, acc1 = 0.f;
    #pragma unroll
    for (int d = 0; d < 32; d++) {
        float kv = keyS[j * 33 + d];
        acc0 += selS[i0 * 33 + d] * kv;
        acc1 += selS[i1 * 33 + d] * kv;
    }
    acc0 *= scale; acc1 *= scale;
    if (i0 == j) acc0 = -1e9f;
    if (i1 == j) acc1 = -1e9f;

    float m0 = acc0, m1 = acc1;
    #pragma unroll
    for (int o = 1; o < 8; o <<= 1) {
        m0 = fmaxf(m0, __shfl_xor_sync(FULLMASK, m0, o));
        m1 = fmaxf(m1, __shfl_xor_sync(FULLMASK, m1, o));
    }
    float e0 = __expf(acc0 - m0), e1 = __expf(acc1 - m1);
    float s0 = e0, s1 = e1;
    #pragma unroll
    for (int o = 1; o < 8; o <<= 1) {
        s0 += __shfl_xor_sync(FULLMASK, s0, o);
        s1 += __shfl_xor_sync(FULLMASK, s1, o);
    }
    wS[lane]      = __fdividef(e0, s0);
    wS[lane + 32] = __fdividef(e1, s1);
    __syncwarp();

    float out[8];
    #pragma unroll
    for (int ii = 0; ii < 8; ii++) out[ii] = 0.f;
    #pragma unroll
    for (int jj = 0; jj < 8; jj++) {
        float v = valS[jj * 33 + lane];
        #pragma unroll
        for (int ii = 0; ii < 8; ii++) out[ii] += wS[ii * 8 + jj] * v;
    }
    #pragma unroll
    for (int ii = 0; ii < 8; ii++)
        g_oth[((size_t)ii * B + b) * HID + p * D + lane] = __uint_as_float(tf32rn(out[ii]));
}

// ============================================================
// K4: critic — fully cp.async-pipelined (A byte-copy; W1 8-ks chunks)
// ============================================================
constexpr int HSTR = 132;
constexpr int CR_OFF_A   = 0;                             // 33792 (h reuses)
constexpr int CR_OFF_B1  = 33792;                         // 2 x 32KB
constexpr int CR_OFF_W2  = 99328;                         // 8448
constexpr int CR_OFF_B1S = 107776;
constexpr int CR_OFF_B2S = 108288;
constexpr int CR_OFF_AMX = 108352;
constexpr int SMEM_CRIT  = 108608;

__device__ __forceinline__ void crit_stageW(uint2* B1, int buf, int ch, int n, int tid) {
    const uint2* base = pWc1[n];
    for (int cc = tid; cc < 2048; cc += 256) {
        int lanepair = cc & 15, ksl = (cc >> 4) & 7, n8 = cc >> 7;
        cp16(B1 + buf + (n8 * 8 + ksl) * 32 + lanepair * 2,
             base + ((n8 * 32 + ch * 8 + ksl) * 32 + lanepair * 2));
    }
}
__device__ __forceinline__ void crit_stageA(uint32_t* uA, const float* __restrict__ src,
                                            size_t row0, int tid) {
    for (int i = tid; i < 2048; i += 256) {
        int r = i >> 5, c4 = i & 31;
        cp16(uA + r * PAD + c4 * 4, src + (row0 + r) * 128 + c4 * 4);
    }
}

__global__ void __launch_bounds__(256, 2)
k_crit(const float* __restrict__ a,
       const float* __restrict__ Bc1,
       const float* __restrict__ Wc2, const float* __restrict__ Bc2,
       float* __restrict__ out)
{
    extern __shared__ char smc[];
    uint32_t* uA = (uint32_t*)(smc + CR_OFF_A);
    uint2*    B1 = (uint2*)(smc + CR_OFF_B1);
    float*    h  = (float*)(smc + CR_OFF_A);
    float*   w2t = (float*)(smc + CR_OFF_W2);
    float*   b1s = (float*)(smc + CR_OFF_B1S);
    float*   b2s = (float*)(smc + CR_OFF_B2S);
    int*     amx = (int*)(smc + CR_OFF_AMX);

    const int n = blockIdx.y, tid = threadIdx.x;
    const int w = tid >> 5, lane = tid & 31;
    const size_t row0 = (size_t)n * B + (size_t)blockIdx.x * 64;

    // async pipeline head: W ch0 -> buf0, A ph0, W ch1 -> buf1
    crit_stageW(B1, 0, 0, n, tid);          CP_COMMIT();
    crit_stageA(uA, g_se, row0, tid);       CP_COMMIT();
    crit_stageW(B1, 4096, 1, n, tid);       CP_COMMIT();

    // small fills (sync loads, overlap with cp.async)
    for (int i = tid; i < HID * AD; i += 256) {
        int k = i >> 4, o = i & 15;
        w2t[o * HSTR + k] = Wc2[n * HID * AD + k * AD + o];
    }
    if (tid < HID) b1s[tid] = Bc1[n * HID + tid];
    if (tid >= HID && tid < HID + AD) b2s[tid - HID] = Bc2[n * AD + (tid - HID)];
    if (tid < 64) {
        const float4* ap = (const float4*)(a + (row0 + tid) * AD);
        float4 q0 = ap[0], q1 = ap[1], q2 = ap[2], q3 = ap[3];
        float vals[16] = {q0.x,q0.y,q0.z,q0.w, q1.x,q1.y,q1.z,q1.w,
                          q2.x,q2.y,q2.z,q2.w, q3.x,q3.y,q3.z,q3.w};
        int bi = 0; float bvv = vals[0];
        #pragma unroll
        for (int i = 1; i < 16; i++) if (vals[i] > bvv) { bvv = vals[i]; bi = i; }
        amx[tid] = bi;
    }

    const int rs_ = w & 1, cq = w >> 1;
    const int g = lane >> 2, tig = lane & 3;

    float4 acc[2][4];
    #pragma unroll
    for (int mi = 0; mi < 2; mi++)
        #pragma unroll
        for (int j = 0; j < 4; j++) acc[mi][j] = make_float4(0,0,0,0);

    const uint32_t* A0 = uA + (rs_ * 32 + g) * PAD + tig;
    const uint32_t* A1 = A0 + 16 * PAD;

    // chunk mma helper (macro-free, manual 4 stages)
    #define CRIT_MMA_CHUNK(BUFOFS, KBASE)                                          \
        _Pragma("unroll")                                                          \
        for (int ksl = 0; ksl < 8; ksl++) {                                        \
            const int ks = (KBASE) + ksl;                                          \
            uint4 fa0 = make_uint4(A0[ks*8], A0[ks*8 + 8*PAD], A0[ks*8 + 4], A0[ks*8 + 8*PAD + 4]); \
            uint4 fa1 = make_uint4(A1[ks*8], A1[ks*8 + 8*PAD], A1[ks*8 + 4], A1[ks*8 + 8*PAD + 4]); \
            _Pragma("unroll")                                                      \
            for (int j = 0; j < 4; j++) {                                          \
                uint2 bb = B1[(BUFOFS) + ((cq * 4 + j) * 8 + ksl) * 32 + lane];    \
                mma8(acc[0][j], fa0, bb); mma8(acc[1][j], fa1, bb);                \
            }                                                                      \
        }

    CP_WAITG(1);            // ch0 + A0 done (ch1 may be pending)
    __syncthreads();
    CRIT_MMA_CHUNK(0, 0)                     // ph0 ks 0..7
    __syncthreads();
    crit_stageW(B1, 0, 2, n, tid); CP_COMMIT();   // ph1 ks0..7 -> buf0
    CP_WAITG(1);            // ch1 done
    __syncthreads();
    CRIT_MMA_CHUNK(4096, 8)                  // ph0 ks 8..15
    __syncthreads();
    crit_stageA(uA, g_oth, row0, tid); CP_COMMIT();   // A refill (ph1)
    crit_stageW(B1, 4096, 3, n, tid); CP_COMMIT();    // ph1 ks8..15 -> buf1
    CP_WAITG(1);            // ch2 + A1 done
    __syncthreads();
    CRIT_MMA_CHUNK(0, 0)                     // ph1 ks 0..7
    __syncthreads();
    CP_WAITG(0);            // ch3 done
    __syncthreads();
    CRIT_MMA_CHUNK(4096, 8)                  // ph1 ks 8..15
    __syncthreads();        // all A reads done before h overwrites uA
    #undef CRIT_MMA_CHUNK

    #pragma unroll
    for (int mi = 0; mi < 2; mi++) {
        #pragma unroll
        for (int j = 0; j < 4; j++) {
            int r = rs_ * 32 + mi * 16 + g;
            int c = cq * 32 + j * 8 + 2 * tig;
            float bb0 = b1s[c], bb1 = b1s[c + 1];
            h[r * HSTR + c]           = lrelu(acc[mi][j].x + bb0);
            h[r * HSTR + c + 1]       = lrelu(acc[mi][j].y + bb1);
            h[(r + 8) * HSTR + c]     = lrelu(acc[mi][j].z + bb0);
            h[(r + 8) * HSTR + c + 1] = lrelu(acc[mi][j].w + bb1);
        }
    }
    __syncthreads();

    const int o = lane & 15, half = lane >> 4;
    #pragma unroll
    for (int rr = 0; rr < 8; rr++) {
        const int r = w * 8 + rr;
        const int bidx = blockIdx.x * 64 + r;
        const float4* hr4 = (const float4*)(h + r * HSTR + half * 64);
        const float4* w4  = (const float4*)(w2t + o * HSTR + half * 64);
        float q = 0.f;
        #pragma unroll
        for (int i = 0; i < 16; i++) {
            float4 hv = hr4[i], wv = w4[i];
            q += hv.x * wv.x + hv.y * wv.y + hv.z * wv.z + hv.w * wv.w;
        }
        q += __shfl_xor_sync(FULLMASK, q, 16);
        q += b2s[o];

        float qsel = __shfl_sync(FULLMASK, q, amx[r]);
        if (lane == 0) out[(size_t)n * B + bidx] = qsel;
    }
}

// ============================================================
extern "C" void kernel_launch(void* const* d_in, const int* in_sizes, int n_in,
                              void* d_out, int out_size)
{
    const float* s    = (const float*)d_in[0];
    const float* a    = (const float*)d_in[1];
    const float* Wsa  = (const float*)d_in[2];
    const float* Bsa  = (const float*)d_in[3];
    const float* Wse  = (const float*)d_in[4];
    const float* Bse  = (const float*)d_in[5];
    const float* Wk   = (const float*)d_in[6];
    const float* Wsel = (const float*)d_in[7];
    const float* Wv   = (const float*)d_in[8];
    const float* bv   = (const float*)d_in[9];
    const float* Wc1  = (const float*)d_in[10];
    const float* Bc1  = (const float*)d_in[11];
    const float* Wc2  = (const float*)d_in[12];
    const float* Bc2  = (const float*)d_in[13];
    float* out = (float*)d_out;

    cudaFuncSetAttribute(k_front, cudaFuncAttributeMaxDynamicSharedMemorySize, SMEM_FRONT);
    cudaFuncSetAttribute(k_crit,  cudaFuncAttributeMaxDynamicSharedMemorySize, SMEM_CRIT);

    k_prep_stats<<<576, 512>>>(Wk, Wv, Wsel, Wsa, Wse, Wc1, s, a);
    k_stats2    <<<1, 640>>>();
    k_front     <<<dim3(B / 64, NAG), 256, SMEM_FRONT>>>(s, a, Bsa, Bse, bv);
    k_attn      <<<dim3((HEADS * B) / 8), 256>>>();
    k_crit      <<<dim3(B / 64, NAG), 256, SMEM_CRIT>>>(a, Bc1, Wc2, Bc2, out);
}

// round 9
// speedup vs baseline: 2.9637x; 1.0006x over previous
#include <cuda_runtime.h>
#include <math.h>
#include <stdint.h>

#define FULLMASK 0xffffffffu

constexpr int NAG  = 8;
constexpr int B    = 16384;
constexpr int SD   = 64;
constexpr int AD   = 16;
constexpr int KSA  = 80;
constexpr int HID  = 128;
constexpr int HEADS= 4;
constexpr int D    = 32;
constexpr float EPS = 1e-5f;

// -------- scratch --------
__device__ __align__(16) float g_mean[NAG * KSA];
__device__ __align__(16) float g_rstd[NAG * KSA];
__device__ __align__(16) float g_part [NAG * 16 * KSA];
__device__ __align__(16) float g_partq[NAG * 16 * KSA];
__device__ __align__(16) float g_se [(size_t)NAG * B * HID];   // FRAGMENT-ORDER tiles of 64 rows (tf32)
__device__ __align__(16) float g_key[(size_t)NAG * B * HID];
__device__ __align__(16) float g_val[(size_t)NAG * B * HID];
__device__ __align__(16) float g_sel[(size_t)NAG * B * HID];
__device__ __align__(16) float g_oth[(size_t)NAG * B * HID];   // row-major, tf32-rounded

// fragment-order tf32 weights
__device__ __align__(16) uint2 pWk  [16 * 16 * 32];
__device__ __align__(16) uint2 pWv  [16 * 16 * 32];
__device__ __align__(16) uint2 pWsel[16 * 16 * 32];
__device__ __align__(16) uint2 pWsa [NAG][16 * 10 * 32];
__device__ __align__(16) uint2 pWse [NAG][16 * 8 * 32];
__device__ __align__(16) uint2 pWc1 [NAG][16 * 32 * 32];

__device__ __forceinline__ float lrelu(float x) { return x > 0.f ? x : 0.01f * x; }

__device__ __forceinline__ uint32_t tf32rn(float x) {
    uint32_t u; asm("cvt.rna.tf32.f32 %0, %1;" : "=r"(u) : "f"(x)); return u;
}
__device__ __forceinline__ void mma8(float4& d, const uint4 a, const uint2 b) {
    asm volatile(
        "mma.sync.aligned.m16n8k8.row.col.f32.tf32.tf32.f32 "
        "{%0,%1,%2,%3}, {%4,%5,%6,%7}, {%8,%9}, {%0,%1,%2,%3};"
        : "+f"(d.x), "+f"(d.y), "+f"(d.z), "+f"(d.w)
        : "r"(a.x), "r"(a.y), "r"(a.z), "r"(a.w), "r"(b.x), "r"(b.y));
}
__device__ __forceinline__ void cp16(void* smem_dst, const void* gsrc) {
    uint32_t sa = (uint32_t)__cvta_generic_to_shared(smem_dst);
    asm volatile("cp.async.cg.shared.global [%0], [%1], 16;" :: "r"(sa), "l"(gsrc));
}
#define CP_COMMIT()  asm volatile("cp.async.commit_group;")
#define CP_WAITG(n)  asm volatile("cp.async.wait_group " #n ";" ::: "memory")

// fragment-order A load: one LDS.128, conflict-free
__device__ __forceinline__ uint4 ldfragA(const uint32_t* uAf, int g16, int ks, int lane) {
    return *(const uint4*)(uAf + (((g16 << 4) + ks) << 7) + (lane << 2));
}

// ============================================================
// K0: prep + BN partial stats, fused
// ============================================================
__global__ void __launch_bounds__(512)
k_prep_stats(const float* __restrict__ Wk, const float* __restrict__ Wv,
             const float* __restrict__ Wsel, const float* __restrict__ Wsa,
             const float* __restrict__ Wse, const float* __restrict__ Wc1,
             const float* __restrict__ s, const float* __restrict__ a)
{
    __shared__ float r1[512], r2[512];
    const int tid = threadIdx.x;

    if (blockIdx.x < 448) {
        int i = blockIdx.x * 512 + tid;
        if (i < 24576) {
            int which = i >> 13;
            int j = i & 8191;
            int n8 = j >> 9, ks = (j >> 5) & 15, lane = j & 31;
            int g = lane >> 2, tig = lane & 3;
            int n = n8 * 8 + g, k = ks * 8 + tig;
            const float* W = which == 0 ? Wk : (which == 1 ? Wv : Wsel);
            const float* base = W + (n >> 5) * (HID * D) + (n & 31);
            uint2 v = make_uint2(tf32rn(base[k * 32]), tf32rn(base[(k + 4) * 32]));
            (which == 0 ? pWk : which == 1 ? pWv : pWsel)[j] = v;
            return;
        }
        int i2 = i - 24576;
        if (i2 < NAG * 5120) {
            int n = i2 / 5120, j = i2 % 5120;
            int lane = j & 31, ks = (j >> 5) % 10, n8 = j / 320;
            int g = lane >> 2, tig = lane & 3;
            int nn = n8 * 8 + g, k = ks * 8 + tig;
            const float* W = Wsa + n * KSA * HID;
            pWsa[n][j] = make_uint2(tf32rn(W[k * HID + nn]), tf32rn(W[(k + 4) * HID + nn]));
            return;
        }
        int i3 = i2 - NAG * 5120;
        if (i3 < NAG * 4096) {
            int n = i3 >> 12, j = i3 & 4095;
            int lane = j & 31, ks = (j >> 5) & 7, n8 = j >> 8;
            int g = lane >> 2, tig = lane & 3;
            int nn = n8 * 8 + g, k = ks * 8 + tig;
            const float* W = Wse + n * SD * HID;
            pWse[n][j] = make_uint2(tf32rn(W[k * HID + nn]), tf32rn(W[(k + 4) * HID + nn]));
            return;
        }
        int i4 = i3 - NAG * 4096;
        if (i4 < NAG * 16384) {
            int n = i4 >> 14, j = i4 & 16383;
            int lane = j & 31, ks = (j >> 5) & 31, n8 = j >> 10;
            int g = lane >> 2, tig = lane & 3;
            int nn = n8 * 8 + g, k = ks * 8 + tig;
            const float* W = Wc1 + (size_t)n * 2 * HID * HID;
            pWc1[n][j] = make_uint2(tf32rn(W[k * HID + nn]), tf32rn(W[(k + 4) * HID + nn]));
        }
        return;
    }

    const int bx = blockIdx.x - 448;
    const int n = bx >> 4, chunk = bx & 15;
    const size_t row0 = (size_t)n * B + chunk * 1024;
    float* part  = g_part  + (n * 16 + chunk) * KSA;
    float* partq = g_partq + (n * 16 + chunk) * KSA;

    {
        const int f = tid & 63, r0 = tid >> 6;
        float sum = 0.f, sq = 0.f;
        const float* p = s + (row0 + r0) * SD + f;
        #pragma unroll 4
        for (int st = 0; st < 128; st++) {
            float x = p[(size_t)st * 8 * SD];
            sum += x; sq += x * x;
        }
        r1[tid] = sum; r2[tid] = sq;
        __syncthreads();
        #pragma unroll
        for (int o = 4; o > 0; o >>= 1) {
            if (tid < o * 64) { r1[tid] += r1[tid + o * 64]; r2[tid] += r2[tid + o * 64]; }
            __syncthreads();
        }
        if (tid < 64) { part[tid] = r1[tid]; partq[tid] = r2[tid]; }
        __syncthreads();
    }
    {
        const int f = tid & 15, r0 = tid >> 4;
        float sum = 0.f, sq = 0.f;
        const float* p = a + (row0 + r0) * AD + f;
        #pragma unroll 4
        for (int st = 0; st < 32; st++) {
            float x = p[(size_t)st * 32 * AD];
            sum += x; sq += x * x;
        }
        r1[tid] = sum; r2[tid] = sq;
        __syncthreads();
        #pragma unroll
        for (int o = 16; o > 0; o >>= 1) {
            if (tid < o * 16) { r1[tid] += r1[tid + o * 16]; r2[tid] += r2[tid + o * 16]; }
            __syncthreads();
        }
        if (tid < 16) { part[64 + tid] = r1[tid]; partq[64 + tid] = r2[tid]; }
    }
}

__global__ void k_stats2()
{
    int i = threadIdx.x;
    if (i >= NAG * KSA) return;
    int n = i / KSA, f = i % KSA;
    float sum = 0.f, sq = 0.f;
    for (int c = 0; c < 16; c++) {
        sum += g_part [(n * 16 + c) * KSA + f];
        sq  += g_partq[(n * 16 + c) * KSA + f];
    }
    float m = sum * (1.f / B);
    float v = sq * (1.f / B) - m * m;
    g_mean[i] = m;
    g_rstd[i] = rsqrtf(v + EPS);
}

// ============================================================
// K2: FUSED front, fragment-order A tile (LDS.128 mainloop)
// ============================================================
constexpr int FR_OFF_A    = 0;                            // 32768
constexpr int FR_OFF_W    = 32768;                        // 73728 (9216 uint2)
constexpr int FR_OFF_MISC = 106496;                       // 544 floats
constexpr int SMEM_FRONT  = 108672;

__device__ __forceinline__ void stage_kv(uint2* W, int buf, int q, int tid) {
    for (int cc = tid; cc < 2048; cc += 256) {
        int lanepair = cc & 15, ksl = (cc >> 4) & 3, n8 = (cc >> 6) & 15, mat = cc >> 10;
        const uint2* src = (mat ? pWv : pWk) + ((n8 * 16 + q * 4 + ksl) * 32 + lanepair * 2);
        cp16(W + buf + mat * 2048 + (n8 * 4 + ksl) * 32 + lanepair * 2, src);
    }
}

__global__ void __launch_bounds__(256, 2)
k_front(const float* __restrict__ s, const float* __restrict__ a,
        const float* __restrict__ Bsa, const float* __restrict__ Bse,
        const float* __restrict__ bv)
{
    extern __shared__ char smc[];
    uint32_t* uAf = (uint32_t*)(smc + FR_OFF_A);
    uint2*    W   = (uint2*)(smc + FR_OFF_W);
    char*     Wc  = smc + FR_OFF_W;
    float*   bsa = (float*)(smc + FR_OFF_MISC);
    float*   bse = bsa + 128;
    float*   bvv = bse + 128;
    float*   mn  = bvv + 128;
    float*   rsd = mn + 80;

    const int n = blockIdx.y, tid = threadIdx.x;
    const size_t gr0 = (size_t)n * B + (size_t)blockIdx.x * 64;

    // prefetch enc weights
    for (int c = tid; c < 4608; c += 256) {
        const char* src = (c < 2560) ? (const char*)pWsa[n] + c * 16
                                     : (const char*)pWse[n] + (c - 2560) * 16;
        cp16(Wc + c * 16, src);
    }
    CP_COMMIT();

    for (int i = tid; i < 128; i += 256) {
        bsa[i] = Bsa[n * HID + i];
        bse[i] = Bse[n * HID + i];
        bvv[i] = bv[i];
    }
    for (int i = tid; i < 80; i += 256) {
        mn[i]  = g_mean[n * KSA + i];
        rsd[i] = g_rstd[n * KSA + i];
    }
    __syncthreads();

    // A fill: BN'd [64 x 80] -> fragment order
    for (int i = tid; i < 64 * 20; i += 256) {
        int r = i / 20, c4 = i - r * 20;
        size_t row = gr0 + r;
        float4 v = (c4 < 16) ? ((const float4*)s)[row * 16 + c4]
                             : ((const float4*)a)[row * 4 + (c4 - 16)];
        int C = c4 * 4;
        int ks = C >> 3, half = (C >> 2) & 1;
        int g16 = r >> 4, comp_r = (r >> 3) & 1, gp = r & 7;
        uint32_t* p = uAf + ((((g16 << 4) + ks) << 5) + (gp << 2)) * 4 + comp_r + 2 * half;
        p[0]  = tf32rn((v.x - mn[C])     * rsd[C]);
        p[4]  = tf32rn((v.y - mn[C + 1]) * rsd[C + 1]);
        p[8]  = tf32rn((v.z - mn[C + 2]) * rsd[C + 2]);
        p[12] = tf32rn((v.w - mn[C + 3]) * rsd[C + 3]);
    }
    CP_WAITG(0);
    __syncthreads();

    const int w = tid >> 5, lane = tid & 31;
    const int rs_ = w & 1, t0 = w >> 1;
    const int g = lane >> 2, tig = lane & 3;
    // fragment write offsets for this thread's (mi,j) outputs
    const int lane0 = g * 4 + ((2 * tig) & 3);
    const int cw    = 2 * (tig >> 1);

    // ---- Phase 1: enc ----
    float4 ae[2][4], as_[2][4];
    #pragma unroll
    for (int mi = 0; mi < 2; mi++)
        #pragma unroll
        for (int j = 0; j < 4; j++) { ae[mi][j] = make_float4(0,0,0,0); as_[mi][j] = make_float4(0,0,0,0); }

    #pragma unroll
    for (int ks = 0; ks < 10; ks++) {
        uint4 fa0 = ldfragA(uAf, rs_ * 2,     ks, lane);
        uint4 fa1 = ldfragA(uAf, rs_ * 2 + 1, ks, lane);
        #pragma unroll
        for (int j = 0; j < 4; j++) {
            uint2 bb = W[((t0 * 4 + j) * 10 + ks) * 32 + lane];
            mma8(ae[0][j], fa0, bb); mma8(ae[1][j], fa1, bb);
        }
        if (ks < 8) {
            #pragma unroll
            for (int j = 0; j < 4; j++) {
                uint2 bb = W[5120 + ((t0 * 4 + j) * 8 + ks) * 32 + lane];
                mma8(as_[0][j], fa0, bb); mma8(as_[1][j], fa1, bb);
            }
        }
    }
    __syncthreads();

    for (int c = tid; c < 4096; c += 256) cp16(Wc + c * 16, (const char*)pWsel + c * 16);
    CP_COMMIT();

    // bias+lrelu; write g_se (fragment-order tile); restage A = se (fragment order)
    uint32_t* gseT = (uint32_t*)g_se + ((gr0 >> 6) << 13);
    #pragma unroll
    for (int mi = 0; mi < 2; mi++) {
        #pragma unroll
        for (int j = 0; j < 4; j++) {
            int c = t0 * 32 + j * 8 + 2 * tig;
            float b0e = bsa[c], b1e = bsa[c + 1];
            float b0s = bse[c], b1s = bse[c + 1];
            ae[mi][j]  = make_float4(lrelu(ae[mi][j].x + b0e), lrelu(ae[mi][j].y + b1e),
                                     lrelu(ae[mi][j].z + b0e), lrelu(ae[mi][j].w + b1e));
            as_[mi][j] = make_float4(lrelu(as_[mi][j].x + b0s), lrelu(as_[mi][j].y + b1s),
                                     lrelu(as_[mi][j].z + b0s), lrelu(as_[mi][j].w + b1s));
            int g16 = rs_ * 2 + mi, ks = t0 * 4 + j;
            int ofs = ((((g16 << 4) + ks) << 5) + lane0) * 4 + cw;
            uint2 u0 = make_uint2(tf32rn(as_[mi][j].x), tf32rn(as_[mi][j].z));   // (R,C),(R+8,C)
            uint2 u1 = make_uint2(tf32rn(as_[mi][j].y), tf32rn(as_[mi][j].w));   // (R,C+1),(R+8,C+1)
            *(uint2*)(uAf + ofs)     = u0;
            *(uint2*)(uAf + ofs + 4) = u1;
            *(uint2*)(gseT + ofs)     = u0;
            *(uint2*)(gseT + ofs + 4) = u1;
        }
    }
    CP_WAITG(0);
    __syncthreads();

    // ---- Phase 2: sel ----
    float4 ac[2][4], acv[2][4];
    #pragma unroll
    for (int mi = 0; mi < 2; mi++)
        #pragma unroll
        for (int j = 0; j < 4; j++) ac[mi][j] = make_float4(0,0,0,0);

    #pragma unroll
    for (int ks = 0; ks < 16; ks++) {
        uint4 fa0 = ldfragA(uAf, rs_ * 2,     ks, lane);
        uint4 fa1 = ldfragA(uAf, rs_ * 2 + 1, ks, lane);
        #pragma unroll
        for (int j = 0; j < 4; j++) {
            uint2 bb = W[((t0 * 4 + j) * 16 + ks) * 32 + lane];
            mma8(ac[0][j], fa0, bb); mma8(ac[1][j], fa1, bb);
        }
    }
    __syncthreads();

    stage_kv(W, 0, 0, tid);    CP_COMMIT();
    stage_kv(W, 4096, 1, tid); CP_COMMIT();

    // sel epilogue: g_sel row-major (attn reads it); restage A = e (fragment order)
    #pragma unroll
    for (int mi = 0; mi < 2; mi++) {
        #pragma unroll
        for (int j = 0; j < 4; j++) {
            int c = t0 * 32 + j * 8 + 2 * tig;
            size_t gr = gr0 + rs_ * 32 + mi * 16 + g;
            *(float2*)&g_sel[gr * 128 + c]       = make_float2(ac[mi][j].x, ac[mi][j].y);
            *(float2*)&g_sel[(gr + 8) * 128 + c] = make_float2(ac[mi][j].z, ac[mi][j].w);
            int g16 = rs_ * 2 + mi, ks = t0 * 4 + j;
            int ofs = ((((g16 << 4) + ks) << 5) + lane0) * 4 + cw;
            *(uint2*)(uAf + ofs)     = make_uint2(tf32rn(ae[mi][j].x), tf32rn(ae[mi][j].z));
            *(uint2*)(uAf + ofs + 4) = make_uint2(tf32rn(ae[mi][j].y), tf32rn(ae[mi][j].w));
        }
    }
    CP_WAITG(1);
    __syncthreads();

    // ---- Phase 3: key+val, 4 chunks of 4 k-steps, double-buffered ----
    #pragma unroll
    for (int mi = 0; mi < 2; mi++)
        #pragma unroll
        for (int j = 0; j < 4; j++) { ac[mi][j] = make_float4(0,0,0,0); acv[mi][j] = make_float4(0,0,0,0); }

    #pragma unroll 1
    for (int q = 0; q < 4; q++) {
        const int buf = (q & 1) << 12;
        #pragma unroll
        for (int ksl = 0; ksl < 4; ksl++) {
            const int ks = q * 4 + ksl;
            uint4 fa0 = ldfragA(uAf, rs_ * 2,     ks, lane);
            uint4 fa1 = ldfragA(uAf, rs_ * 2 + 1, ks, lane);
            #pragma unroll
            for (int j = 0; j < 4; j++) {
                int bi = buf + ((t0 * 4 + j) * 4 + ksl) * 32 + lane;
                uint2 bk = W[bi], bw = W[bi + 2048];
                mma8(ac[0][j],  fa0, bk); mma8(ac[1][j],  fa1, bk);
                mma8(acv[0][j], fa0, bw); mma8(acv[1][j], fa1, bw);
            }
        }
        if (q == 3) break;
        __syncthreads();
        if (q < 2) {
            stage_kv(W, buf, q + 2, tid);
            CP_COMMIT();
            CP_WAITG(1);
        } else {
            CP_WAITG(0);
        }
        __syncthreads();
    }

    #pragma unroll
    for (int mi = 0; mi < 2; mi++) {
        #pragma unroll
        for (int j = 0; j < 4; j++) {
            size_t gr = gr0 + rs_ * 32 + mi * 16 + g;
            int c = t0 * 32 + j * 8 + 2 * tig;
            *(float2*)&g_key[gr * 128 + c]       = make_float2(ac[mi][j].x, ac[mi][j].y);
            *(float2*)&g_key[(gr + 8) * 128 + c] = make_float2(ac[mi][j].z, ac[mi][j].w);
            float bb0 = bvv[c], bb1 = bvv[c + 1];
            *(float2*)&g_val[gr * 128 + c]       = make_float2(lrelu(acv[mi][j].x + bb0), lrelu(acv[mi][j].y + bb1));
            *(float2*)&g_val[(gr + 8) * 128 + c] = make_float2(lrelu(acv[mi][j].z + bb0), lrelu(acv[mi][j].w + bb1));
        }
    }
}

// ============================================================
// K3: attention — vectorized float4 loads (stride-36 smem)
// ============================================================
constexpr int ASTR = 36;
__global__ void __launch_bounds__(256, 4)
k_attn()
{
    __shared__ float smem[8][3 * 8 * ASTR + 64];
    const int tid = threadIdx.x, warp = tid >> 5, lane = tid & 31;
    const int gid = blockIdx.x * 8 + warp;
    const int b = gid >> 2;
    const int p = gid & 3;

    float* selS = smem[warp];
    float* keyS = selS + 8 * ASTR;
    float* valS = keyS + 8 * ASTR;
    float* wS   = valS + 8 * ASTR;
    const float scale = 0.17677669529663687f;

    #pragma unroll
    for (int it = 0; it < 6; it++) {
        int idx = it * 32 + lane;
        int sgm = idx >> 3;          // 0..23
        int q   = idx & 7;
        int arr = sgm >> 3;          // 0:sel 1:key 2:val
        int i   = sgm & 7;
        const float* gsrc = (arr == 0) ? g_sel : (arr == 1) ? g_key : g_val;
        float4 v = *(const float4*)(gsrc + ((size_t)i * B + b) * HID + p * D + q * 4);
        *(float4*)(selS + arr * (8 * ASTR) + i * ASTR + q * 4) = v;
    }
    __syncwarp();

    const int i0 = lane >> 3, j = lane & 7, i1 = i0 + 4;
    float acc0 = 0.f, acc1 = 0.f;
    #pragma unroll
    for (int d = 0; d < 32; d++) {
        float kv = keyS[j * ASTR + d];
        acc0 += selS[i0 * ASTR + d] * kv;
        acc1 += selS[i1 * ASTR + d] * kv;
    }
    acc0 *= scale; acc1 *= scale;
    if (i0 == j) acc0 = -1e9f;
    if (i1 == j) acc1 = -1e9f;

    float m0 = acc0, m1 = acc1;
    #pragma unroll
    for (int o = 1; o < 8; o <<= 1) {
        m0 = fmaxf(m0, __shfl_xor_sync(FULLMASK, m0, o));
        m1 = fmaxf(m1, __shfl_xor_sync(FULLMASK, m1, o));
    }
    float e0 = __expf(acc0 - m0), e1 = __expf(acc1 - m1);
    float s0 = e0, s1 = e1;
    #pragma unroll
    for (int o = 1; o < 8; o <<= 1) {
        s0 += __shfl_xor_sync(FULLMASK, s0, o);
        s1 += __shfl_xor_sync(FULLMASK, s1, o);
    }
    wS[lane]      = __fdividef(e0, s0);
    wS[lane + 32] = __fdividef(e1, s1);
    __syncwarp();

    float out[8];
    #pragma unroll
    for (int ii = 0; ii < 8; ii++) out[ii] = 0.f;
    #pragma unroll
    for (int jj = 0; jj < 8; jj++) {
        float v = valS[jj * ASTR + lane];
        #pragma unroll
        for (int ii = 0; ii < 8; ii++) out[ii] += wS[ii * 8 + jj] * v;
    }
    #pragma unroll
    for (int ii = 0; ii < 8; ii++)
        g_oth[((size_t)ii * B + b) * HID + p * D + lane] = __uint_as_float(tf32rn(out[ii]));
}

// ============================================================
// K4: critic — ph0 A from fragment-order g_se (byte copy + LDS.128),
// ph1 A from row-major g_oth (byte copy + 4x LDS.32)
// ============================================================
constexpr int PAD  = 132;
constexpr int HSTR = 132;
constexpr int CR_OFF_A   = 0;                             // 33792
constexpr int CR_OFF_B1  = 33792;                         // 2 x 32KB
constexpr int CR_OFF_W2  = 99328;
constexpr int CR_OFF_B1S = 107776;
constexpr int CR_OFF_B2S = 108288;
constexpr int CR_OFF_AMX = 108352;
constexpr int SMEM_CRIT  = 108608;

__device__ __forceinline__ void crit_stageW(uint2* B1, int buf, int ch, int n, int tid) {
    const uint2* base = pWc1[n];
    for (int cc = tid; cc < 2048; cc += 256) {
        int lanepair = cc & 15, ksl = (cc >> 4) & 7, n8 = cc >> 7;
        cp16(B1 + buf + (n8 * 8 + ksl) * 32 + lanepair * 2,
             base + ((n8 * 32 + ch * 8 + ksl) * 32 + lanepair * 2));
    }
}

__global__ void __launch_bounds__(256, 2)
k_crit(const float* __restrict__ a,
       const float* __restrict__ Bc1,
       const float* __restrict__ Wc2, const float* __restrict__ Bc2,
       float* __restrict__ out)
{
    extern __shared__ char smc[];
    uint32_t* uA = (uint32_t*)(smc + CR_OFF_A);
    uint2*    B1 = (uint2*)(smc + CR_OFF_B1);
    float*    h  = (float*)(smc + CR_OFF_A);
    float*   w2t = (float*)(smc + CR_OFF_W2);
    float*   b1s = (float*)(smc + CR_OFF_B1S);
    float*   b2s = (float*)(smc + CR_OFF_B2S);
    int*     amx = (int*)(smc + CR_OFF_AMX);

    const int n = blockIdx.y, tid = threadIdx.x;
    const int w = tid >> 5, lane = tid & 31;
    const size_t row0 = (size_t)n * B + (size_t)blockIdx.x * 64;

    // pipeline head: W ch0, A ph0 (fragment tile byte-copy), W ch1
    crit_stageW(B1, 0, 0, n, tid);          CP_COMMIT();
    {
        const uint32_t* gseT = (const uint32_t*)g_se + ((row0 >> 6) << 13);
        for (int i = tid; i < 2048; i += 256) cp16(uA + i * 4, gseT + i * 4);
    }
    CP_COMMIT();
    crit_stageW(B1, 4096, 1, n, tid);       CP_COMMIT();

    for (int i = tid; i < HID * AD; i += 256) {
        int k = i >> 4, o = i & 15;
        w2t[o * HSTR + k] = Wc2[n * HID * AD + k * AD + o];
    }
    if (tid < HID) b1s[tid] = Bc1[n * HID + tid];
    if (tid >= HID && tid < HID + AD) b2s[tid - HID] = Bc2[n * AD + (tid - HID)];
    if (tid < 64) {
        const float4* ap = (const float4*)(a + (row0 + tid) * AD);
        float4 q0 = ap[0], q1 = ap[1], q2 = ap[2], q3 = ap[3];
        float vals[16] = {q0.x,q0.y,q0.z,q0.w, q1.x,q1.y,q1.z,q1.w,
                          q2.x,q2.y,q2.z,q2.w, q3.x,q3.y,q3.z,q3.w};
        int bi = 0; float bvv = vals[0];
        #pragma unroll
        for (int i = 1; i < 16; i++) if (vals[i] > bvv) { bvv = vals[i]; bi = i; }
        amx[tid] = bi;
    }

    const int rs_ = w & 1, cq = w >> 1;
    const int g = lane >> 2, tig = lane & 3;

    float4 acc[2][4];
    #pragma unroll
    for (int mi = 0; mi < 2; mi++)
        #pragma unroll
        for (int j = 0; j < 4; j++) acc[mi][j] = make_float4(0,0,0,0);

    const uint32_t* A0 = uA + (rs_ * 32 + g) * PAD + tig;   // row-major pointers (ph1)
    const uint32_t* A1 = A0 + 16 * PAD;

    #define CRIT_CHUNK_FRAG(BUFOFS)                                                \
        _Pragma("unroll")                                                          \
        for (int ksl = 0; ksl < 8; ksl++) {                                        \
            const int ksA = ((BUFOFS) ? 8 : 0) + ksl;                              \
            uint4 fa0 = ldfragA(uA, rs_ * 2,     ksA, lane);                       \
            uint4 fa1 = ldfragA(uA, rs_ * 2 + 1, ksA, lane);                       \
            _Pragma("unroll")                                                      \
            for (int j = 0; j < 4; j++) {                                          \
                uint2 bb = B1[(BUFOFS) + ((cq * 4 + j) * 8 + ksl) * 32 + lane];    \
                mma8(acc[0][j], fa0, bb); mma8(acc[1][j], fa1, bb);                \
            }                                                                      \
        }
    #define CRIT_CHUNK_ROW(BUFOFS, KBASE)                                          \
        _Pragma("unroll")                                                          \
        for (int ksl = 0; ksl < 8; ksl++) {                                        \
            const int ks = (KBASE) + ksl;                                          \
            uint4 fa0 = make_uint4(A0[ks*8], A0[ks*8 + 8*PAD], A0[ks*8 + 4], A0[ks*8 + 8*PAD + 4]); \
            uint4 fa1 = make_uint4(A1[ks*8], A1[ks*8 + 8*PAD], A1[ks*8 + 4], A1[ks*8 + 8*PAD + 4]); \
            _Pragma("unroll")                                                      \
            for (int j = 0; j < 4; j++) {                                          \
                uint2 bb = B1[(BUFOFS) + ((cq * 4 + j) * 8 + ksl) * 32 + lane];    \
                mma8(acc[0][j], fa0, bb); mma8(acc[1][j], fa1, bb);                \
            }                                                                      \
        }

    CP_WAITG(1);            // ch0 + A0 done
    __syncthreads();
    CRIT_CHUNK_FRAG(0)                       // ph0 ks 0..7
    __syncthreads();
    crit_stageW(B1, 0, 2, n, tid); CP_COMMIT();
    CP_WAITG(1);            // ch1 done
    __syncthreads();
    CRIT_CHUNK_FRAG(4096)                    // ph0 ks 8..15
    __syncthreads();
    {   // A refill (ph1, row-major from g_oth)
        const float* src = g_oth;
        for (int i = tid; i < 2048; i += 256) {
            int r = i >> 5, c4 = i & 31;
            cp16(uA + r * PAD + c4 * 4, src + (row0 + r) * 128 + c4 * 4);
        }
    }
    CP_COMMIT();
    crit_stageW(B1, 4096, 3, n, tid); CP_COMMIT();
    CP_WAITG(1);            // ch2 + A1 done
    __syncthreads();
    CRIT_CHUNK_ROW(0, 0)                     // ph1 ks 0..7
    __syncthreads();
    CP_WAITG(0);
    __syncthreads();
    CRIT_CHUNK_ROW(4096, 8)                  // ph1 ks 8..15
    __syncthreads();
    #undef CRIT_CHUNK_FRAG
    #undef CRIT_CHUNK_ROW

    #pragma unroll
    for (int mi = 0; mi < 2; mi++) {
        #pragma unroll
        for (int j = 0; j < 4; j++) {
            int r = rs_ * 32 + mi * 16 + g;
            int c = cq * 32 + j * 8 + 2 * tig;
            float bb0 = b1s[c], bb1 = b1s[c + 1];
            h[r * HSTR + c]           = lrelu(acc[mi][j].x + bb0);
            h[r * HSTR + c + 1]       = lrelu(acc[mi][j].y + bb1);
            h[(r + 8) * HSTR + c]     = lrelu(acc[mi][j].z + bb0);
            h[(r + 8) * HSTR + c + 1] = lrelu(acc[mi][j].w + bb1);
        }
    }
    __syncthreads();

    const int o = lane & 15, half = lane >> 4;
    #pragma unroll
    for (int rr = 0; rr < 8; rr++) {
        const int r = w * 8 + rr;
        const int bidx = blockIdx.x * 64 + r;
        const float4* hr4 = (const float4*)(h + r * HSTR + half * 64);
        const float4* w4  = (const float4*)(w2t + o * HSTR + half * 64);
        float q = 0.f;
        #pragma unroll
        for (int i = 0; i < 16; i++) {
            float4 hv = hr4[i], wv = w4[i];
            q += hv.x * wv.x + hv.y * wv.y + hv.z * wv.z + hv.w * wv.w;
        }
        q += __shfl_xor_sync(FULLMASK, q, 16);
        q += b2s[o];

        float qsel = __shfl_sync(FULLMASK, q, amx[r]);
        if (lane == 0) out[(size_t)n * B + bidx] = qsel;
    }
}

// ============================================================
extern "C" void kernel_launch(void* const* d_in, const int* in_sizes, int n_in,
                              void* d_out, int out_size)
{
    const float* s    = (const float*)d_in[0];
    const float* a    = (const float*)d_in[1];
    const float* Wsa  = (const float*)d_in[2];
    const float* Bsa  = (const float*)d_in[3];
    const float* Wse  = (const float*)d_in[4];
    const float* Bse  = (const float*)d_in[5];
    const float* Wk   = (const float*)d_in[6];
    const float* Wsel = (const float*)d_in[7];
    const float* Wv   = (const float*)d_in[8];
    const float* bv   = (const float*)d_in[9];
    const float* Wc1  = (const float*)d_in[10];
    const float* Bc1  = (const float*)d_in[11];
    const float* Wc2  = (const float*)d_in[12];
    const float* Bc2  = (const float*)d_in[13];
    float* out = (float*)d_out;

    cudaFuncSetAttribute(k_front, cudaFuncAttributeMaxDynamicSharedMemorySize, SMEM_FRONT);
    cudaFuncSetAttribute(k_crit,  cudaFuncAttributeMaxDynamicSharedMemorySize, SMEM_CRIT);

    k_prep_stats<<<576, 512>>>(Wk, Wv, Wsel, Wsa, Wse, Wc1, s, a);
    k_stats2    <<<1, 640>>>();
    k_front     <<<dim3(B / 64, NAG), 256, SMEM_FRONT>>>(s, a, Bsa, Bse, bv);
    k_attn      <<<dim3((HEADS * B) / 8), 256>>>();
    k_crit      <<<dim3(B / 64, NAG), 256, SMEM_CRIT>>>(a, Bc1, Wc2, Bc2, out);
}

// round 11
// speedup vs baseline: 3.7468x; 1.2642x over previous
#include <cuda_runtime.h>
#include <cuda_fp16.h>
#include <math.h>
#include <stdint.h>

#define FULLMASK 0xffffffffu

constexpr int NAG  = 8;
constexpr int B    = 16384;
constexpr int SD   = 64;
constexpr int AD   = 16;
constexpr int KSA  = 80;
constexpr int HID  = 128;
constexpr int HEADS= 4;
constexpr int D    = 32;
constexpr float EPS = 1e-5f;

// -------- scratch --------
__device__ __align__(16) float g_mean[NAG * KSA];
__device__ __align__(16) float g_rstd[NAG * KSA];
__device__ __align__(16) float g_part [NAG * 16 * KSA];
__device__ __align__(16) float g_partq[NAG * 16 * KSA];
__device__ __align__(16) __half g_se [(size_t)NAG * B * HID];   // fp16 FRAGMENT-ORDER 64-row tiles
__device__ __align__(16) __half g_key[(size_t)NAG * B * HID];   // fp16 row-major
__device__ __align__(16) __half g_val[(size_t)NAG * B * HID];
__device__ __align__(16) __half g_sel[(size_t)NAG * B * HID];
__device__ __align__(16) __half g_oth[(size_t)NAG * B * HID];   // fp16 row-major

// fragment-order weights: enc tf32, rest fp16
__device__ __align__(16) uint2 pWsa [NAG][16 * 10 * 32];   // tf32
__device__ __align__(16) uint2 pWse [NAG][16 * 8 * 32];    // tf32
__device__ __align__(16) uint2 pWk16 [8 * 16 * 32];        // fp16: [(n8*8+ksh)*32+lane]
__device__ __align__(16) uint2 pWv16 [8 * 16 * 32];
__device__ __align__(16) uint2 pWsel16[8 * 16 * 32];
__device__ __align__(16) uint2 pWc116[NAG][16 * 16 * 32];  // fp16: [(n8*16+ksh)*32+lane]

__device__ __forceinline__ float lrelu(float x) { return x > 0.f ? x : 0.01f * x; }

__device__ __forceinline__ uint32_t tf32rn(float x) {
    uint32_t u; asm("cvt.rna.tf32.f32 %0, %1;" : "=r"(u) : "f"(x)); return u;
}
// pack (lo,hi) floats -> f16x2 (lo in low half)
__device__ __forceinline__ uint32_t h2(float lo, float hi) {
    uint32_t r; asm("cvt.rn.f16x2.f32 %0, %1, %2;" : "=r"(r) : "f"(hi), "f"(lo)); return r;
}
__device__ __forceinline__ void mma8(float4& d, const uint4 a, const uint2 b) {
    asm volatile(
        "mma.sync.aligned.m16n8k8.row.col.f32.tf32.tf32.f32 "
        "{%0,%1,%2,%3}, {%4,%5,%6,%7}, {%8,%9}, {%0,%1,%2,%3};"
        : "+f"(d.x), "+f"(d.y), "+f"(d.z), "+f"(d.w)
        : "r"(a.x), "r"(a.y), "r"(a.z), "r"(a.w), "r"(b.x), "r"(b.y));
}
__device__ __forceinline__ void mma16(float4& d, const uint4 a, const uint2 b) {
    asm volatile(
        "mma.sync.aligned.m16n8k16.row.col.f32.f16.f16.f32 "
        "{%0,%1,%2,%3}, {%4,%5,%6,%7}, {%8,%9}, {%0,%1,%2,%3};"
        : "+f"(d.x), "+f"(d.y), "+f"(d.z), "+f"(d.w)
        : "r"(a.x), "r"(a.y), "r"(a.z), "r"(a.w), "r"(b.x), "r"(b.y));
}
__device__ __forceinline__ void cp16(void* smem_dst, const void* gsrc) {
    uint32_t sa = (uint32_t)__cvta_generic_to_shared(smem_dst);
    asm volatile("cp.async.cg.shared.global [%0], [%1], 16;" :: "r"(sa), "l"(gsrc));
}
#define CP_COMMIT()  asm volatile("cp.async.commit_group;")
#define CP_WAITG(n)  asm volatile("cp.async.wait_group " #n ";" ::: "memory")

// fp16 fragment-order A load: one LDS.128 (tile: 4 g16 x 8 ksh x 32 lanes x uint4)
__device__ __forceinline__ uint4 ldfrag16(const uint32_t* A16, int g16, int ksh, int lane) {
    return *(const uint4*)(A16 + (((g16 << 3) + ksh) << 7) + (lane << 2));
}
// store one (mi,j) accumulator's 4 values as fp16 fragment words
__device__ __forceinline__ void st_frag16(uint32_t* A16, int g16, int n8, int tig, int g, float4 v) {
    int C = n8 * 8 + 2 * tig;
    int ksh = C >> 4;
    int co  = C & 15;
    int rego = (co >= 8) ? 2 : 0;
    int lanep = g * 4 + ((co & 7) >> 1);
    uint32_t* base = A16 + ((((g16 << 3) + ksh) << 5) + lanep) * 4;
    base[rego]     = h2(v.x, v.y);   // row R  : cols C,C+1
    base[rego + 1] = h2(v.z, v.w);   // row R+8
}

// ============================================================
// K0: prep (weight fragments) + BN partial stats, fused
// grid 424 x 512: blocks [0,296) prep, [296,424) stats
// ============================================================
__global__ void __launch_bounds__(512)
k_prep_stats(const float* __restrict__ Wk, const float* __restrict__ Wv,
             const float* __restrict__ Wsel, const float* __restrict__ Wsa,
             const float* __restrict__ Wse, const float* __restrict__ Wc1,
             const float* __restrict__ s, const float* __restrict__ a)
{
    __shared__ float r1[512], r2[512];
    const int tid = threadIdx.x;

    if (blockIdx.x < 296) {
        int i = blockIdx.x * 512 + tid;
        if (i < 12288) {                      // proj fp16: [(n8*8+ksh)*32+lane]
            int which = i >> 12;
            int j = i & 4095;
            int n8 = j >> 8, ksh = (j >> 5) & 7, lane = j & 31;
            int g = lane >> 2, tig = lane & 3;
            int n = n8 * 8 + g, k0 = ksh * 16 + tig * 2;
            const float* W = which == 0 ? Wk : (which == 1 ? Wv : Wsel);
            const float* base = W + (n >> 5) * (HID * D) + (n & 31);
            uint2 v = make_uint2(h2(base[k0 * 32],       base[(k0 + 1) * 32]),
                                 h2(base[(k0 + 8) * 32], base[(k0 + 9) * 32]));
            (which == 0 ? pWk16 : which == 1 ? pWv16 : pWsel16)[j] = v;
            return;
        }
        int i2 = i - 12288;
        if (i2 < NAG * 5120) {                // pWsa tf32
            int n = i2 / 5120, j = i2 % 5120;
            int lane = j & 31, ks = (j >> 5) % 10, n8 = j / 320;
            int g = lane >> 2, tig = lane & 3;
            int nn = n8 * 8 + g, k = ks * 8 + tig;
            const float* W = Wsa + n * KSA * HID;
            pWsa[n][j] = make_uint2(tf32rn(W[k * HID + nn]), tf32rn(W[(k + 4) * HID + nn]));
            return;
        }
        int i3 = i2 - NAG * 5120;
        if (i3 < NAG * 4096) {                // pWse tf32
            int n = i3 >> 12, j = i3 & 4095;
            int lane = j & 31, ks = (j >> 5) & 7, n8 = j >> 8;
            int g = lane >> 2, tig = lane & 3;
            int nn = n8 * 8 + g, k = ks * 8 + tig;
            const float* W = Wse + n * SD * HID;
            pWse[n][j] = make_uint2(tf32rn(W[k * HID + nn]), tf32rn(W[(k + 4) * HID + nn]));
            return;
        }
        int i4 = i3 - NAG * 4096;
        if (i4 < NAG * 8192) {                // pWc116 fp16: [(n8*16+ksh)*32+lane]
            int n = i4 >> 13, j = i4 & 8191;
            int lane = j & 31, ksh = (j >> 5) & 15, n8 = j >> 9;
            int g = lane >> 2, tig = lane & 3;
            int nn = n8 * 8 + g, k0 = ksh * 16 + tig * 2;
            const float* W = Wc1 + (size_t)n * 2 * HID * HID;
            pWc116[n][j] = make_uint2(h2(W[k0 * 128 + nn],       W[(k0 + 1) * 128 + nn]),
                                      h2(W[(k0 + 8) * 128 + nn], W[(k0 + 9) * 128 + nn]));
        }
        return;
    }

    const int bx = blockIdx.x - 296;
    const int n = bx >> 4, chunk = bx & 15;
    const size_t row0 = (size_t)n * B + chunk * 1024;
    float* part  = g_part  + (n * 16 + chunk) * KSA;
    float* partq = g_partq + (n * 16 + chunk) * KSA;

    {
        const int f = tid & 63, r0 = tid >> 6;
        float sum = 0.f, sq = 0.f;
        const float* p = s + (row0 + r0) * SD + f;
        #pragma unroll 4
        for (int st = 0; st < 128; st++) {
            float x = p[(size_t)st * 8 * SD];
            sum += x; sq += x * x;
        }
        r1[tid] = sum; r2[tid] = sq;
        __syncthreads();
        #pragma unroll
        for (int o = 4; o > 0; o >>= 1) {
            if (tid < o * 64) { r1[tid] += r1[tid + o * 64]; r2[tid] += r2[tid + o * 64]; }
            __syncthreads();
        }
        if (tid < 64) { part[tid] = r1[tid]; partq[tid] = r2[tid]; }
        __syncthreads();
    }
    {
        const int f = tid & 15, r0 = tid >> 4;
        float sum = 0.f, sq = 0.f;
        const float* p = a + (row0 + r0) * AD + f;
        #pragma unroll 4
        for (int st = 0; st < 32; st++) {
            float x = p[(size_t)st * 32 * AD];
            sum += x; sq += x * x;
        }
        r1[tid] = sum; r2[tid] = sq;
        __syncthreads();
        #pragma unroll
        for (int o = 16; o > 0; o >>= 1) {
            if (tid < o * 16) { r1[tid] += r1[tid + o * 16]; r2[tid] += r2[tid + o * 16]; }
            __syncthreads();
        }
        if (tid < 16) { part[64 + tid] = r1[tid]; partq[64 + tid] = r2[tid]; }
    }
}

__global__ void k_stats2()
{
    int i = threadIdx.x;
    if (i >= NAG * KSA) return;
    int n = i / KSA, f = i % KSA;
    float sum = 0.f, sq = 0.f;
    for (int c = 0; c < 16; c++) {
        sum += g_part [(n * 16 + c) * KSA + f];
        sq  += g_partq[(n * 16 + c) * KSA + f];
    }
    float m = sum * (1.f / B);
    float v = sq * (1.f / B) - m * m;
    g_mean[i] = m;
    g_rstd[i] = rsqrtf(v + EPS);
}

// ============================================================
// K2: FUSED front: enc(tf32) -> sel(fp16) -> kv(fp16)
// 64-row tiles, 256 thr, 2 blocks/SM
// ============================================================
constexpr int FR_OFF_ATF  = 0;                            // 4*10*32*16 = 20480
constexpr int FR_OFF_A16  = 20480;                        // 4*8*32*16  = 16384
constexpr int FR_OFF_W    = 36864;                        // 73728
constexpr int FR_OFF_MISC = 110592;                       // 544 floats
constexpr int SMEM_FRONT  = 112768;

__global__ void __launch_bounds__(256, 2)
k_front(const float* __restrict__ s, const float* __restrict__ a,
        const float* __restrict__ Bsa, const float* __restrict__ Bse,
        const float* __restrict__ bv)
{
    extern __shared__ char smc[];
    uint32_t* uAtf = (uint32_t*)(smc + FR_OFF_ATF);
    uint32_t* uA16 = (uint32_t*)(smc + FR_OFF_A16);
    uint2*    W    = (uint2*)(smc + FR_OFF_W);
    char*     Wc   = smc + FR_OFF_W;
    float*   bsa = (float*)(smc + FR_OFF_MISC);
    float*   bse = bsa + 128;
    float*   bvv = bse + 128;
    float*   mn  = bvv + 128;
    float*   rsd = mn + 80;

    const int n = blockIdx.y, tid = threadIdx.x;
    const size_t gr0 = (size_t)n * B + (size_t)blockIdx.x * 64;

    // prefetch enc weights (tf32): Wsa 40960B + Wse 32768B
    for (int c = tid; c < 4608; c += 256) {
        const char* src = (c < 2560) ? (const char*)pWsa[n] + c * 16
                                     : (const char*)pWse[n] + (c - 2560) * 16;
        cp16(Wc + c * 16, src);
    }
    CP_COMMIT();

    for (int i = tid; i < 128; i += 256) {
        bsa[i] = Bsa[n * HID + i];
        bse[i] = Bse[n * HID + i];
        bvv[i] = bv[i];
    }
    for (int i = tid; i < 80; i += 256) {
        mn[i]  = g_mean[n * KSA + i];
        rsd[i] = g_rstd[n * KSA + i];
    }
    __syncthreads();

    // A fill: BN'd [64 x 80] -> tf32 fragment order (10 k8-steps)
    for (int i = tid; i < 64 * 20; i += 256) {
        int r = i / 20, c4 = i - r * 20;
        size_t row = gr0 + r;
        float4 v = (c4 < 16) ? ((const float4*)s)[row * 16 + c4]
                             : ((const float4*)a)[row * 4 + (c4 - 16)];
        int C = c4 * 4;
        int ks = C >> 3, half = (C >> 2) & 1;
        int g16 = r >> 4, comp_r = (r >> 3) & 1, gp = r & 7;
        uint32_t* p = uAtf + (((g16 * 10 + ks) << 5) + (gp << 2)) * 4 + comp_r + 2 * half;
        p[0]  = tf32rn((v.x - mn[C])     * rsd[C]);
        p[4]  = tf32rn((v.y - mn[C + 1]) * rsd[C + 1]);
        p[8]  = tf32rn((v.z - mn[C + 2]) * rsd[C + 2]);
        p[12] = tf32rn((v.w - mn[C + 3]) * rsd[C + 3]);
    }
    CP_WAITG(0);
    __syncthreads();

    const int w = tid >> 5, lane = tid & 31;
    const int rs_ = w & 1, t0 = w >> 1;
    const int g = lane >> 2, tig = lane & 3;

    // ---- Phase 1: enc (tf32) ----
    float4 ae[2][4], as_[2][4];
    #pragma unroll
    for (int mi = 0; mi < 2; mi++)
        #pragma unroll
        for (int j = 0; j < 4; j++) { ae[mi][j] = make_float4(0,0,0,0); as_[mi][j] = make_float4(0,0,0,0); }

    #pragma unroll
    for (int ks = 0; ks < 10; ks++) {
        uint4 fa0 = *(const uint4*)(uAtf + (((rs_*2)   * 10 + ks) << 7) + (lane << 2));
        uint4 fa1 = *(const uint4*)(uAtf + (((rs_*2+1) * 10 + ks) << 7) + (lane << 2));
        #pragma unroll
        for (int j = 0; j < 4; j++) {
            uint2 bb = W[((t0 * 4 + j) * 10 + ks) * 32 + lane];
            mma8(ae[0][j], fa0, bb); mma8(ae[1][j], fa1, bb);
        }
        if (ks < 8) {
            #pragma unroll
            for (int j = 0; j < 4; j++) {
                uint2 bb = W[5120 + ((t0 * 4 + j) * 8 + ks) * 32 + lane];
                mma8(as_[0][j], fa0, bb); mma8(as_[1][j], fa1, bb);
            }
        }
    }
    __syncthreads();

    // prefetch Wsel16 (32KB) during epilogue
    for (int c = tid; c < 2048; c += 256) cp16(Wc + c * 16, (const char*)pWsel16 + c * 16);
    CP_COMMIT();

    // bias+lrelu; write g_se (fp16 fragment tile) and A16 = se
    uint32_t* gseT = (uint32_t*)g_se + ((gr0 >> 6) << 12);
    #pragma unroll
    for (int mi = 0; mi < 2; mi++) {
        #pragma unroll
        for (int j = 0; j < 4; j++) {
            int c = t0 * 32 + j * 8 + 2 * tig;
            float b0e = bsa[c], b1e = bsa[c + 1];
            float b0s = bse[c], b1s = bse[c + 1];
            ae[mi][j]  = make_float4(lrelu(ae[mi][j].x + b0e), lrelu(ae[mi][j].y + b1e),
                                     lrelu(ae[mi][j].z + b0e), lrelu(ae[mi][j].w + b1e));
            as_[mi][j] = make_float4(lrelu(as_[mi][j].x + b0s), lrelu(as_[mi][j].y + b1s),
                                     lrelu(as_[mi][j].z + b0s), lrelu(as_[mi][j].w + b1s));
            st_frag16(uA16, rs_ * 2 + mi, t0 * 4 + j, tig, g, as_[mi][j]);
            st_frag16(gseT, rs_ * 2 + mi, t0 * 4 + j, tig, g, as_[mi][j]);
        }
    }
    CP_WAITG(0);
    __syncthreads();

    // ---- Phase 2: sel (fp16) ----
    float4 ac[2][4], acv[2][4];
    #pragma unroll
    for (int mi = 0; mi < 2; mi++)
        #pragma unroll
        for (int j = 0; j < 4; j++) ac[mi][j] = make_float4(0,0,0,0);

    #pragma unroll
    for (int ksh = 0; ksh < 8; ksh++) {
        uint4 fa0 = ldfrag16(uA16, rs_ * 2,     ksh, lane);
        uint4 fa1 = ldfrag16(uA16, rs_ * 2 + 1, ksh, lane);
        #pragma unroll
        for (int j = 0; j < 4; j++) {
            uint2 bb = W[((t0 * 4 + j) * 8 + ksh) * 32 + lane];
            mma16(ac[0][j], fa0, bb); mma16(ac[1][j], fa1, bb);
        }
    }
    __syncthreads();    // sel weights + A16(se) fully read

    // prefetch Wk16 + Wv16 (64KB total): Wk -> W[0..4095], Wv -> W[4096..8191]
    for (int c = tid; c < 4096; c += 256) {
        const char* src = (c < 2048) ? (const char*)pWk16 + c * 16
                                     : (const char*)pWv16 + (c - 2048) * 16;
        cp16(Wc + c * 16, src);
    }
    CP_COMMIT();

    // sel epilogue: g_sel fp16 row-major; restage A16 = e
    #pragma unroll
    for (int mi = 0; mi < 2; mi++) {
        #pragma unroll
        for (int j = 0; j < 4; j++) {
            int c = t0 * 32 + j * 8 + 2 * tig;
            size_t gr = gr0 + rs_ * 32 + mi * 16 + g;
            *(uint32_t*)&g_sel[gr * 128 + c]       = h2(ac[mi][j].x, ac[mi][j].y);
            *(uint32_t*)&g_sel[(gr + 8) * 128 + c] = h2(ac[mi][j].z, ac[mi][j].w);
            st_frag16(uA16, rs_ * 2 + mi, t0 * 4 + j, tig, g, ae[mi][j]);
        }
    }
    CP_WAITG(0);
    __syncthreads();

    // ---- Phase 3: key + val (fp16, both weight mats resident) ----
    #pragma unroll
    for (int mi = 0; mi < 2; mi++)
        #pragma unroll
        for (int j = 0; j < 4; j++) { ac[mi][j] = make_float4(0,0,0,0); acv[mi][j] = make_float4(0,0,0,0); }

    #pragma unroll
    for (int ksh = 0; ksh < 8; ksh++) {
        uint4 fa0 = ldfrag16(uA16, rs_ * 2,     ksh, lane);
        uint4 fa1 = ldfrag16(uA16, rs_ * 2 + 1, ksh, lane);
        #pragma unroll
        for (int j = 0; j < 4; j++) {
            int bi = ((t0 * 4 + j) * 8 + ksh) * 32 + lane;
            uint2 bk = W[bi], bw = W[4096 + bi];     // FIXED: Wv lives at uint2 4096+
            mma16(ac[0][j],  fa0, bk); mma16(ac[1][j],  fa1, bk);
            mma16(acv[0][j], fa0, bw); mma16(acv[1][j], fa1, bw);
        }
    }

    // kv epilogue: fp16 row-major
    #pragma unroll
    for (int mi = 0; mi < 2; mi++) {
        #pragma unroll
        for (int j = 0; j < 4; j++) {
            size_t gr = gr0 + rs_ * 32 + mi * 16 + g;
            int c = t0 * 32 + j * 8 + 2 * tig;
            *(uint32_t*)&g_key[gr * 128 + c]       = h2(ac[mi][j].x, ac[mi][j].y);
            *(uint32_t*)&g_key[(gr + 8) * 128 + c] = h2(ac[mi][j].z, ac[mi][j].w);
            float bb0 = bvv[c], bb1 = bvv[c + 1];
            *(uint32_t*)&g_val[gr * 128 + c]       = h2(lrelu(acv[mi][j].x + bb0), lrelu(acv[mi][j].y + bb1));
            *(uint32_t*)&g_val[(gr + 8) * 128 + c] = h2(lrelu(acv[mi][j].z + bb0), lrelu(acv[mi][j].w + bb1));
        }
    }
}

// ============================================================
// K3: attention — fp16 inputs/outputs, fp32 math
// ============================================================
constexpr int ASTR = 36;
__global__ void __launch_bounds__(256, 4)
k_attn()
{
    __shared__ float smem[8][3 * 8 * ASTR + 64];
    const int tid = threadIdx.x, warp = tid >> 5, lane = tid & 31;
    const int gid = blockIdx.x * 8 + warp;
    const int b = gid >> 2;
    const int p = gid & 3;

    float* selS = smem[warp];
    float* keyS = selS + 8 * ASTR;
    float* valS = keyS + 8 * ASTR;
    float* wS   = valS + 8 * ASTR;
    const float scale = 0.17677669529663687f;

    // 24 segs (3 arrays x 8 agents) x 32 halves; 4 uint4 per seg -> 3 per lane
    #pragma unroll
    for (int it = 0; it < 3; it++) {
        int idx = it * 32 + lane;
        int seg = idx >> 2, q4 = idx & 3;
        int arr = seg >> 3, i = seg & 7;
        const __half* gsrc = (arr == 0) ? g_sel : (arr == 1) ? g_key : g_val;
        uint4 v = *(const uint4*)(gsrc + ((size_t)i * B + b) * HID + p * D + q4 * 8);
        const __half2* hp = (const __half2*)&v;
        float* dst = selS + arr * (8 * ASTR) + i * ASTR + q4 * 8;
        #pragma unroll
        for (int q = 0; q < 4; q++) {
            float2 f = __half22float2(hp[q]);
            dst[q * 2] = f.x; dst[q * 2 + 1] = f.y;
        }
    }
    __syncwarp();

    const int i0 = lane >> 3, j = lane & 7, i1 = i0 + 4;
    float acc0 = 0.f, acc1 = 0.f;
    #pragma unroll
    for (int d = 0; d < 32; d++) {
        float kv = keyS[j * ASTR + d];
        acc0 += selS[i0 * ASTR + d] * kv;
        acc1 += selS[i1 * ASTR + d] * kv;
    }
    acc0 *= scale; acc1 *= scale;
    if (i0 == j) acc0 = -1e9f;
    if (i1 == j) acc1 = -1e9f;

    float m0 = acc0, m1 = acc1;
    #pragma unroll
    for (int o = 1; o < 8; o <<= 1) {
        m0 = fmaxf(m0, __shfl_xor_sync(FULLMASK, m0, o));
        m1 = fmaxf(m1, __shfl_xor_sync(FULLMASK, m1, o));
    }
    float e0 = __expf(acc0 - m0), e1 = __expf(acc1 - m1);
    float s0 = e0, s1 = e1;
    #pragma unroll
    for (int o = 1; o < 8; o <<= 1) {
        s0 += __shfl_xor_sync(FULLMASK, s0, o);
        s1 += __shfl_xor_sync(FULLMASK, s1, o);
    }
    wS[lane]      = __fdividef(e0, s0);
    wS[lane + 32] = __fdividef(e1, s1);
    __syncwarp();

    float out[8];
    #pragma unroll
    for (int ii = 0; ii < 8; ii++) out[ii] = 0.f;
    #pragma unroll
    for (int jj = 0; jj < 8; jj++) {
        float v = valS[jj * ASTR + lane];
        #pragma unroll
        for (int ii = 0; ii < 8; ii++) out[ii] += wS[ii * 8 + jj] * v;
    }
    #pragma unroll
    for (int ii = 0; ii < 8; ii++)
        g_oth[((size_t)ii * B + b) * HID + p * D + lane] = __float2half_rn(out[ii]);
}

// ============================================================
// K4: critic fp16 — ph0 A = g_se fragment tile (byte copy),
// ph1 A = g_oth rows (padded stride 136 halves)
// ============================================================
constexpr int HSTR   = 132;   // f32 h stride
constexpr int OSTRU  = 68;    // ph1 A row stride in u32 (136 halves)
constexpr int CR_OFF_A   = 0;                             // 33792
constexpr int CR_OFF_B1  = 33792;                         // 2 x 32768
constexpr int CR_OFF_W2  = 99328;                         // 8448
constexpr int CR_OFF_B1S = 107776;
constexpr int CR_OFF_B2S = 108288;
constexpr int CR_OFF_AMX = 108352;
constexpr int SMEM_CRIT  = 108608;

__device__ __forceinline__ void crit_stageW16(uint2* B1, int buf, int ph, int n, int tid) {
    const uint2* base = pWc116[n];
    for (int cc = tid; cc < 2048; cc += 256) {
        int lanepair = cc & 15, ksl = (cc >> 4) & 7, n8 = cc >> 7;
        cp16(B1 + buf + (n8 * 8 + ksl) * 32 + lanepair * 2,
             base + ((n8 * 16 + ph * 8 + ksl) * 32 + lanepair * 2));
    }
}

__global__ void __launch_bounds__(256, 2)
k_crit(const float* __restrict__ a,
       const float* __restrict__ Bc1,
       const float* __restrict__ Wc2, const float* __restrict__ Bc2,
       float* __restrict__ out)
{
    extern __shared__ char smc[];
    uint32_t* uA = (uint32_t*)(smc + CR_OFF_A);
    uint2*    B1 = (uint2*)(smc + CR_OFF_B1);
    float*    h  = (float*)(smc + CR_OFF_A);
    float*   w2t = (float*)(smc + CR_OFF_W2);
    float*   b1s = (float*)(smc + CR_OFF_B1S);
    float*   b2s = (float*)(smc + CR_OFF_B2S);
    int*     amx = (int*)(smc + CR_OFF_AMX);

    const int n = blockIdx.y, tid = threadIdx.x;
    const int w = tid >> 5, lane = tid & 31;
    const size_t row0 = (size_t)n * B + (size_t)blockIdx.x * 64;

    // pipeline head: Wph0 -> buf0 ; A ph0 (se fragment tile, 16KB) ; Wph1 -> buf1
    crit_stageW16(B1, 0, 0, n, tid);        CP_COMMIT();
    {
        const uint32_t* gseT = (const uint32_t*)g_se + ((row0 >> 6) << 12);
        for (int i = tid; i < 1024; i += 256) cp16(uA + i * 4, gseT + i * 4);
    }
    CP_COMMIT();
    crit_stageW16(B1, 4096, 1, n, tid);     CP_COMMIT();

    for (int i = tid; i < HID * AD; i += 256) {
        int k = i >> 4, o = i & 15;
        w2t[o * HSTR + k] = Wc2[n * HID * AD + k * AD + o];
    }
    if (tid < HID) b1s[tid] = Bc1[n * HID + tid];
    if (tid >= HID && tid < HID + AD) b2s[tid - HID] = Bc2[n * AD + (tid - HID)];
    if (tid < 64) {
        const float4* ap = (const float4*)(a + (row0 + tid) * AD);
        float4 q0 = ap[0], q1 = ap[1], q2 = ap[2], q3 = ap[3];
        float vals[16] = {q0.x,q0.y,q0.z,q0.w, q1.x,q1.y,q1.z,q1.w,
                          q2.x,q2.y,q2.z,q2.w, q3.x,q3.y,q3.z,q3.w};
        int bi = 0; float bvv = vals[0];
        #pragma unroll
        for (int i = 1; i < 16; i++) if (vals[i] > bvv) { bvv = vals[i]; bi = i; }
        amx[tid] = bi;
    }

    const int rs_ = w & 1, cq = w >> 1;
    const int g = lane >> 2, tig = lane & 3;

    float4 acc[2][4];
    #pragma unroll
    for (int mi = 0; mi < 2; mi++)
        #pragma unroll
        for (int j = 0; j < 4; j++) acc[mi][j] = make_float4(0,0,0,0);

    CP_WAITG(1);            // Wph0 + A0 done
    __syncthreads();

    // ---- ph0: se (fragment-order fp16) ----
    #pragma unroll
    for (int ksl = 0; ksl < 8; ksl++) {
        uint4 fa0 = ldfrag16(uA, rs_ * 2,     ksl, lane);
        uint4 fa1 = ldfrag16(uA, rs_ * 2 + 1, ksl, lane);
        #pragma unroll
        for (int j = 0; j < 4; j++) {
            uint2 bb = B1[((cq * 4 + j) * 8 + ksl) * 32 + lane];
            mma16(acc[0][j], fa0, bb); mma16(acc[1][j], fa1, bb);
        }
    }
    __syncthreads();        // A region free

    // A refill (ph1: oth rows fp16, padded stride 136 halves)
    for (int i = tid; i < 1024; i += 256) {
        int r = i >> 4, c = i & 15;
        cp16(uA + r * OSTRU + c * 4,
             (const uint32_t*)g_oth + (row0 + r) * 64 + c * 4);
    }
    CP_COMMIT();
    CP_WAITG(0);            // Wph1 + A1 done
    __syncthreads();

    // ---- ph1: oth (row-major fp16) ----
    const int R0 = rs_ * 32 + g;
    #pragma unroll
    for (int ksl = 0; ksl < 8; ksl++) {
        uint4 fa0, fa1;
        {
            const uint32_t* b0 = uA + R0 * OSTRU + ksl * 8 + tig;
            fa0 = make_uint4(b0[0], b0[8 * OSTRU], b0[4], b0[8 * OSTRU + 4]);
            const uint32_t* b1 = b0 + 16 * OSTRU;
            fa1 = make_uint4(b1[0], b1[8 * OSTRU], b1[4], b1[8 * OSTRU + 4]);
        }
        #pragma unroll
        for (int j = 0; j < 4; j++) {
            uint2 bb = B1[4096 + ((cq * 4 + j) * 8 + ksl) * 32 + lane];
            mma16(acc[0][j], fa0, bb); mma16(acc[1][j], fa1, bb);
        }
    }
    __syncthreads();        // all A reads done before h overwrites uA

    #pragma unroll
    for (int mi = 0; mi < 2; mi++) {
        #pragma unroll
        for (int j = 0; j < 4; j++) {
            int r = rs_ * 32 + mi * 16 + g;
            int c = cq * 32 + j * 8 + 2 * tig;
            float bb0 = b1s[c], bb1 = b1s[c + 1];
            h[r * HSTR + c]           = lrelu(acc[mi][j].x + bb0);
            h[r * HSTR + c + 1]       = lrelu(acc[mi][j].y + bb1);
            h[(r + 8) * HSTR + c]     = lrelu(acc[mi][j].z + bb0);
            h[(r + 8) * HSTR + c + 1] = lrelu(acc[mi][j].w + bb1);
        }
    }
    __syncthreads();

    const int o = lane & 15, half = lane >> 4;
    #pragma unroll
    for (int rr = 0; rr < 8; rr++) {
        const int r = w * 8 + rr;
        const int bidx = blockIdx.x * 64 + r;
        const float4* hr4 = (const float4*)(h + r * HSTR + half * 64);
        const float4* w4  = (const float4*)(w2t + o * HSTR + half * 64);
        float q = 0.f;
        #pragma unroll
        for (int i = 0; i < 16; i++) {
            float4 hv = hr4[i], wv = w4[i];
            q += hv.x * wv.x + hv.y * wv.y + hv.z * wv.z + hv.w * wv.w;
        }
        q += __shfl_xor_sync(FULLMASK, q, 16);
        q += b2s[o];

        float qsel = __shfl_sync(FULLMASK, q, amx[r]);
        if (lane == 0) out[(size_t)n * B + bidx] = qsel;
    }
}

// ============================================================
extern "C" void kernel_launch(void* const* d_in, const int* in_sizes, int n_in,
                              void* d_out, int out_size)
{
    const float* s    = (const float*)d_in[0];
    const float* a    = (const float*)d_in[1];
    const float* Wsa  = (const float*)d_in[2];
    const float* Bsa  = (const float*)d_in[3];
    const float* Wse  = (const float*)d_in[4];
    const float* Bse  = (const float*)d_in[5];
    const float* Wk   = (const float*)d_in[6];
    const float* Wsel = (const float*)d_in[7];
    const float* Wv   = (const float*)d_in[8];
    const float* bv   = (const float*)d_in[9];
    const float* Wc1  = (const float*)d_in[10];
    const float* Bc1  = (const float*)d_in[11];
    const float* Wc2  = (const float*)d_in[12];
    const float* Bc2  = (const float*)d_in[13];
    float* out = (float*)d_out;

    cudaFuncSetAttribute(k_front, cudaFuncAttributeMaxDynamicSharedMemorySize, SMEM_FRONT);
    cudaFuncSetAttribute(k_crit,  cudaFuncAttributeMaxDynamicSharedMemorySize, SMEM_CRIT);

    k_prep_stats<<<424, 512>>>(Wk, Wv, Wsel, Wsa, Wse, Wc1, s, a);
    k_stats2    <<<1, 640>>>();
    k_front     <<<dim3(B / 64, NAG), 256, SMEM_FRONT>>>(s, a, Bsa, Bse, bv);
    k_attn      <<<dim3((HEADS * B) / 8), 256>>>();
    k_crit      <<<dim3(B / 64, NAG), 256, SMEM_CRIT>>>(a, Bc1, Wc2, Bc2, out);
}

// round 13
// speedup vs baseline: 4.0585x; 1.0832x over previous
#include <cuda_runtime.h>
#include <cuda_fp16.h>
#include <math.h>
#include <stdint.h>

#define FULLMASK 0xffffffffu

constexpr int NAG  = 8;
constexpr int B    = 16384;
constexpr int SD   = 64;
constexpr int AD   = 16;
constexpr int KSA  = 80;
constexpr int HID  = 128;
constexpr int HEADS= 4;
constexpr int D    = 32;
constexpr float EPS = 1e-5f;

// -------- scratch --------
__device__ __align__(16) float g_mean[NAG * KSA];
__device__ __align__(16) float g_rstd[NAG * KSA];
__device__ __align__(16) float g_part [NAG * 16 * KSA];
__device__ __align__(16) float g_partq[NAG * 16 * KSA];
__device__ __align__(16) __half g_se [(size_t)NAG * B * HID];   // fp16 FRAGMENT-ORDER 64-row tiles
__device__ __align__(16) __half g_key[(size_t)NAG * B * HID];   // fp16 row-major
__device__ __align__(16) __half g_val[(size_t)NAG * B * HID];
__device__ __align__(16) __half g_sel[(size_t)NAG * B * HID];
__device__ __align__(16) __half g_oth[(size_t)NAG * B * HID];   // fp16 row-major

// fragment-order fp16 weights
__device__ __align__(16) uint2 pWsa16[NAG][16 * 5 * 32];   // [(n8*5+ksh)*32+lane]
__device__ __align__(16) uint2 pWse16[NAG][16 * 4 * 32];   // [(n8*4+ksh)*32+lane]
__device__ __align__(16) uint2 pWk16 [8 * 16 * 32];        // [(n8*8+ksh)*32+lane]
__device__ __align__(16) uint2 pWv16 [8 * 16 * 32];
__device__ __align__(16) uint2 pWsel16[8 * 16 * 32];
__device__ __align__(16) uint2 pWc116[NAG][16 * 16 * 32];  // [(n8*16+ksh)*32+lane]

__device__ __forceinline__ float lrelu(float x) { return x > 0.f ? x : 0.01f * x; }

// pack (lo,hi) floats -> f16x2 (lo in low half)
__device__ __forceinline__ uint32_t h2(float lo, float hi) {
    uint32_t r; asm("cvt.rn.f16x2.f32 %0, %1, %2;" : "=r"(r) : "f"(hi), "f"(lo)); return r;
}
__device__ __forceinline__ void mma16(float4& d, const uint4 a, const uint2 b) {
    asm volatile(
        "mma.sync.aligned.m16n8k16.row.col.f32.f16.f16.f32 "
        "{%0,%1,%2,%3}, {%4,%5,%6,%7}, {%8,%9}, {%0,%1,%2,%3};"
        : "+f"(d.x), "+f"(d.y), "+f"(d.z), "+f"(d.w)
        : "r"(a.x), "r"(a.y), "r"(a.z), "r"(a.w), "r"(b.x), "r"(b.y));
}
__device__ __forceinline__ void cp16(void* smem_dst, const void* gsrc) {
    uint32_t sa = (uint32_t)__cvta_generic_to_shared(smem_dst);
    asm volatile("cp.async.cg.shared.global [%0], [%1], 16;" :: "r"(sa), "l"(gsrc));
}
#define CP_COMMIT()  asm volatile("cp.async.commit_group;")
#define CP_WAITG(n)  asm volatile("cp.async.wait_group " #n ";" ::: "memory")

// fp16 fragment-order A load (8-ksh tile): one LDS.128
__device__ __forceinline__ uint4 ldfrag16(const uint32_t* A16, int g16, int ksh, int lane) {
    return *(const uint4*)(A16 + (((g16 << 3) + ksh) << 7) + (lane << 2));
}
// store one (mi,j) accumulator's 4 values as fp16 fragment words (8-ksh tile)
__device__ __forceinline__ void st_frag16(uint32_t* A16, int g16, int n8, int tig, int g, float4 v) {
    int C = n8 * 8 + 2 * tig;
    int ksh = C >> 4;
    int co  = C & 15;
    int rego = (co >= 8) ? 2 : 0;
    int lanep = g * 4 + ((co & 7) >> 1);
    uint32_t* base = A16 + ((((g16 << 3) + ksh) << 5) + lanep) * 4;
    base[rego]     = h2(v.x, v.y);   // row R  : cols C,C+1
    base[rego + 1] = h2(v.z, v.w);   // row R+8
}

// ============================================================
// K0: prep (fp16 weight fragments) + BN partial stats, fused
// grid 352 x 512: blocks [0,224) prep, [224,352) stats
// ============================================================
__global__ void __launch_bounds__(512)
k_prep_stats(const float* __restrict__ Wk, const float* __restrict__ Wv,
             const float* __restrict__ Wsel, const float* __restrict__ Wsa,
             const float* __restrict__ Wse, const float* __restrict__ Wc1,
             const float* __restrict__ s, const float* __restrict__ a)
{
    __shared__ float r1[512], r2[512];
    const int tid = threadIdx.x;

    if (blockIdx.x < 224) {
        int i = blockIdx.x * 512 + tid;
        if (i < 12288) {                      // proj fp16: [(n8*8+ksh)*32+lane]
            int which = i >> 12;
            int j = i & 4095;
            int n8 = j >> 8, ksh = (j >> 5) & 7, lane = j & 31;
            int g = lane >> 2, tig = lane & 3;
            int n = n8 * 8 + g, k0 = ksh * 16 + tig * 2;
            const float* W = which == 0 ? Wk : (which == 1 ? Wv : Wsel);
            const float* base = W + (n >> 5) * (HID * D) + (n & 31);
            uint2 v = make_uint2(h2(base[k0 * 32],       base[(k0 + 1) * 32]),
                                 h2(base[(k0 + 8) * 32], base[(k0 + 9) * 32]));
            (which == 0 ? pWk16 : which == 1 ? pWv16 : pWsel16)[j] = v;
            return;
        }
        int i2 = i - 12288;
        if (i2 < NAG * 2560) {                // pWsa16: 5 ksh, K=80
            int n = i2 / 2560, j = i2 % 2560;
            int n8 = j / 160, rem = j % 160;
            int ksh = rem >> 5, lane = rem & 31;
            int g = lane >> 2, tig = lane & 3;
            int nn = n8 * 8 + g, k0 = ksh * 16 + tig * 2;
            const float* W = Wsa + n * KSA * HID;
            pWsa16[n][j] = make_uint2(h2(W[k0 * HID + nn],       W[(k0 + 1) * HID + nn]),
                                      h2(W[(k0 + 8) * HID + nn], W[(k0 + 9) * HID + nn]));
            return;
        }
        int i3 = i2 - NAG * 2560;
        if (i3 < NAG * 2048) {                // pWse16: 4 ksh, K=64
            int n = i3 >> 11, j = i3 & 2047;
            int n8 = j >> 7, ksh = (j >> 5) & 3, lane = j & 31;
            int g = lane >> 2, tig = lane & 3;
            int nn = n8 * 8 + g, k0 = ksh * 16 + tig * 2;
            const float* W = Wse + n * SD * HID;
            pWse16[n][j] = make_uint2(h2(W[k0 * HID + nn],       W[(k0 + 1) * HID + nn]),
                                      h2(W[(k0 + 8) * HID + nn], W[(k0 + 9) * HID + nn]));
            return;
        }
        int i4 = i3 - NAG * 2048;
        if (i4 < NAG * 8192) {                // pWc116: 16 ksh, K=256
            int n = i4 >> 13, j = i4 & 8191;
            int lane = j & 31, ksh = (j >> 5) & 15, n8 = j >> 9;
            int g = lane >> 2, tig = lane & 3;
            int nn = n8 * 8 + g, k0 = ksh * 16 + tig * 2;
            const float* W = Wc1 + (size_t)n * 2 * HID * HID;
            pWc116[n][j] = make_uint2(h2(W[k0 * 128 + nn],       W[(k0 + 1) * 128 + nn]),
                                      h2(W[(k0 + 8) * 128 + nn], W[(k0 + 9) * 128 + nn]));
        }
        return;
    }

    const int bx = blockIdx.x - 224;
    const int n = bx >> 4, chunk = bx & 15;
    const size_t row0 = (size_t)n * B + chunk * 1024;
    float* part  = g_part  + (n * 16 + chunk) * KSA;
    float* partq = g_partq + (n * 16 + chunk) * KSA;

    {
        const int f = tid & 63, r0 = tid >> 6;
        float sum = 0.f, sq = 0.f;
        const float* p = s + (row0 + r0) * SD + f;
        #pragma unroll 4
        for (int st = 0; st < 128; st++) {
            float x = p[(size_t)st * 8 * SD];
            sum += x; sq += x * x;
        }
        r1[tid] = sum; r2[tid] = sq;
        __syncthreads();
        #pragma unroll
        for (int o = 4; o > 0; o >>= 1) {
            if (tid < o * 64) { r1[tid] += r1[tid + o * 64]; r2[tid] += r2[tid + o * 64]; }
            __syncthreads();
        }
        if (tid < 64) { part[tid] = r1[tid]; partq[tid] = r2[tid]; }
        __syncthreads();
    }
    {
        const int f = tid & 15, r0 = tid >> 4;
        float sum = 0.f, sq = 0.f;
        const float* p = a + (row0 + r0) * AD + f;
        #pragma unroll 4
        for (int st = 0; st < 32; st++) {
            float x = p[(size_t)st * 32 * AD];
            sum += x; sq += x * x;
        }
        r1[tid] = sum; r2[tid] = sq;
        __syncthreads();
        #pragma unroll
        for (int o = 16; o > 0; o >>= 1) {
            if (tid < o * 16) { r1[tid] += r1[tid + o * 16]; r2[tid] += r2[tid + o * 16]; }
            __syncthreads();
        }
        if (tid < 16) { part[64 + tid] = r1[tid]; partq[64 + tid] = r2[tid]; }
    }
}

__global__ void k_stats2()
{
    int i = threadIdx.x;
    if (i >= NAG * KSA) return;
    int n = i / KSA, f = i % KSA;
    float sum = 0.f, sq = 0.f;
    for (int c = 0; c < 16; c++) {
        sum += g_part [(n * 16 + c) * KSA + f];
        sq  += g_partq[(n * 16 + c) * KSA + f];
    }
    float m = sum * (1.f / B);
    float v = sq * (1.f / B) - m * m;
    g_mean[i] = m;
    g_rstd[i] = rsqrtf(v + EPS);
}

// ============================================================
// K2: FUSED front, all fp16: enc -> sel -> kv
// ============================================================
constexpr int FR_OFF_AE   = 0;                            // 4*5*32*16 = 10240
constexpr int FR_OFF_A16  = 10240;                        // 4*8*32*16 = 16384
constexpr int FR_OFF_W    = 26624;                        // 73728
constexpr int FR_OFF_MISC = 100352;                       // 544 floats
constexpr int SMEM_FRONT  = 102528;

__global__ void __launch_bounds__(256, 2)
k_front(const float* __restrict__ s, const float* __restrict__ a,
        const float* __restrict__ Bsa, const float* __restrict__ Bse,
        const float* __restrict__ bv)
{
    extern __shared__ char smc[];
    uint32_t* uAe  = (uint32_t*)(smc + FR_OFF_AE);
    uint32_t* uA16 = (uint32_t*)(smc + FR_OFF_A16);
    uint2*    W    = (uint2*)(smc + FR_OFF_W);
    char*     Wc   = smc + FR_OFF_W;
    float*   bsa = (float*)(smc + FR_OFF_MISC);
    float*   bse = bsa + 128;
    float*   bvv = bse + 128;
    float*   mn  = bvv + 128;
    float*   rsd = mn + 80;

    const int n = blockIdx.y, tid = threadIdx.x;
    const size_t gr0 = (size_t)n * B + (size_t)blockIdx.x * 64;

    // prefetch enc weights (fp16): Wsa16 20480B (1280 chunks = 2560 uint2)
    // then Wse16 16384B at uint2 offset 2560
    for (int c = tid; c < 2304; c += 256) {
        const char* src = (c < 1280) ? (const char*)pWsa16[n] + c * 16
                                     : (const char*)pWse16[n] + (c - 1280) * 16;
        cp16(Wc + c * 16, src);
    }
    CP_COMMIT();

    for (int i = tid; i < 128; i += 256) {
        bsa[i] = Bsa[n * HID + i];
        bse[i] = Bse[n * HID + i];
        bvv[i] = bv[i];
    }
    for (int i = tid; i < 80; i += 256) {
        mn[i]  = g_mean[n * KSA + i];
        rsd[i] = g_rstd[n * KSA + i];
    }
    __syncthreads();

    // A fill: BN'd [64 x 80] -> fp16 fragment order (5 ksh)
    for (int i = tid; i < 64 * 20; i += 256) {
        int r = i / 20, c4 = i - r * 20;
        size_t row = gr0 + r;
        float4 v = (c4 < 16) ? ((const float4*)s)[row * 16 + c4]
                             : ((const float4*)a)[row * 4 + (c4 - 16)];
        int C = c4 * 4;
        float f0 = (v.x - mn[C])     * rsd[C];
        float f1 = (v.y - mn[C + 1]) * rsd[C + 1];
        float f2 = (v.z - mn[C + 2]) * rsd[C + 2];
        float f3 = (v.w - mn[C + 3]) * rsd[C + 3];
        int ksh = C >> 4, co = C & 15;
        int g16 = r >> 4, rr = r & 15;
        int comp = (rr >> 3) & 1, gp = rr & 7;
        int tig0 = (co & 7) >> 1;
        uint32_t* base = uAe + (((g16 * 5 + ksh) << 5) + (gp << 2) + tig0) * 4
                         + ((co >= 8) ? 2 : 0) + comp;
        base[0] = h2(f0, f1);
        base[4] = h2(f2, f3);       // tig0+1 -> +4 u32
    }
    CP_WAITG(0);
    __syncthreads();

    const int w = tid >> 5, lane = tid & 31;
    const int rs_ = w & 1, t0 = w >> 1;
    const int g = lane >> 2, tig = lane & 3;

    // ---- Phase 1: enc (fp16, 5 ksh; Wse only first 4) ----
    float4 ae[2][4], as_[2][4];
    #pragma unroll
    for (int mi = 0; mi < 2; mi++)
        #pragma unroll
        for (int j = 0; j < 4; j++) { ae[mi][j] = make_float4(0,0,0,0); as_[mi][j] = make_float4(0,0,0,0); }

    #pragma unroll
    for (int ksh = 0; ksh < 5; ksh++) {
        uint4 fa0 = *(const uint4*)(uAe + (((rs_*2)   * 5 + ksh) << 7) + (lane << 2));
        uint4 fa1 = *(const uint4*)(uAe + (((rs_*2+1) * 5 + ksh) << 7) + (lane << 2));
        #pragma unroll
        for (int j = 0; j < 4; j++) {
            uint2 bb = W[((t0 * 4 + j) * 5 + ksh) * 32 + lane];
            mma16(ae[0][j], fa0, bb); mma16(ae[1][j], fa1, bb);
        }
        if (ksh < 4) {
            #pragma unroll
            for (int j = 0; j < 4; j++) {
                uint2 bb = W[2560 + ((t0 * 4 + j) * 4 + ksh) * 32 + lane];   // FIXED: Wse at uint2 2560
                mma16(as_[0][j], fa0, bb); mma16(as_[1][j], fa1, bb);
            }
        }
    }
    __syncthreads();

    // prefetch Wsel16 (32KB) during epilogue
    for (int c = tid; c < 2048; c += 256) cp16(Wc + c * 16, (const char*)pWsel16 + c * 16);
    CP_COMMIT();

    // bias+lrelu; write g_se (fp16 fragment tile) and A16 = se
    uint32_t* gseT = (uint32_t*)g_se + ((gr0 >> 6) << 12);
    #pragma unroll
    for (int mi = 0; mi < 2; mi++) {
        #pragma unroll
        for (int j = 0; j < 4; j++) {
            int c = t0 * 32 + j * 8 + 2 * tig;
            float b0e = bsa[c], b1e = bsa[c + 1];
            float b0s = bse[c], b1s = bse[c + 1];
            ae[mi][j]  = make_float4(lrelu(ae[mi][j].x + b0e), lrelu(ae[mi][j].y + b1e),
                                     lrelu(ae[mi][j].z + b0e), lrelu(ae[mi][j].w + b1e));
            as_[mi][j] = make_float4(lrelu(as_[mi][j].x + b0s), lrelu(as_[mi][j].y + b1s),
                                     lrelu(as_[mi][j].z + b0s), lrelu(as_[mi][j].w + b1s));
            st_frag16(uA16, rs_ * 2 + mi, t0 * 4 + j, tig, g, as_[mi][j]);
            st_frag16(gseT, rs_ * 2 + mi, t0 * 4 + j, tig, g, as_[mi][j]);
        }
    }
    CP_WAITG(0);
    __syncthreads();

    // ---- Phase 2: sel (fp16) ----
    float4 ac[2][4], acv[2][4];
    #pragma unroll
    for (int mi = 0; mi < 2; mi++)
        #pragma unroll
        for (int j = 0; j < 4; j++) ac[mi][j] = make_float4(0,0,0,0);

    #pragma unroll
    for (int ksh = 0; ksh < 8; ksh++) {
        uint4 fa0 = ldfrag16(uA16, rs_ * 2,     ksh, lane);
        uint4 fa1 = ldfrag16(uA16, rs_ * 2 + 1, ksh, lane);
        #pragma unroll
        for (int j = 0; j < 4; j++) {
            uint2 bb = W[((t0 * 4 + j) * 8 + ksh) * 32 + lane];
            mma16(ac[0][j], fa0, bb); mma16(ac[1][j], fa1, bb);
        }
    }
    __syncthreads();    // sel weights + A16(se) fully read

    // prefetch Wk16 -> W[0..4095], Wv16 -> W[4096..8191]
    for (int c = tid; c < 4096; c += 256) {
        const char* src = (c < 2048) ? (const char*)pWk16 + c * 16
                                     : (const char*)pWv16 + (c - 2048) * 16;
        cp16(Wc + c * 16, src);
    }
    CP_COMMIT();

    // sel epilogue: g_sel fp16 row-major; restage A16 = e
    #pragma unroll
    for (int mi = 0; mi < 2; mi++) {
        #pragma unroll
        for (int j = 0; j < 4; j++) {
            int c = t0 * 32 + j * 8 + 2 * tig;
            size_t gr = gr0 + rs_ * 32 + mi * 16 + g;
            *(uint32_t*)&g_sel[gr * 128 + c]       = h2(ac[mi][j].x, ac[mi][j].y);
            *(uint32_t*)&g_sel[(gr + 8) * 128 + c] = h2(ac[mi][j].z, ac[mi][j].w);
            st_frag16(uA16, rs_ * 2 + mi, t0 * 4 + j, tig, g, ae[mi][j]);
        }
    }
    CP_WAITG(0);
    __syncthreads();

    // ---- Phase 3: key + val ----
    #pragma unroll
    for (int mi = 0; mi < 2; mi++)
        #pragma unroll
        for (int j = 0; j < 4; j++) { ac[mi][j] = make_float4(0,0,0,0); acv[mi][j] = make_float4(0,0,0,0); }

    #pragma unroll
    for (int ksh = 0; ksh < 8; ksh++) {
        uint4 fa0 = ldfrag16(uA16, rs_ * 2,     ksh, lane);
        uint4 fa1 = ldfrag16(uA16, rs_ * 2 + 1, ksh, lane);
        #pragma unroll
        for (int j = 0; j < 4; j++) {
            int bi = ((t0 * 4 + j) * 8 + ksh) * 32 + lane;
            uint2 bk = W[bi], bw = W[4096 + bi];
            mma16(ac[0][j],  fa0, bk); mma16(ac[1][j],  fa1, bk);
            mma16(acv[0][j], fa0, bw); mma16(acv[1][j], fa1, bw);
        }
    }

    #pragma unroll
    for (int mi = 0; mi < 2; mi++) {
        #pragma unroll
        for (int j = 0; j < 4; j++) {
            size_t gr = gr0 + rs_ * 32 + mi * 16 + g;
            int c = t0 * 32 + j * 8 + 2 * tig;
            *(uint32_t*)&g_key[gr * 128 + c]       = h2(ac[mi][j].x, ac[mi][j].y);
            *(uint32_t*)&g_key[(gr + 8) * 128 + c] = h2(ac[mi][j].z, ac[mi][j].w);
            float bb0 = bvv[c], bb1 = bvv[c + 1];
            *(uint32_t*)&g_val[gr * 128 + c]       = h2(lrelu(acv[mi][j].x + bb0), lrelu(acv[mi][j].y + bb1));
            *(uint32_t*)&g_val[(gr + 8) * 128 + c] = h2(lrelu(acv[mi][j].z + bb0), lrelu(acv[mi][j].w + bb1));
        }
    }
}

// ============================================================
// K3: attention — fp16 inputs/outputs, fp32 math
// ============================================================
constexpr int ASTR = 36;
__global__ void __launch_bounds__(256, 4)
k_attn()
{
    __shared__ float smem[8][3 * 8 * ASTR + 64];
    const int tid = threadIdx.x, warp = tid >> 5, lane = tid & 31;
    const int gid = blockIdx.x * 8 + warp;
    const int b = gid >> 2;
    const int p = gid & 3;

    float* selS = smem[warp];
    float* keyS = selS + 8 * ASTR;
    float* valS = keyS + 8 * ASTR;
    float* wS   = valS + 8 * ASTR;
    const float scale = 0.17677669529663687f;

    #pragma unroll
    for (int it = 0; it < 3; it++) {
        int idx = it * 32 + lane;
        int seg = idx >> 2, q4 = idx & 3;
        int arr = seg >> 3, i = seg & 7;
        const __half* gsrc = (arr == 0) ? g_sel : (arr == 1) ? g_key : g_val;
        uint4 v = *(const uint4*)(gsrc + ((size_t)i * B + b) * HID + p * D + q4 * 8);
        const __half2* hp = (const __half2*)&v;
        float* dst = selS + arr * (8 * ASTR) + i * ASTR + q4 * 8;
        #pragma unroll
        for (int q = 0; q < 4; q++) {
            float2 f = __half22float2(hp[q]);
            dst[q * 2] = f.x; dst[q * 2 + 1] = f.y;
        }
    }
    __syncwarp();

    const int i0 = lane >> 3, j = lane & 7, i1 = i0 + 4;
    float acc0 = 0.f, acc1 = 0.f;
    #pragma unroll
    for (int d = 0; d < 32; d++) {
        float kv = keyS[j * ASTR + d];
        acc0 += selS[i0 * ASTR + d] * kv;
        acc1 += selS[i1 * ASTR + d] * kv;
    }
    acc0 *= scale; acc1 *= scale;
    if (i0 == j) acc0 = -1e9f;
    if (i1 == j) acc1 = -1e9f;

    float m0 = acc0, m1 = acc1;
    #pragma unroll
    for (int o = 1; o < 8; o <<= 1) {
        m0 = fmaxf(m0, __shfl_xor_sync(FULLMASK, m0, o));
        m1 = fmaxf(m1, __shfl_xor_sync(FULLMASK, m1, o));
    }
    float e0 = __expf(acc0 - m0), e1 = __expf(acc1 - m1);
    float s0 = e0, s1 = e1;
    #pragma unroll
    for (int o = 1; o < 8; o <<= 1) {
        s0 += __shfl_xor_sync(FULLMASK, s0, o);
        s1 += __shfl_xor_sync(FULLMASK, s1, o);
    }
    wS[lane]      = __fdividef(e0, s0);
    wS[lane + 32] = __fdividef(e1, s1);
    __syncwarp();

    float out[8];
    #pragma unroll
    for (int ii = 0; ii < 8; ii++) out[ii] = 0.f;
    #pragma unroll
    for (int jj = 0; jj < 8; jj++) {
        float v = valS[jj * ASTR + lane];
        #pragma unroll
        for (int ii = 0; ii < 8; ii++) out[ii] += wS[ii * 8 + jj] * v;
    }
    #pragma unroll
    for (int ii = 0; ii < 8; ii++)
        g_oth[((size_t)ii * B + b) * HID + p * D + lane] = __float2half_rn(out[ii]);
}

// ============================================================
// K4: critic fp16 — everything staged up front, single mma sweep
// A region: se frag tile [0,16384) + oth rows [16384, 33792)
// ============================================================
constexpr int HSTR   = 132;   // f32 h stride
constexpr int OSTRU  = 68;    // ph1 A row stride in u32 (136 halves)
constexpr int CR_OFF_A   = 0;                             // 33792 (h reuses whole region)
constexpr int CR_OFF_B1  = 33792;                         // 2 x 32768
constexpr int CR_OFF_W2  = 99328;                         // 8448
constexpr int CR_OFF_B1S = 107776;
constexpr int CR_OFF_B2S = 108288;
constexpr int CR_OFF_AMX = 108352;
constexpr int SMEM_CRIT  = 108608;

__device__ __forceinline__ void crit_stageW16(uint2* B1, int buf, int ph, int n, int tid) {
    const uint2* base = pWc116[n];
    for (int cc = tid; cc < 2048; cc += 256) {
        int lanepair = cc & 15, ksl = (cc >> 4) & 7, n8 = cc >> 7;
        cp16(B1 + buf + (n8 * 8 + ksl) * 32 + lanepair * 2,
             base + ((n8 * 16 + ph * 8 + ksl) * 32 + lanepair * 2));
    }
}

__global__ void __launch_bounds__(256, 2)
k_crit(const float* __restrict__ a,
       const float* __restrict__ Bc1,
       const float* __restrict__ Wc2, const float* __restrict__ Bc2,
       float* __restrict__ out)
{
    extern __shared__ char smc[];
    uint32_t* uA = (uint32_t*)(smc + CR_OFF_A);
    uint32_t* uAo = uA + 4096;                 // oth rows region
    uint2*    B1 = (uint2*)(smc + CR_OFF_B1);
    float*    h  = (float*)(smc + CR_OFF_A);
    float*   w2t = (float*)(smc + CR_OFF_W2);
    float*   b1s = (float*)(smc + CR_OFF_B1S);
    float*   b2s = (float*)(smc + CR_OFF_B2S);
    int*     amx = (int*)(smc + CR_OFF_AMX);

    const int n = blockIdx.y, tid = threadIdx.x;
    const int w = tid >> 5, lane = tid & 31;
    const size_t row0 = (size_t)n * B + (size_t)blockIdx.x * 64;

    // stage EVERYTHING up front
    crit_stageW16(B1, 0, 0, n, tid);
    crit_stageW16(B1, 4096, 1, n, tid);
    {
        const uint32_t* gseT = (const uint32_t*)g_se + ((row0 >> 6) << 12);
        for (int i = tid; i < 1024; i += 256) cp16(uA + i * 4, gseT + i * 4);
    }
    for (int i = tid; i < 1024; i += 256) {
        int r = i >> 4, c = i & 15;
        cp16(uAo + r * OSTRU + c * 4,
             (const uint32_t*)g_oth + (row0 + r) * 64 + c * 4);
    }
    CP_COMMIT();

    // small fills overlap the async copies
    for (int i = tid; i < HID * AD; i += 256) {
        int k = i >> 4, o = i & 15;
        w2t[o * HSTR + k] = Wc2[n * HID * AD + k * AD + o];
    }
    if (tid < HID) b1s[tid] = Bc1[n * HID + tid];
    if (tid >= HID && tid < HID + AD) b2s[tid - HID] = Bc2[n * AD + (tid - HID)];
    if (tid < 64) {
        const float4* ap = (const float4*)(a + (row0 + tid) * AD);
        float4 q0 = ap[0], q1 = ap[1], q2 = ap[2], q3 = ap[3];
        float vals[16] = {q0.x,q0.y,q0.z,q0.w, q1.x,q1.y,q1.z,q1.w,
                          q2.x,q2.y,q2.z,q2.w, q3.x,q3.y,q3.z,q3.w};
        int bi = 0; float bvv = vals[0];
        #pragma unroll
        for (int i = 1; i < 16; i++) if (vals[i] > bvv) { bvv = vals[i]; bi = i; }
        amx[tid] = bi;
    }

    const int rs_ = w & 1, cq = w >> 1;
    const int g = lane >> 2, tig = lane & 3;

    float4 acc[2][4];
    #pragma unroll
    for (int mi = 0; mi < 2; mi++)
        #pragma unroll
        for (int j = 0; j < 4; j++) acc[mi][j] = make_float4(0,0,0,0);

    CP_WAITG(0);
    __syncthreads();

    // ---- ph0: se (fragment-order fp16) ----
    #pragma unroll
    for (int ksl = 0; ksl < 8; ksl++) {
        uint4 fa0 = ldfrag16(uA, rs_ * 2,     ksl, lane);
        uint4 fa1 = ldfrag16(uA, rs_ * 2 + 1, ksl, lane);
        #pragma unroll
        for (int j = 0; j < 4; j++) {
            uint2 bb = B1[((cq * 4 + j) * 8 + ksl) * 32 + lane];
            mma16(acc[0][j], fa0, bb); mma16(acc[1][j], fa1, bb);
        }
    }
    // ---- ph1: oth (row-major fp16) ----
    const int R0 = rs_ * 32 + g;
    #pragma unroll
    for (int ksl = 0; ksl < 8; ksl++) {
        uint4 fa0, fa1;
        {
            const uint32_t* b0 = uAo + R0 * OSTRU + ksl * 8 + tig;
            fa0 = make_uint4(b0[0], b0[8 * OSTRU], b0[4], b0[8 * OSTRU + 4]);
            const uint32_t* b1 = b0 + 16 * OSTRU;
            fa1 = make_uint4(b1[0], b1[8 * OSTRU], b1[4], b1[8 * OSTRU + 4]);
        }
        #pragma unroll
        for (int j = 0; j < 4; j++) {
            uint2 bb = B1[4096 + ((cq * 4 + j) * 8 + ksl) * 32 + lane];
            mma16(acc[0][j], fa0, bb); mma16(acc[1][j], fa1, bb);
        }
    }
    __syncthreads();        // all A reads done before h overwrites uA

    #pragma unroll
    for (int mi = 0; mi < 2; mi++) {
        #pragma unroll
        for (int j = 0; j < 4; j++) {
            int r = rs_ * 32 + mi * 16 + g;
            int c = cq * 32 + j * 8 + 2 * tig;
            float bb0 = b1s[c], bb1 = b1s[c + 1];
            h[r * HSTR + c]           = lrelu(acc[mi][j].x + bb0);
            h[r * HSTR + c + 1]       = lrelu(acc[mi][j].y + bb1);
            h[(r + 8) * HSTR + c]     = lrelu(acc[mi][j].z + bb0);
            h[(r + 8) * HSTR + c + 1] = lrelu(acc[mi][j].w + bb1);
        }
    }
    __syncthreads();

    const int o = lane & 15, half = lane >> 4;
    #pragma unroll
    for (int rr = 0; rr < 8; rr++) {
        const int r = w * 8 + rr;
        const int bidx = blockIdx.x * 64 + r;
        const float4* hr4 = (const float4*)(h + r * HSTR + half * 64);
        const float4* w4  = (const float4*)(w2t + o * HSTR + half * 64);
        float q = 0.f;
        #pragma unroll
        for (int i = 0; i < 16; i++) {
            float4 hv = hr4[i], wv = w4[i];
            q += hv.x * wv.x + hv.y * wv.y + hv.z * wv.z + hv.w * wv.w;
        }
        q += __shfl_xor_sync(FULLMASK, q, 16);
        q += b2s[o];

        float qsel = __shfl_sync(FULLMASK, q, amx[r]);
        if (lane == 0) out[(size_t)n * B + bidx] = qsel;
    }
}

// ============================================================
extern "C" void kernel_launch(void* const* d_in, const int* in_sizes, int n_in,
                              void* d_out, int out_size)
{
    const float* s    = (const float*)d_in[0];
    const float* a    = (const float*)d_in[1];
    const float* Wsa  = (const float*)d_in[2];
    const float* Bsa  = (const float*)d_in[3];
    const float* Wse  = (const float*)d_in[4];
    const float* Bse  = (const float*)d_in[5];
    const float* Wk   = (const float*)d_in[6];
    const float* Wsel = (const float*)d_in[7];
    const float* Wv   = (const float*)d_in[8];
    const float* bv   = (const float*)d_in[9];
    const float* Wc1  = (const float*)d_in[10];
    const float* Bc1  = (const float*)d_in[11];
    const float* Wc2  = (const float*)d_in[12];
    const float* Bc2  = (const float*)d_in[13];
    float* out = (float*)d_out;

    cudaFuncSetAttribute(k_front, cudaFuncAttributeMaxDynamicSharedMemorySize, SMEM_FRONT);
    cudaFuncSetAttribute(k_crit,  cudaFuncAttributeMaxDynamicSharedMemorySize, SMEM_CRIT);

    k_prep_stats<<<352, 512>>>(Wk, Wv, Wsel, Wsa, Wse, Wc1, s, a);
    k_stats2    <<<1, 640>>>();
    k_front     <<<dim3(B / 64, NAG), 256, SMEM_FRONT>>>(s, a, Bsa, Bse, bv);
    k_attn      <<<dim3((HEADS * B) / 8), 256>>>();
    k_crit      <<<dim3(B / 64, NAG), 256, SMEM_CRIT>>>(a, Bc1, Wc2, Bc2, out);
}

// round 14
// speedup vs baseline: 4.1010x; 1.0105x over previous
#include <cuda_runtime.h>
#include <cuda_fp16.h>
#include <math.h>
#include <stdint.h>

#define FULLMASK 0xffffffffu

constexpr int NAG  = 8;
constexpr int B    = 16384;
constexpr int SD   = 64;
constexpr int AD   = 16;
constexpr int KSA  = 80;
constexpr int HID  = 128;
constexpr int HEADS= 4;
constexpr int D    = 32;
constexpr float EPS = 1e-5f;

// -------- scratch --------
__device__ __align__(16) float g_part [NAG * 16 * KSA];
__device__ __align__(16) float g_partq[NAG * 16 * KSA];
__device__ __align__(16) __half g_se [(size_t)NAG * B * HID];   // fp16 FRAGMENT-ORDER 64-row tiles
__device__ __align__(16) __half g_key[(size_t)NAG * B * HID];   // fp16 row-major
__device__ __align__(16) __half g_val[(size_t)NAG * B * HID];
__device__ __align__(16) __half g_sel[(size_t)NAG * B * HID];
__device__ __align__(16) __half g_oth[(size_t)NAG * B * HID];   // fp16 row-major

// fragment-order fp16 weights
__device__ __align__(16) uint2 pWsa16[NAG][16 * 5 * 32];   // [(n8*5+ksh)*32+lane]
__device__ __align__(16) uint2 pWse16[NAG][16 * 4 * 32];   // [(n8*4+ksh)*32+lane]
__device__ __align__(16) uint2 pWk16 [8 * 16 * 32];        // [(n8*8+ksh)*32+lane]
__device__ __align__(16) uint2 pWv16 [8 * 16 * 32];
__device__ __align__(16) uint2 pWsel16[8 * 16 * 32];
__device__ __align__(16) uint2 pWc116[NAG][16 * 16 * 32];  // [(n8*16+ksh)*32+lane]

__device__ __forceinline__ float lrelu(float x) { return x > 0.f ? x : 0.01f * x; }

// pack (lo,hi) floats -> f16x2 (lo in low half)
__device__ __forceinline__ uint32_t h2(float lo, float hi) {
    uint32_t r; asm("cvt.rn.f16x2.f32 %0, %1, %2;" : "=r"(r) : "f"(hi), "f"(lo)); return r;
}
__device__ __forceinline__ void mma16(float4& d, const uint4 a, const uint2 b) {
    asm volatile(
        "mma.sync.aligned.m16n8k16.row.col.f32.f16.f16.f32 "
        "{%0,%1,%2,%3}, {%4,%5,%6,%7}, {%8,%9}, {%0,%1,%2,%3};"
        : "+f"(d.x), "+f"(d.y), "+f"(d.z), "+f"(d.w)
        : "r"(a.x), "r"(a.y), "r"(a.z), "r"(a.w), "r"(b.x), "r"(b.y));
}
__device__ __forceinline__ void cp16(void* smem_dst, const void* gsrc) {
    uint32_t sa = (uint32_t)__cvta_generic_to_shared(smem_dst);
    asm volatile("cp.async.cg.shared.global [%0], [%1], 16;" :: "r"(sa), "l"(gsrc));
}
#define CP_COMMIT()  asm volatile("cp.async.commit_group;")
#define CP_WAITG(n)  asm volatile("cp.async.wait_group " #n ";" ::: "memory")

// fp16 fragment-order A load (8-ksh tile): one LDS.128
__device__ __forceinline__ uint4 ldfrag16(const uint32_t* A16, int g16, int ksh, int lane) {
    return *(const uint4*)(A16 + (((g16 << 3) + ksh) << 7) + (lane << 2));
}
// store one (mi,j) accumulator's 4 values as fp16 fragment words (8-ksh tile)
__device__ __forceinline__ void st_frag16(uint32_t* A16, int g16, int n8, int tig, int g, float4 v) {
    int C = n8 * 8 + 2 * tig;
    int ksh = C >> 4;
    int co  = C & 15;
    int rego = (co >= 8) ? 2 : 0;
    int lanep = g * 4 + ((co & 7) >> 1);
    uint32_t* base = A16 + ((((g16 << 3) + ksh) << 5) + lanep) * 4;
    base[rego]     = h2(v.x, v.y);   // row R  : cols C,C+1
    base[rego + 1] = h2(v.z, v.w);   // row R+8
}

// ============================================================
// K0: prep (fp16 weight fragments) + BN partial stats, fused
// grid 352 x 512: blocks [0,224) prep, [224,352) stats
// ============================================================
__global__ void __launch_bounds__(512)
k_prep_stats(const float* __restrict__ Wk, const float* __restrict__ Wv,
             const float* __restrict__ Wsel, const float* __restrict__ Wsa,
             const float* __restrict__ Wse, const float* __restrict__ Wc1,
             const float* __restrict__ s, const float* __restrict__ a)
{
    __shared__ float r1[512], r2[512];
    const int tid = threadIdx.x;

    if (blockIdx.x < 224) {
        int i = blockIdx.x * 512 + tid;
        if (i < 12288) {                      // proj fp16: [(n8*8+ksh)*32+lane]
            int which = i >> 12;
            int j = i & 4095;
            int n8 = j >> 8, ksh = (j >> 5) & 7, lane = j & 31;
            int g = lane >> 2, tig = lane & 3;
            int n = n8 * 8 + g, k0 = ksh * 16 + tig * 2;
            const float* W = which == 0 ? Wk : (which == 1 ? Wv : Wsel);
            const float* base = W + (n >> 5) * (HID * D) + (n & 31);
            uint2 v = make_uint2(h2(base[k0 * 32],       base[(k0 + 1) * 32]),
                                 h2(base[(k0 + 8) * 32], base[(k0 + 9) * 32]));
            (which == 0 ? pWk16 : which == 1 ? pWv16 : pWsel16)[j] = v;
            return;
        }
        int i2 = i - 12288;
        if (i2 < NAG * 2560) {                // pWsa16: 5 ksh, K=80
            int n = i2 / 2560, j = i2 % 2560;
            int n8 = j / 160, rem = j % 160;
            int ksh = rem >> 5, lane = rem & 31;
            int g = lane >> 2, tig = lane & 3;
            int nn = n8 * 8 + g, k0 = ksh * 16 + tig * 2;
            const float* W = Wsa + n * KSA * HID;
            pWsa16[n][j] = make_uint2(h2(W[k0 * HID + nn],       W[(k0 + 1) * HID + nn]),
                                      h2(W[(k0 + 8) * HID + nn], W[(k0 + 9) * HID + nn]));
            return;
        }
        int i3 = i2 - NAG * 2560;
        if (i3 < NAG * 2048) {                // pWse16: 4 ksh, K=64
            int n = i3 >> 11, j = i3 & 2047;
            int n8 = j >> 7, ksh = (j >> 5) & 3, lane = j & 31;
            int g = lane >> 2, tig = lane & 3;
            int nn = n8 * 8 + g, k0 = ksh * 16 + tig * 2;
            const float* W = Wse + n * SD * HID;
            pWse16[n][j] = make_uint2(h2(W[k0 * HID + nn],       W[(k0 + 1) * HID + nn]),
                                      h2(W[(k0 + 8) * HID + nn], W[(k0 + 9) * HID + nn]));
            return;
        }
        int i4 = i3 - NAG * 2048;
        if (i4 < NAG * 8192) {                // pWc116: 16 ksh, K=256
            int n = i4 >> 13, j = i4 & 8191;
            int lane = j & 31, ksh = (j >> 5) & 15, n8 = j >> 9;
            int g = lane >> 2, tig = lane & 3;
            int nn = n8 * 8 + g, k0 = ksh * 16 + tig * 2;
            const float* W = Wc1 + (size_t)n * 2 * HID * HID;
            pWc116[n][j] = make_uint2(h2(W[k0 * 128 + nn],       W[(k0 + 1) * 128 + nn]),
                                      h2(W[(k0 + 8) * 128 + nn], W[(k0 + 9) * 128 + nn]));
        }
        return;
    }

    const int bx = blockIdx.x - 224;
    const int n = bx >> 4, chunk = bx & 15;
    const size_t row0 = (size_t)n * B + chunk * 1024;
    float* part  = g_part  + (n * 16 + chunk) * KSA;
    float* partq = g_partq + (n * 16 + chunk) * KSA;

    {
        const int f = tid & 63, r0 = tid >> 6;
        float sum = 0.f, sq = 0.f;
        const float* p = s + (row0 + r0) * SD + f;
        #pragma unroll 4
        for (int st = 0; st < 128; st++) {
            float x = p[(size_t)st * 8 * SD];
            sum += x; sq += x * x;
        }
        r1[tid] = sum; r2[tid] = sq;
        __syncthreads();
        #pragma unroll
        for (int o = 4; o > 0; o >>= 1) {
            if (tid < o * 64) { r1[tid] += r1[tid + o * 64]; r2[tid] += r2[tid + o * 64]; }
            __syncthreads();
        }
        if (tid < 64) { part[tid] = r1[tid]; partq[tid] = r2[tid]; }
        __syncthreads();
    }
    {
        const int f = tid & 15, r0 = tid >> 4;
        float sum = 0.f, sq = 0.f;
        const float* p = a + (row0 + r0) * AD + f;
        #pragma unroll 4
        for (int st = 0; st < 32; st++) {
            float x = p[(size_t)st * 32 * AD];
            sum += x; sq += x * x;
        }
        r1[tid] = sum; r2[tid] = sq;
        __syncthreads();
        #pragma unroll
        for (int o = 16; o > 0; o >>= 1) {
            if (tid < o * 16) { r1[tid] += r1[tid + o * 16]; r2[tid] += r2[tid + o * 16]; }
            __syncthreads();
        }
        if (tid < 16) { part[64 + tid] = r1[tid]; partq[64 + tid] = r2[tid]; }
    }
}

// ============================================================
// K2: FUSED front, all fp16: enc -> sel -> kv
// (BN final reduction inlined; k_stats2 eliminated)
// ============================================================
constexpr int FR_OFF_AE   = 0;                            // 4*5*32*16 = 10240
constexpr int FR_OFF_A16  = 10240;                        // 4*8*32*16 = 16384
constexpr int FR_OFF_W    = 26624;                        // 73728
constexpr int FR_OFF_MISC = 100352;                       // 544 floats
constexpr int SMEM_FRONT  = 102528;

__global__ void __launch_bounds__(256, 2)
k_front(const float* __restrict__ s, const float* __restrict__ a,
        const float* __restrict__ Bsa, const float* __restrict__ Bse,
        const float* __restrict__ bv)
{
    extern __shared__ char smc[];
    uint32_t* uAe  = (uint32_t*)(smc + FR_OFF_AE);
    uint32_t* uA16 = (uint32_t*)(smc + FR_OFF_A16);
    uint2*    W    = (uint2*)(smc + FR_OFF_W);
    char*     Wc   = smc + FR_OFF_W;
    float*   bsa = (float*)(smc + FR_OFF_MISC);
    float*   bse = bsa + 128;
    float*   bvv = bse + 128;
    float*   mn  = bvv + 128;
    float*   rsd = mn + 80;

    const int n = blockIdx.y, tid = threadIdx.x;
    const size_t gr0 = (size_t)n * B + (size_t)blockIdx.x * 64;

    // prefetch enc weights (fp16): Wsa16 20480B (=2560 uint2), Wse16 at uint2 2560
    for (int c = tid; c < 2304; c += 256) {
        const char* src = (c < 1280) ? (const char*)pWsa16[n] + c * 16
                                     : (const char*)pWse16[n] + (c - 1280) * 16;
        cp16(Wc + c * 16, src);
    }
    CP_COMMIT();

    for (int i = tid; i < 128; i += 256) {
        bsa[i] = Bsa[n * HID + i];
        bse[i] = Bse[n * HID + i];
        bvv[i] = bv[i];
    }
    // inline BN final reduction (same order as old k_stats2)
    for (int i = tid; i < 80; i += 256) {
        float sum = 0.f, sq = 0.f;
        #pragma unroll
        for (int c = 0; c < 16; c++) {
            sum += g_part [(n * 16 + c) * KSA + i];
            sq  += g_partq[(n * 16 + c) * KSA + i];
        }
        float m = sum * (1.f / B);
        mn[i]  = m;
        rsd[i] = rsqrtf(sq * (1.f / B) - m * m + EPS);
    }
    __syncthreads();

    // A fill: BN'd [64 x 80] -> fp16 fragment order (5 ksh)
    for (int i = tid; i < 64 * 20; i += 256) {
        int r = i / 20, c4 = i - r * 20;
        size_t row = gr0 + r;
        float4 v = (c4 < 16) ? ((const float4*)s)[row * 16 + c4]
                             : ((const float4*)a)[row * 4 + (c4 - 16)];
        int C = c4 * 4;
        float f0 = (v.x - mn[C])     * rsd[C];
        float f1 = (v.y - mn[C + 1]) * rsd[C + 1];
        float f2 = (v.z - mn[C + 2]) * rsd[C + 2];
        float f3 = (v.w - mn[C + 3]) * rsd[C + 3];
        int ksh = C >> 4, co = C & 15;
        int g16 = r >> 4, rr = r & 15;
        int comp = (rr >> 3) & 1, gp = rr & 7;
        int tig0 = (co & 7) >> 1;
        uint32_t* base = uAe + (((g16 * 5 + ksh) << 5) + (gp << 2) + tig0) * 4
                         + ((co >= 8) ? 2 : 0) + comp;
        base[0] = h2(f0, f1);
        base[4] = h2(f2, f3);
    }
    CP_WAITG(0);
    __syncthreads();

    const int w = tid >> 5, lane = tid & 31;
    const int rs_ = w & 1, t0 = w >> 1;
    const int g = lane >> 2, tig = lane & 3;

    // ---- Phase 1: enc (fp16, 5 ksh; Wse only first 4) ----
    float4 ae[2][4], as_[2][4];
    #pragma unroll
    for (int mi = 0; mi < 2; mi++)
        #pragma unroll
        for (int j = 0; j < 4; j++) { ae[mi][j] = make_float4(0,0,0,0); as_[mi][j] = make_float4(0,0,0,0); }

    #pragma unroll
    for (int ksh = 0; ksh < 5; ksh++) {
        uint4 fa0 = *(const uint4*)(uAe + (((rs_*2)   * 5 + ksh) << 7) + (lane << 2));
        uint4 fa1 = *(const uint4*)(uAe + (((rs_*2+1) * 5 + ksh) << 7) + (lane << 2));
        #pragma unroll
        for (int j = 0; j < 4; j++) {
            uint2 bb = W[((t0 * 4 + j) * 5 + ksh) * 32 + lane];
            mma16(ae[0][j], fa0, bb); mma16(ae[1][j], fa1, bb);
        }
        if (ksh < 4) {
            #pragma unroll
            for (int j = 0; j < 4; j++) {
                uint2 bb = W[2560 + ((t0 * 4 + j) * 4 + ksh) * 32 + lane];
                mma16(as_[0][j], fa0, bb); mma16(as_[1][j], fa1, bb);
            }
        }
    }
    __syncthreads();

    // prefetch Wsel16 (32KB) during epilogue
    for (int c = tid; c < 2048; c += 256) cp16(Wc + c * 16, (const char*)pWsel16 + c * 16);
    CP_COMMIT();

    // bias+lrelu; write g_se (fp16 fragment tile) and A16 = se
    uint32_t* gseT = (uint32_t*)g_se + ((gr0 >> 6) << 12);
    #pragma unroll
    for (int mi = 0; mi < 2; mi++) {
        #pragma unroll
        for (int j = 0; j < 4; j++) {
            int c = t0 * 32 + j * 8 + 2 * tig;
            float b0e = bsa[c], b1e = bsa[c + 1];
            float b0s = bse[c], b1s = bse[c + 1];
            ae[mi][j]  = make_float4(lrelu(ae[mi][j].x + b0e), lrelu(ae[mi][j].y + b1e),
                                     lrelu(ae[mi][j].z + b0e), lrelu(ae[mi][j].w + b1e));
            as_[mi][j] = make_float4(lrelu(as_[mi][j].x + b0s), lrelu(as_[mi][j].y + b1s),
                                     lrelu(as_[mi][j].z + b0s), lrelu(as_[mi][j].w + b1s));
            st_frag16(uA16, rs_ * 2 + mi, t0 * 4 + j, tig, g, as_[mi][j]);
            st_frag16(gseT, rs_ * 2 + mi, t0 * 4 + j, tig, g, as_[mi][j]);
        }
    }
    CP_WAITG(0);
    __syncthreads();

    // ---- Phase 2: sel (fp16) ----
    float4 ac[2][4], acv[2][4];
    #pragma unroll
    for (int mi = 0; mi < 2; mi++)
        #pragma unroll
        for (int j = 0; j < 4; j++) ac[mi][j] = make_float4(0,0,0,0);

    #pragma unroll
    for (int ksh = 0; ksh < 8; ksh++) {
        uint4 fa0 = ldfrag16(uA16, rs_ * 2,     ksh, lane);
        uint4 fa1 = ldfrag16(uA16, rs_ * 2 + 1, ksh, lane);
        #pragma unroll
        for (int j = 0; j < 4; j++) {
            uint2 bb = W[((t0 * 4 + j) * 8 + ksh) * 32 + lane];
            mma16(ac[0][j], fa0, bb); mma16(ac[1][j], fa1, bb);
        }
    }
    __syncthreads();    // sel weights + A16(se) fully read

    // prefetch Wk16 -> W[0..4095], Wv16 -> W[4096..8191]
    for (int c = tid; c < 4096; c += 256) {
        const char* src = (c < 2048) ? (const char*)pWk16 + c * 16
                                     : (const char*)pWv16 + (c - 2048) * 16;
        cp16(Wc + c * 16, src);
    }
    CP_COMMIT();

    // sel epilogue: g_sel fp16 row-major; restage A16 = e
    #pragma unroll
    for (int mi = 0; mi < 2; mi++) {
        #pragma unroll
        for (int j = 0; j < 4; j++) {
            int c = t0 * 32 + j * 8 + 2 * tig;
            size_t gr = gr0 + rs_ * 32 + mi * 16 + g;
            *(uint32_t*)&g_sel[gr * 128 + c]       = h2(ac[mi][j].x, ac[mi][j].y);
            *(uint32_t*)&g_sel[(gr + 8) * 128 + c] = h2(ac[mi][j].z, ac[mi][j].w);
            st_frag16(uA16, rs_ * 2 + mi, t0 * 4 + j, tig, g, ae[mi][j]);
        }
    }
    CP_WAITG(0);
    __syncthreads();

    // ---- Phase 3: key + val ----
    #pragma unroll
    for (int mi = 0; mi < 2; mi++)
        #pragma unroll
        for (int j = 0; j < 4; j++) { ac[mi][j] = make_float4(0,0,0,0); acv[mi][j] = make_float4(0,0,0,0); }

    #pragma unroll
    for (int ksh = 0; ksh < 8; ksh++) {
        uint4 fa0 = ldfrag16(uA16, rs_ * 2,     ksh, lane);
        uint4 fa1 = ldfrag16(uA16, rs_ * 2 + 1, ksh, lane);
        #pragma unroll
        for (int j = 0; j < 4; j++) {
            int bi = ((t0 * 4 + j) * 8 + ksh) * 32 + lane;
            uint2 bk = W[bi], bw = W[4096 + bi];
            mma16(ac[0][j],  fa0, bk); mma16(ac[1][j],  fa1, bk);
            mma16(acv[0][j], fa0, bw); mma16(acv[1][j], fa1, bw);
        }
    }

    #pragma unroll
    for (int mi = 0; mi < 2; mi++) {
        #pragma unroll
        for (int j = 0; j < 4; j++) {
            size_t gr = gr0 + rs_ * 32 + mi * 16 + g;
            int c = t0 * 32 + j * 8 + 2 * tig;
            *(uint32_t*)&g_key[gr * 128 + c]       = h2(ac[mi][j].x, ac[mi][j].y);
            *(uint32_t*)&g_key[(gr + 8) * 128 + c] = h2(ac[mi][j].z, ac[mi][j].w);
            float bb0 = bvv[c], bb1 = bvv[c + 1];
            *(uint32_t*)&g_val[gr * 128 + c]       = h2(lrelu(acv[mi][j].x + bb0), lrelu(acv[mi][j].y + bb1));
            *(uint32_t*)&g_val[(gr + 8) * 128 + c] = h2(lrelu(acv[mi][j].z + bb0), lrelu(acv[mi][j].w + bb1));
        }
    }
}

// ============================================================
// K3: attention — vectorized smem (float4 LDS/STS, register AV)
// ============================================================
constexpr int ASTR = 36;
__global__ void __launch_bounds__(256, 4)
k_attn()
{
    __shared__ float smem[8][3 * 8 * ASTR + 64];
    const int tid = threadIdx.x, warp = tid >> 5, lane = tid & 31;
    const int gid = blockIdx.x * 8 + warp;
    const int b = gid >> 2;
    const int p = gid & 3;

    float* selS = smem[warp];
    float* keyS = selS + 8 * ASTR;
    float* valS = keyS + 8 * ASTR;
    float* wS   = valS + 8 * ASTR;
    const float scale = 0.17677669529663687f;

    // fill: 24 segs (3 arrays x 8 agents) x 32 halves; vectorized stores
    #pragma unroll
    for (int it = 0; it < 3; it++) {
        int idx = it * 32 + lane;
        int seg = idx >> 2, q4 = idx & 3;
        int arr = seg >> 3, i = seg & 7;
        const __half* gsrc = (arr == 0) ? g_sel : (arr == 1) ? g_key : g_val;
        uint4 v = *(const uint4*)(gsrc + ((size_t)i * B + b) * HID + p * D + q4 * 8);
        const __half2* hp = (const __half2*)&v;
        float2 f0 = __half22float2(hp[0]);
        float2 f1 = __half22float2(hp[1]);
        float2 f2 = __half22float2(hp[2]);
        float2 f3 = __half22float2(hp[3]);
        float* dst = selS + arr * (8 * ASTR) + i * ASTR + q4 * 8;
        *(float4*)dst       = make_float4(f0.x, f0.y, f1.x, f1.y);
        *(float4*)(dst + 4) = make_float4(f2.x, f2.y, f3.x, f3.y);
    }
    __syncwarp();

    const int i0 = lane >> 3, j = lane & 7;
    const float4* selR0 = (const float4*)(selS + i0 * ASTR);
    const float4* selR1 = (const float4*)(selS + (i0 + 4) * ASTR);
    const float4* keyR  = (const float4*)(keyS + j * ASTR);
    float acc0 = 0.f, acc1 = 0.f;
    #pragma unroll
    for (int d4 = 0; d4 < 8; d4++) {
        float4 kv = keyR[d4];
        float4 sa = selR0[d4], sb = selR1[d4];
        acc0 += sa.x * kv.x + sa.y * kv.y + sa.z * kv.z + sa.w * kv.w;
        acc1 += sb.x * kv.x + sb.y * kv.y + sb.z * kv.z + sb.w * kv.w;
    }
    acc0 *= scale; acc1 *= scale;
    if (i0 == j)     acc0 = -1e9f;
    if (i0 + 4 == j) acc1 = -1e9f;

    float m0 = acc0, m1 = acc1;
    #pragma unroll
    for (int o = 1; o < 8; o <<= 1) {
        m0 = fmaxf(m0, __shfl_xor_sync(FULLMASK, m0, o));
        m1 = fmaxf(m1, __shfl_xor_sync(FULLMASK, m1, o));
    }
    float e0 = __expf(acc0 - m0), e1 = __expf(acc1 - m1);
    float s0 = e0, s1 = e1;
    #pragma unroll
    for (int o = 1; o < 8; o <<= 1) {
        s0 += __shfl_xor_sync(FULLMASK, s0, o);
        s1 += __shfl_xor_sync(FULLMASK, s1, o);
    }
    wS[lane]      = __fdividef(e0, s0);
    wS[lane + 32] = __fdividef(e1, s1);
    __syncwarp();

    // AV: v rows in registers, w rows as float4 pairs
    float v[8];
    #pragma unroll
    for (int jj = 0; jj < 8; jj++) v[jj] = valS[jj * ASTR + lane];
    #pragma unroll
    for (int ii = 0; ii < 8; ii++) {
        float4 wa = *(const float4*)(wS + ii * 8);
        float4 wb = *(const float4*)(wS + ii * 8 + 4);
        float o = wa.x * v[0] + wa.y * v[1] + wa.z * v[2] + wa.w * v[3]
                + wb.x * v[4] + wb.y * v[5] + wb.z * v[6] + wb.w * v[7];
        g_oth[((size_t)ii * B + b) * HID + p * D + lane] = __float2half_rn(o);
    }
}

// ============================================================
// K4: critic fp16 — everything staged up front, single mma sweep
// ============================================================
constexpr int HSTR   = 132;   // f32 h stride
constexpr int OSTRU  = 68;    // ph1 A row stride in u32 (136 halves)
constexpr int CR_OFF_A   = 0;                             // 33792 (h reuses whole region)
constexpr int CR_OFF_B1  = 33792;                         // 2 x 32768
constexpr int CR_OFF_W2  = 99328;                         // 8448
constexpr int CR_OFF_B1S = 107776;
constexpr int CR_OFF_B2S = 108288;
constexpr int CR_OFF_AMX = 108352;
constexpr int SMEM_CRIT  = 108608;

__device__ __forceinline__ void crit_stageW16(uint2* B1, int buf, int ph, int n, int tid) {
    const uint2* base = pWc116[n];
    for (int cc = tid; cc < 2048; cc += 256) {
        int lanepair = cc & 15, ksl = (cc >> 4) & 7, n8 = cc >> 7;
        cp16(B1 + buf + (n8 * 8 + ksl) * 32 + lanepair * 2,
             base + ((n8 * 16 + ph * 8 + ksl) * 32 + lanepair * 2));
    }
}

__global__ void __launch_bounds__(256, 2)
k_crit(const float* __restrict__ a,
       const float* __restrict__ Bc1,
       const float* __restrict__ Wc2, const float* __restrict__ Bc2,
       float* __restrict__ out)
{
    extern __shared__ char smc[];
    uint32_t* uA = (uint32_t*)(smc + CR_OFF_A);
    uint32_t* uAo = uA + 4096;                 // oth rows region
    uint2*    B1 = (uint2*)(smc + CR_OFF_B1);
    float*    h  = (float*)(smc + CR_OFF_A);
    float*   w2t = (float*)(smc + CR_OFF_W2);
    float*   b1s = (float*)(smc + CR_OFF_B1S);
    float*   b2s = (float*)(smc + CR_OFF_B2S);
    int*     amx = (int*)(smc + CR_OFF_AMX);

    const int n = blockIdx.y, tid = threadIdx.x;
    const int w = tid >> 5, lane = tid & 31;
    const size_t row0 = (size_t)n * B + (size_t)blockIdx.x * 64;

    // stage EVERYTHING up front
    crit_stageW16(B1, 0, 0, n, tid);
    crit_stageW16(B1, 4096, 1, n, tid);
    {
        const uint32_t* gseT = (const uint32_t*)g_se + ((row0 >> 6) << 12);
        for (int i = tid; i < 1024; i += 256) cp16(uA + i * 4, gseT + i * 4);
    }
    for (int i = tid; i < 1024; i += 256) {
        int r = i >> 4, c = i & 15;
        cp16(uAo + r * OSTRU + c * 4,
             (const uint32_t*)g_oth + (row0 + r) * 64 + c * 4);
    }
    CP_COMMIT();

    // small fills overlap the async copies
    for (int i = tid; i < HID * AD; i += 256) {
        int k = i >> 4, o = i & 15;
        w2t[o * HSTR + k] = Wc2[n * HID * AD + k * AD + o];
    }
    if (tid < HID) b1s[tid] = Bc1[n * HID + tid];
    if (tid >= HID && tid < HID + AD) b2s[tid - HID] = Bc2[n * AD + (tid - HID)];
    if (tid < 64) {
        const float4* ap = (const float4*)(a + (row0 + tid) * AD);
        float4 q0 = ap[0], q1 = ap[1], q2 = ap[2], q3 = ap[3];
        float vals[16] = {q0.x,q0.y,q0.z,q0.w, q1.x,q1.y,q1.z,q1.w,
                          q2.x,q2.y,q2.z,q2.w, q3.x,q3.y,q3.z,q3.w};
        int bi = 0; float bvv = vals[0];
        #pragma unroll
        for (int i = 1; i < 16; i++) if (vals[i] > bvv) { bvv = vals[i]; bi = i; }
        amx[tid] = bi;
    }

    const int rs_ = w & 1, cq = w >> 1;
    const int g = lane >> 2, tig = lane & 3;

    float4 acc[2][4];
    #pragma unroll
    for (int mi = 0; mi < 2; mi++)
        #pragma unroll
        for (int j = 0; j < 4; j++) acc[mi][j] = make_float4(0,0,0,0);

    CP_WAITG(0);
    __syncthreads();

    // ---- ph0: se (fragment-order fp16) ----
    #pragma unroll
    for (int ksl = 0; ksl < 8; ksl++) {
        uint4 fa0 = ldfrag16(uA, rs_ * 2,     ksl, lane);
        uint4 fa1 = ldfrag16(uA, rs_ * 2 + 1, ksl, lane);
        #pragma unroll
        for (int j = 0; j < 4; j++) {
            uint2 bb = B1[((cq * 4 + j) * 8 + ksl) * 32 + lane];
            mma16(acc[0][j], fa0, bb); mma16(acc[1][j], fa1, bb);
        }
    }
    // ---- ph1: oth (row-major fp16) ----
    const int R0 = rs_ * 32 + g;
    #pragma unroll
    for (int ksl = 0; ksl < 8; ksl++) {
        uint4 fa0, fa1;
        {
            const uint32_t* b0 = uAo + R0 * OSTRU + ksl * 8 + tig;
            fa0 = make_uint4(b0[0], b0[8 * OSTRU], b0[4], b0[8 * OSTRU + 4]);
            const uint32_t* b1 = b0 + 16 * OSTRU;
            fa1 = make_uint4(b1[0], b1[8 * OSTRU], b1[4], b1[8 * OSTRU + 4]);
        }
        #pragma unroll
        for (int j = 0; j < 4; j++) {
            uint2 bb = B1[4096 + ((cq * 4 + j) * 8 + ksl) * 32 + lane];
            mma16(acc[0][j], fa0, bb); mma16(acc[1][j], fa1, bb);
        }
    }
    __syncthreads();        // all A reads done before h overwrites uA

    #pragma unroll
    for (int mi = 0; mi < 2; mi++) {
        #pragma unroll
        for (int j = 0; j < 4; j++) {
            int r = rs_ * 32 + mi * 16 + g;
            int c = cq * 32 + j * 8 + 2 * tig;
            float bb0 = b1s[c], bb1 = b1s[c + 1];
            h[r * HSTR + c]           = lrelu(acc[mi][j].x + bb0);
            h[r * HSTR + c + 1]       = lrelu(acc[mi][j].y + bb1);
            h[(r + 8) * HSTR + c]     = lrelu(acc[mi][j].z + bb0);
            h[(r + 8) * HSTR + c + 1] = lrelu(acc[mi][j].w + bb1);
        }
    }
    __syncthreads();

    const int o = lane & 15, half = lane >> 4;
    #pragma unroll
    for (int rr = 0; rr < 8; rr++) {
        const int r = w * 8 + rr;
        const int bidx = blockIdx.x * 64 + r;
        const float4* hr4 = (const float4*)(h + r * HSTR + half * 64);
        const float4* w4  = (const float4*)(w2t + o * HSTR + half * 64);
        float q = 0.f;
        #pragma unroll
        for (int i = 0; i < 16; i++) {
            float4 hv = hr4[i], wv = w4[i];
            q += hv.x * wv.x + hv.y * wv.y + hv.z * wv.z + hv.w * wv.w;
        }
        q += __shfl_xor_sync(FULLMASK, q, 16);
        q += b2s[o];

        float qsel = __shfl_sync(FULLMASK, q, amx[r]);
        if (lane == 0) out[(size_t)n * B + bidx] = qsel;
    }
}

// ============================================================
extern "C" void kernel_launch(void* const* d_in, const int* in_sizes, int n_in,
                              void* d_out, int out_size)
{
    const float* s    = (const float*)d_in[0];
    const float* a    = (const float*)d_in[1];
    const float* Wsa  = (const float*)d_in[2];
    const float* Bsa  = (const float*)d_in[3];
    const float* Wse  = (const float*)d_in[4];
    const float* Bse  = (const float*)d_in[5];
    const float* Wk   = (const float*)d_in[6];
    const float* Wsel = (const float*)d_in[7];
    const float* Wv   = (const float*)d_in[8];
    const float* bv   = (const float*)d_in[9];
    const float* Wc1  = (const float*)d_in[10];
    const float* Bc1  = (const float*)d_in[11];
    const float* Wc2  = (const float*)d_in[12];
    const float* Bc2  = (const float*)d_in[13];
    float* out = (float*)d_out;

    cudaFuncSetAttribute(k_front, cudaFuncAttributeMaxDynamicSharedMemorySize, SMEM_FRONT);
    cudaFuncSetAttribute(k_crit,  cudaFuncAttributeMaxDynamicSharedMemorySize, SMEM_CRIT);

    k_prep_stats<<<352, 512>>>(Wk, Wv, Wsel, Wsa, Wse, Wc1, s, a);
    k_front     <<<dim3(B / 64, NAG), 256, SMEM_FRONT>>>(s, a, Bsa, Bse, bv);
    k_attn      <<<dim3((HEADS * B) / 8), 256>>>();
    k_crit      <<<dim3(B / 64, NAG), 256, SMEM_CRIT>>>(a, Bc1, Wc2, Bc2, out);
}

// round 15
// speedup vs baseline: 4.2899x; 1.0461x over previous
#include <cuda_runtime.h>
#include <cuda_fp16.h>
#include <math.h>
#include <stdint.h>

#define FULLMASK 0xffffffffu

constexpr int NAG  = 8;
constexpr int B    = 16384;
constexpr int SD   = 64;
constexpr int AD   = 16;
constexpr int KSA  = 80;
constexpr int HID  = 128;
constexpr int HEADS= 4;
constexpr int D    = 32;
constexpr float EPS = 1e-5f;

// -------- scratch --------
__device__ __align__(16) float g_part [NAG * 16 * KSA];
__device__ __align__(16) float g_partq[NAG * 16 * KSA];
__device__ __align__(16) __half g_se [(size_t)NAG * B * HID];   // fp16 FRAGMENT-ORDER 64-row tiles
__device__ __align__(16) __half g_key[(size_t)NAG * B * HID];   // fp16 row-major
__device__ __align__(16) __half g_val[(size_t)NAG * B * HID];
__device__ __align__(16) __half g_sel[(size_t)NAG * B * HID];
__device__ __align__(16) __half g_oth[(size_t)NAG * B * HID];   // fp16 row-major

// fragment-order fp16 weights
__device__ __align__(16) uint2 pWsa16[NAG][16 * 5 * 32];   // [(n8*5+ksh)*32+lane]
__device__ __align__(16) uint2 pWse16[NAG][16 * 4 * 32];   // [(n8*4+ksh)*32+lane]
__device__ __align__(16) uint2 pWk16 [8 * 16 * 32];        // [(n8*8+ksh)*32+lane]
__device__ __align__(16) uint2 pWv16 [8 * 16 * 32];
__device__ __align__(16) uint2 pWsel16[8 * 16 * 32];
__device__ __align__(16) uint2 pWc116[NAG][16 * 16 * 32];  // [(n8*16+ksh)*32+lane]

__device__ __forceinline__ float lrelu(float x) { return x > 0.f ? x : 0.01f * x; }

// pack (lo,hi) floats -> f16x2 (lo in low half)
__device__ __forceinline__ uint32_t h2(float lo, float hi) {
    uint32_t r; asm("cvt.rn.f16x2.f32 %0, %1, %2;" : "=r"(r) : "f"(hi), "f"(lo)); return r;
}
__device__ __forceinline__ void mma16(float4& d, const uint4 a, const uint2 b) {
    asm volatile(
        "mma.sync.aligned.m16n8k16.row.col.f32.f16.f16.f32 "
        "{%0,%1,%2,%3}, {%4,%5,%6,%7}, {%8,%9}, {%0,%1,%2,%3};"
        : "+f"(d.x), "+f"(d.y), "+f"(d.z), "+f"(d.w)
        : "r"(a.x), "r"(a.y), "r"(a.z), "r"(a.w), "r"(b.x), "r"(b.y));
}
__device__ __forceinline__ void cp16(void* smem_dst, const void* gsrc) {
    uint32_t sa = (uint32_t)__cvta_generic_to_shared(smem_dst);
    asm volatile("cp.async.cg.shared.global [%0], [%1], 16;" :: "r"(sa), "l"(gsrc));
}
#define CP_COMMIT()  asm volatile("cp.async.commit_group;")
#define CP_WAITG(n)  asm volatile("cp.async.wait_group " #n ";" ::: "memory")

// fp16 fragment-order A load (8-ksh tile): one LDS.128
__device__ __forceinline__ uint4 ldfrag16(const uint32_t* A16, int g16, int ksh, int lane) {
    return *(const uint4*)(A16 + (((g16 << 3) + ksh) << 7) + (lane << 2));
}
// store one (mi,j) accumulator's 4 values as fp16 fragment words (8-ksh tile)
__device__ __forceinline__ void st_frag16(uint32_t* A16, int g16, int n8, int tig, int g, float4 v) {
    int C = n8 * 8 + 2 * tig;
    int ksh = C >> 4;
    int co  = C & 15;
    int rego = (co >= 8) ? 2 : 0;
    int lanep = g * 4 + ((co & 7) >> 1);
    uint32_t* base = A16 + ((((g16 << 3) + ksh) << 5) + lanep) * 4;
    base[rego]     = h2(v.x, v.y);   // row R  : cols C,C+1
    base[rego + 1] = h2(v.z, v.w);   // row R+8
}

// ============================================================
// K0: prep (fp16 weight fragments) + BN partial stats, fused
// ============================================================
__global__ void __launch_bounds__(512)
k_prep_stats(const float* __restrict__ Wk, const float* __restrict__ Wv,
             const float* __restrict__ Wsel, const float* __restrict__ Wsa,
             const float* __restrict__ Wse, const float* __restrict__ Wc1,
             const float* __restrict__ s, const float* __restrict__ a)
{
    __shared__ float r1[512], r2[512];
    const int tid = threadIdx.x;

    if (blockIdx.x < 224) {
        int i = blockIdx.x * 512 + tid;
        if (i < 12288) {
            int which = i >> 12;
            int j = i & 4095;
            int n8 = j >> 8, ksh = (j >> 5) & 7, lane = j & 31;
            int g = lane >> 2, tig = lane & 3;
            int n = n8 * 8 + g, k0 = ksh * 16 + tig * 2;
            const float* W = which == 0 ? Wk : (which == 1 ? Wv : Wsel);
            const float* base = W + (n >> 5) * (HID * D) + (n & 31);
            uint2 v = make_uint2(h2(base[k0 * 32],       base[(k0 + 1) * 32]),
                                 h2(base[(k0 + 8) * 32], base[(k0 + 9) * 32]));
            (which == 0 ? pWk16 : which == 1 ? pWv16 : pWsel16)[j] = v;
            return;
        }
        int i2 = i - 12288;
        if (i2 < NAG * 2560) {
            int n = i2 / 2560, j = i2 % 2560;
            int n8 = j / 160, rem = j % 160;
            int ksh = rem >> 5, lane = rem & 31;
            int g = lane >> 2, tig = lane & 3;
            int nn = n8 * 8 + g, k0 = ksh * 16 + tig * 2;
            const float* W = Wsa + n * KSA * HID;
            pWsa16[n][j] = make_uint2(h2(W[k0 * HID + nn],       W[(k0 + 1) * HID + nn]),
                                      h2(W[(k0 + 8) * HID + nn], W[(k0 + 9) * HID + nn]));
            return;
        }
        int i3 = i2 - NAG * 2560;
        if (i3 < NAG * 2048) {
            int n = i3 >> 11, j = i3 & 2047;
            int n8 = j >> 7, ksh = (j >> 5) & 3, lane = j & 31;
            int g = lane >> 2, tig = lane & 3;
            int nn = n8 * 8 + g, k0 = ksh * 16 + tig * 2;
            const float* W = Wse + n * SD * HID;
            pWse16[n][j] = make_uint2(h2(W[k0 * HID + nn],       W[(k0 + 1) * HID + nn]),
                                      h2(W[(k0 + 8) * HID + nn], W[(k0 + 9) * HID + nn]));
            return;
        }
        int i4 = i3 - NAG * 2048;
        if (i4 < NAG * 8192) {
            int n = i4 >> 13, j = i4 & 8191;
            int lane = j & 31, ksh = (j >> 5) & 15, n8 = j >> 9;
            int g = lane >> 2, tig = lane & 3;
            int nn = n8 * 8 + g, k0 = ksh * 16 + tig * 2;
            const float* W = Wc1 + (size_t)n * 2 * HID * HID;
            pWc116[n][j] = make_uint2(h2(W[k0 * 128 + nn],       W[(k0 + 1) * 128 + nn]),
                                      h2(W[(k0 + 8) * 128 + nn], W[(k0 + 9) * 128 + nn]));
        }
        return;
    }

    const int bx = blockIdx.x - 224;
    const int n = bx >> 4, chunk = bx & 15;
    const size_t row0 = (size_t)n * B + chunk * 1024;
    float* part  = g_part  + (n * 16 + chunk) * KSA;
    float* partq = g_partq + (n * 16 + chunk) * KSA;

    {
        const int f = tid & 63, r0 = tid >> 6;
        float sum = 0.f, sq = 0.f;
        const float* p = s + (row0 + r0) * SD + f;
        #pragma unroll 4
        for (int st = 0; st < 128; st++) {
            float x = p[(size_t)st * 8 * SD];
            sum += x; sq += x * x;
        }
        r1[tid] = sum; r2[tid] = sq;
        __syncthreads();
        #pragma unroll
        for (int o = 4; o > 0; o >>= 1) {
            if (tid < o * 64) { r1[tid] += r1[tid + o * 64]; r2[tid] += r2[tid + o * 64]; }
            __syncthreads();
        }
        if (tid < 64) { part[tid] = r1[tid]; partq[tid] = r2[tid]; }
        __syncthreads();
    }
    {
        const int f = tid & 15, r0 = tid >> 4;
        float sum = 0.f, sq = 0.f;
        const float* p = a + (row0 + r0) * AD + f;
        #pragma unroll 4
        for (int st = 0; st < 32; st++) {
            float x = p[(size_t)st * 32 * AD];
            sum += x; sq += x * x;
        }
        r1[tid] = sum; r2[tid] = sq;
        __syncthreads();
        #pragma unroll
        for (int o = 16; o > 0; o >>= 1) {
            if (tid < o * 16) { r1[tid] += r1[tid + o * 16]; r2[tid] += r2[tid + o * 16]; }
            __syncthreads();
        }
        if (tid < 16) { part[64 + tid] = r1[tid]; partq[64 + tid] = r2[tid]; }
    }
}

// ============================================================
// K2: FUSED front, all fp16: enc -> sel -> kv (BN reduction inlined)
// ============================================================
constexpr int FR_OFF_AE   = 0;                            // 10240
constexpr int FR_OFF_A16  = 10240;                        // 16384
constexpr int FR_OFF_W    = 26624;                        // 73728
constexpr int FR_OFF_MISC = 100352;                       // 544 floats
constexpr int SMEM_FRONT  = 102528;

__global__ void __launch_bounds__(256, 2)
k_front(const float* __restrict__ s, const float* __restrict__ a,
        const float* __restrict__ Bsa, const float* __restrict__ Bse,
        const float* __restrict__ bv)
{
    extern __shared__ char smc[];
    uint32_t* uAe  = (uint32_t*)(smc + FR_OFF_AE);
    uint32_t* uA16 = (uint32_t*)(smc + FR_OFF_A16);
    uint2*    W    = (uint2*)(smc + FR_OFF_W);
    char*     Wc   = smc + FR_OFF_W;
    float*   bsa = (float*)(smc + FR_OFF_MISC);
    float*   bse = bsa + 128;
    float*   bvv = bse + 128;
    float*   mn  = bvv + 128;
    float*   rsd = mn + 80;

    const int n = blockIdx.y, tid = threadIdx.x;
    const size_t gr0 = (size_t)n * B + (size_t)blockIdx.x * 64;

    for (int c = tid; c < 2304; c += 256) {
        const char* src = (c < 1280) ? (const char*)pWsa16[n] + c * 16
                                     : (const char*)pWse16[n] + (c - 1280) * 16;
        cp16(Wc + c * 16, src);
    }
    CP_COMMIT();

    for (int i = tid; i < 128; i += 256) {
        bsa[i] = Bsa[n * HID + i];
        bse[i] = Bse[n * HID + i];
        bvv[i] = bv[i];
    }
    for (int i = tid; i < 80; i += 256) {
        float sum = 0.f, sq = 0.f;
        #pragma unroll
        for (int c = 0; c < 16; c++) {
            sum += g_part [(n * 16 + c) * KSA + i];
            sq  += g_partq[(n * 16 + c) * KSA + i];
        }
        float m = sum * (1.f / B);
        mn[i]  = m;
        rsd[i] = rsqrtf(sq * (1.f / B) - m * m + EPS);
    }
    __syncthreads();

    for (int i = tid; i < 64 * 20; i += 256) {
        int r = i / 20, c4 = i - r * 20;
        size_t row = gr0 + r;
        float4 v = (c4 < 16) ? ((const float4*)s)[row * 16 + c4]
                             : ((const float4*)a)[row * 4 + (c4 - 16)];
        int C = c4 * 4;
        float f0 = (v.x - mn[C])     * rsd[C];
        float f1 = (v.y - mn[C + 1]) * rsd[C + 1];
        float f2 = (v.z - mn[C + 2]) * rsd[C + 2];
        float f3 = (v.w - mn[C + 3]) * rsd[C + 3];
        int ksh = C >> 4, co = C & 15;
        int g16 = r >> 4, rr = r & 15;
        int comp = (rr >> 3) & 1, gp = rr & 7;
        int tig0 = (co & 7) >> 1;
        uint32_t* base = uAe + (((g16 * 5 + ksh) << 5) + (gp << 2) + tig0) * 4
                         + ((co >= 8) ? 2 : 0) + comp;
        base[0] = h2(f0, f1);
        base[4] = h2(f2, f3);
    }
    CP_WAITG(0);
    __syncthreads();

    const int w = tid >> 5, lane = tid & 31;
    const int rs_ = w & 1, t0 = w >> 1;
    const int g = lane >> 2, tig = lane & 3;

    // ---- Phase 1: enc ----
    float4 ae[2][4], as_[2][4];
    #pragma unroll
    for (int mi = 0; mi < 2; mi++)
        #pragma unroll
        for (int j = 0; j < 4; j++) { ae[mi][j] = make_float4(0,0,0,0); as_[mi][j] = make_float4(0,0,0,0); }

    #pragma unroll
    for (int ksh = 0; ksh < 5; ksh++) {
        uint4 fa0 = *(const uint4*)(uAe + (((rs_*2)   * 5 + ksh) << 7) + (lane << 2));
        uint4 fa1 = *(const uint4*)(uAe + (((rs_*2+1) * 5 + ksh) << 7) + (lane << 2));
        #pragma unroll
        for (int j = 0; j < 4; j++) {
            uint2 bb = W[((t0 * 4 + j) * 5 + ksh) * 32 + lane];
            mma16(ae[0][j], fa0, bb); mma16(ae[1][j], fa1, bb);
        }
        if (ksh < 4) {
            #pragma unroll
            for (int j = 0; j < 4; j++) {
                uint2 bb = W[2560 + ((t0 * 4 + j) * 4 + ksh) * 32 + lane];
                mma16(as_[0][j], fa0, bb); mma16(as_[1][j], fa1, bb);
            }
        }
    }
    __syncthreads();

    for (int c = tid; c < 2048; c += 256) cp16(Wc + c * 16, (const char*)pWsel16 + c * 16);
    CP_COMMIT();

    uint32_t* gseT = (uint32_t*)g_se + ((gr0 >> 6) << 12);
    #pragma unroll
    for (int mi = 0; mi < 2; mi++) {
        #pragma unroll
        for (int j = 0; j < 4; j++) {
            int c = t0 * 32 + j * 8 + 2 * tig;
            float b0e = bsa[c], b1e = bsa[c + 1];
            float b0s = bse[c], b1s = bse[c + 1];
            ae[mi][j]  = make_float4(lrelu(ae[mi][j].x + b0e), lrelu(ae[mi][j].y + b1e),
                                     lrelu(ae[mi][j].z + b0e), lrelu(ae[mi][j].w + b1e));
            as_[mi][j] = make_float4(lrelu(as_[mi][j].x + b0s), lrelu(as_[mi][j].y + b1s),
                                     lrelu(as_[mi][j].z + b0s), lrelu(as_[mi][j].w + b1s));
            st_frag16(uA16, rs_ * 2 + mi, t0 * 4 + j, tig, g, as_[mi][j]);
            st_frag16(gseT, rs_ * 2 + mi, t0 * 4 + j, tig, g, as_[mi][j]);
        }
    }
    CP_WAITG(0);
    __syncthreads();

    // ---- Phase 2: sel ----
    float4 ac[2][4], acv[2][4];
    #pragma unroll
    for (int mi = 0; mi < 2; mi++)
        #pragma unroll
        for (int j = 0; j < 4; j++) ac[mi][j] = make_float4(0,0,0,0);

    #pragma unroll
    for (int ksh = 0; ksh < 8; ksh++) {
        uint4 fa0 = ldfrag16(uA16, rs_ * 2,     ksh, lane);
        uint4 fa1 = ldfrag16(uA16, rs_ * 2 + 1, ksh, lane);
        #pragma unroll
        for (int j = 0; j < 4; j++) {
            uint2 bb = W[((t0 * 4 + j) * 8 + ksh) * 32 + lane];
            mma16(ac[0][j], fa0, bb); mma16(ac[1][j], fa1, bb);
        }
    }
    __syncthreads();

    for (int c = tid; c < 4096; c += 256) {
        const char* src = (c < 2048) ? (const char*)pWk16 + c * 16
                                     : (const char*)pWv16 + (c - 2048) * 16;
        cp16(Wc + c * 16, src);
    }
    CP_COMMIT();

    #pragma unroll
    for (int mi = 0; mi < 2; mi++) {
        #pragma unroll
        for (int j = 0; j < 4; j++) {
            int c = t0 * 32 + j * 8 + 2 * tig;
            size_t gr = gr0 + rs_ * 32 + mi * 16 + g;
            *(uint32_t*)&g_sel[gr * 128 + c]       = h2(ac[mi][j].x, ac[mi][j].y);
            *(uint32_t*)&g_sel[(gr + 8) * 128 + c] = h2(ac[mi][j].z, ac[mi][j].w);
            st_frag16(uA16, rs_ * 2 + mi, t0 * 4 + j, tig, g, ae[mi][j]);
        }
    }
    CP_WAITG(0);
    __syncthreads();

    // ---- Phase 3: key + val ----
    #pragma unroll
    for (int mi = 0; mi < 2; mi++)
        #pragma unroll
        for (int j = 0; j < 4; j++) { ac[mi][j] = make_float4(0,0,0,0); acv[mi][j] = make_float4(0,0,0,0); }

    #pragma unroll
    for (int ksh = 0; ksh < 8; ksh++) {
        uint4 fa0 = ldfrag16(uA16, rs_ * 2,     ksh, lane);
        uint4 fa1 = ldfrag16(uA16, rs_ * 2 + 1, ksh, lane);
        #pragma unroll
        for (int j = 0; j < 4; j++) {
            int bi = ((t0 * 4 + j) * 8 + ksh) * 32 + lane;
            uint2 bk = W[bi], bw = W[4096 + bi];
            mma16(ac[0][j],  fa0, bk); mma16(ac[1][j],  fa1, bk);
            mma16(acv[0][j], fa0, bw); mma16(acv[1][j], fa1, bw);
        }
    }

    #pragma unroll
    for (int mi = 0; mi < 2; mi++) {
        #pragma unroll
        for (int j = 0; j < 4; j++) {
            size_t gr = gr0 + rs_ * 32 + mi * 16 + g;
            int c = t0 * 32 + j * 8 + 2 * tig;
            *(uint32_t*)&g_key[gr * 128 + c]       = h2(ac[mi][j].x, ac[mi][j].y);
            *(uint32_t*)&g_key[(gr + 8) * 128 + c] = h2(ac[mi][j].z, ac[mi][j].w);
            float bb0 = bvv[c], bb1 = bvv[c + 1];
            *(uint32_t*)&g_val[gr * 128 + c]       = h2(lrelu(acv[mi][j].x + bb0), lrelu(acv[mi][j].y + bb1));
            *(uint32_t*)&g_val[(gr + 8) * 128 + c] = h2(lrelu(acv[mi][j].z + bb0), lrelu(acv[mi][j].w + bb1));
        }
    }
}

// ============================================================
// K3: attention — vectorized smem (float4 LDS/STS, register AV)
// ============================================================
constexpr int ASTR = 36;
__global__ void __launch_bounds__(256, 4)
k_attn()
{
    __shared__ float smem[8][3 * 8 * ASTR + 64];
    const int tid = threadIdx.x, warp = tid >> 5, lane = tid & 31;
    const int gid = blockIdx.x * 8 + warp;
    const int b = gid >> 2;
    const int p = gid & 3;

    float* selS = smem[warp];
    float* keyS = selS + 8 * ASTR;
    float* valS = keyS + 8 * ASTR;
    float* wS   = valS + 8 * ASTR;
    const float scale = 0.17677669529663687f;

    #pragma unroll
    for (int it = 0; it < 3; it++) {
        int idx = it * 32 + lane;
        int seg = idx >> 2, q4 = idx & 3;
        int arr = seg >> 3, i = seg & 7;
        const __half* gsrc = (arr == 0) ? g_sel : (arr == 1) ? g_key : g_val;
        uint4 v = *(const uint4*)(gsrc + ((size_t)i * B + b) * HID + p * D + q4 * 8);
        const __half2* hp = (const __half2*)&v;
        float2 f0 = __half22float2(hp[0]);
        float2 f1 = __half22float2(hp[1]);
        float2 f2 = __half22float2(hp[2]);
        float2 f3 = __half22float2(hp[3]);
        float* dst = selS + arr * (8 * ASTR) + i * ASTR + q4 * 8;
        *(float4*)dst       = make_float4(f0.x, f0.y, f1.x, f1.y);
        *(float4*)(dst + 4) = make_float4(f2.x, f2.y, f3.x, f3.y);
    }
    __syncwarp();

    const int i0 = lane >> 3, j = lane & 7;
    const float4* selR0 = (const float4*)(selS + i0 * ASTR);
    const float4* selR1 = (const float4*)(selS + (i0 + 4) * ASTR);
    const float4* keyR  = (const float4*)(keyS + j * ASTR);
    float acc0 = 0.f, acc1 = 0.f;
    #pragma unroll
    for (int d4 = 0; d4 < 8; d4++) {
        float4 kv = keyR[d4];
        float4 sa = selR0[d4], sb = selR1[d4];
        acc0 += sa.x * kv.x + sa.y * kv.y + sa.z * kv.z + sa.w * kv.w;
        acc1 += sb.x * kv.x + sb.y * kv.y + sb.z * kv.z + sb.w * kv.w;
    }
    acc0 *= scale; acc1 *= scale;
    if (i0 == j)     acc0 = -1e9f;
    if (i0 + 4 == j) acc1 = -1e9f;

    float m0 = acc0, m1 = acc1;
    #pragma unroll
    for (int o = 1; o < 8; o <<= 1) {
        m0 = fmaxf(m0, __shfl_xor_sync(FULLMASK, m0, o));
        m1 = fmaxf(m1, __shfl_xor_sync(FULLMASK, m1, o));
    }
    float e0 = __expf(acc0 - m0), e1 = __expf(acc1 - m1);
    float s0 = e0, s1 = e1;
    #pragma unroll
    for (int o = 1; o < 8; o <<= 1) {
        s0 += __shfl_xor_sync(FULLMASK, s0, o);
        s1 += __shfl_xor_sync(FULLMASK, s1, o);
    }
    wS[lane]      = __fdividef(e0, s0);
    wS[lane + 32] = __fdividef(e1, s1);
    __syncwarp();

    float v[8];
    #pragma unroll
    for (int jj = 0; jj < 8; jj++) v[jj] = valS[jj * ASTR + lane];
    #pragma unroll
    for (int ii = 0; ii < 8; ii++) {
        float4 wa = *(const float4*)(wS + ii * 8);
        float4 wb = *(const float4*)(wS + ii * 8 + 4);
        float o = wa.x * v[0] + wa.y * v[1] + wa.z * v[2] + wa.w * v[3]
                + wb.x * v[4] + wb.y * v[5] + wb.z * v[6] + wb.w * v[7];
        g_oth[((size_t)ii * B + b) * HID + p * D + lane] = __float2half_rn(o);
    }
}

// ============================================================
// K4: critic fp16 — front-loaded staging; SELECTED-COLUMN layer 2
// ============================================================
constexpr int HSTR   = 132;   // f32 h stride
constexpr int OSTRU  = 68;    // ph1 A row stride in u32 (136 halves)
constexpr int CR_OFF_A   = 0;                             // 33792 (h reuses whole region)
constexpr int CR_OFF_B1  = 33792;                         // 2 x 32768
constexpr int CR_OFF_W2  = 99328;                         // 8448
constexpr int CR_OFF_B1S = 107776;
constexpr int CR_OFF_B2S = 108288;
constexpr int CR_OFF_AMX = 108352;
constexpr int SMEM_CRIT  = 108608;

__device__ __forceinline__ void crit_stageW16(uint2* B1, int buf, int ph, int n, int tid) {
    const uint2* base = pWc116[n];
    for (int cc = tid; cc < 2048; cc += 256) {
        int lanepair = cc & 15, ksl = (cc >> 4) & 7, n8 = cc >> 7;
        cp16(B1 + buf + (n8 * 8 + ksl) * 32 + lanepair * 2,
             base + ((n8 * 16 + ph * 8 + ksl) * 32 + lanepair * 2));
    }
}

__global__ void __launch_bounds__(256, 2)
k_crit(const float* __restrict__ a,
       const float* __restrict__ Bc1,
       const float* __restrict__ Wc2, const float* __restrict__ Bc2,
       float* __restrict__ out)
{
    extern __shared__ char smc[];
    uint32_t* uA = (uint32_t*)(smc + CR_OFF_A);
    uint32_t* uAo = uA + 4096;
    uint2*    B1 = (uint2*)(smc + CR_OFF_B1);
    float*    h  = (float*)(smc + CR_OFF_A);
    float*   w2t = (float*)(smc + CR_OFF_W2);
    float*   b1s = (float*)(smc + CR_OFF_B1S);
    float*   b2s = (float*)(smc + CR_OFF_B2S);
    int*     amx = (int*)(smc + CR_OFF_AMX);

    const int n = blockIdx.y, tid = threadIdx.x;
    const int w = tid >> 5, lane = tid & 31;
    const size_t row0 = (size_t)n * B + (size_t)blockIdx.x * 64;

    // stage EVERYTHING up front
    crit_stageW16(B1, 0, 0, n, tid);
    crit_stageW16(B1, 4096, 1, n, tid);
    {
        const uint32_t* gseT = (const uint32_t*)g_se + ((row0 >> 6) << 12);
        for (int i = tid; i < 1024; i += 256) cp16(uA + i * 4, gseT + i * 4);
    }
    for (int i = tid; i < 1024; i += 256) {
        int r = i >> 4, c = i & 15;
        cp16(uAo + r * OSTRU + c * 4,
             (const uint32_t*)g_oth + (row0 + r) * 64 + c * 4);
    }
    CP_COMMIT();

    for (int i = tid; i < HID * AD; i += 256) {
        int k = i >> 4, o = i & 15;
        w2t[o * HSTR + k] = Wc2[n * HID * AD + k * AD + o];
    }
    if (tid < HID) b1s[tid] = Bc1[n * HID + tid];
    if (tid >= HID && tid < HID + AD) b2s[tid - HID] = Bc2[n * AD + (tid - HID)];
    if (tid < 64) {
        const float4* ap = (const float4*)(a + (row0 + tid) * AD);
        float4 q0 = ap[0], q1 = ap[1], q2 = ap[2], q3 = ap[3];
        float vals[16] = {q0.x,q0.y,q0.z,q0.w, q1.x,q1.y,q1.z,q1.w,
                          q2.x,q2.y,q2.z,q2.w, q3.x,q3.y,q3.z,q3.w};
        int bi = 0; float bvv = vals[0];
        #pragma unroll
        for (int i = 1; i < 16; i++) if (vals[i] > bvv) { bvv = vals[i]; bi = i; }
        amx[tid] = bi;
    }

    const int rs_ = w & 1, cq = w >> 1;
    const int g = lane >> 2, tig = lane & 3;

    float4 acc[2][4];
    #pragma unroll
    for (int mi = 0; mi < 2; mi++)
        #pragma unroll
        for (int j = 0; j < 4; j++) acc[mi][j] = make_float4(0,0,0,0);

    CP_WAITG(0);
    __syncthreads();

    // ---- ph0: se (fragment-order fp16) ----
    #pragma unroll
    for (int ksl = 0; ksl < 8; ksl++) {
        uint4 fa0 = ldfrag16(uA, rs_ * 2,     ksl, lane);
        uint4 fa1 = ldfrag16(uA, rs_ * 2 + 1, ksl, lane);
        #pragma unroll
        for (int j = 0; j < 4; j++) {
            uint2 bb = B1[((cq * 4 + j) * 8 + ksl) * 32 + lane];
            mma16(acc[0][j], fa0, bb); mma16(acc[1][j], fa1, bb);
        }
    }
    // ---- ph1: oth (row-major fp16) ----
    const int R0 = rs_ * 32 + g;
    #pragma unroll
    for (int ksl = 0; ksl < 8; ksl++) {
        uint4 fa0, fa1;
        {
            const uint32_t* b0 = uAo + R0 * OSTRU + ksl * 8 + tig;
            fa0 = make_uint4(b0[0], b0[8 * OSTRU], b0[4], b0[8 * OSTRU + 4]);
            const uint32_t* b1 = b0 + 16 * OSTRU;
            fa1 = make_uint4(b1[0], b1[8 * OSTRU], b1[4], b1[8 * OSTRU + 4]);
        }
        #pragma unroll
        for (int j = 0; j < 4; j++) {
            uint2 bb = B1[4096 + ((cq * 4 + j) * 8 + ksl) * 32 + lane];
            mma16(acc[0][j], fa0, bb); mma16(acc[1][j], fa1, bb);
        }
    }
    __syncthreads();        // all A reads done before h overwrites uA

    #pragma unroll
    for (int mi = 0; mi < 2; mi++) {
        #pragma unroll
        for (int j = 0; j < 4; j++) {
            int r = rs_ * 32 + mi * 16 + g;
            int c = cq * 32 + j * 8 + 2 * tig;
            float bb0 = b1s[c], bb1 = b1s[c + 1];
            *(float2*)&h[r * HSTR + c]       = make_float2(lrelu(acc[mi][j].x + bb0), lrelu(acc[mi][j].y + bb1));
            *(float2*)&h[(r + 8) * HSTR + c] = make_float2(lrelu(acc[mi][j].z + bb0), lrelu(acc[mi][j].w + bb1));
        }
    }
    __syncthreads();

    // layer 2: ONLY the selected output column per row.
    // warp w handles rows w*8..w*8+7; each lane covers 4 of 128 dims.
    #pragma unroll
    for (int rr = 0; rr < 8; rr++) {
        const int r = w * 8 + rr;
        const int o = amx[r];
        float4 hv = *(const float4*)(h + r * HSTR + lane * 4);
        float4 wv = *(const float4*)(w2t + o * HSTR + lane * 4);
        float q = hv.x * wv.x + hv.y * wv.y + hv.z * wv.z + hv.w * wv.w;
        #pragma unroll
        for (int off = 16; off > 0; off >>= 1)
            q += __shfl_xor_sync(FULLMASK, q, off);
        if (lane == 0)
            out[(size_t)n * B + blockIdx.x * 64 + r] = q + b2s[o];
    }
}

// ============================================================
extern "C" void kernel_launch(void* const* d_in, const int* in_sizes, int n_in,
                              void* d_out, int out_size)
{
    const float* s    = (const float*)d_in[0];
    const float* a    = (const float*)d_in[1];
    const float* Wsa  = (const float*)d_in[2];
    const float* Bsa  = (const float*)d_in[3];
    const float* Wse  = (const float*)d_in[4];
    const float* Bse  = (const float*)d_in[5];
    const float* Wk   = (const float*)d_in[6];
    const float* Wsel = (const float*)d_in[7];
    const float* Wv   = (const float*)d_in[8];
    const float* bv   = (const float*)d_in[9];
    const float* Wc1  = (const float*)d_in[10];
    const float* Bc1  = (const float*)d_in[11];
    const float* Wc2  = (const float*)d_in[12];
    const float* Bc2  = (const float*)d_in[13];
    float* out = (float*)d_out;

    cudaFuncSetAttribute(k_front, cudaFuncAttributeMaxDynamicSharedMemorySize, SMEM_FRONT);
    cudaFuncSetAttribute(k_crit,  cudaFuncAttributeMaxDynamicSharedMemorySize, SMEM_CRIT);

    k_prep_stats<<<352, 512>>>(Wk, Wv, Wsel, Wsa, Wse, Wc1, s, a);
    k_front     <<<dim3(B / 64, NAG), 256, SMEM_FRONT>>>(s, a, Bsa, Bse, bv);
    k_attn      <<<dim3((HEADS * B) / 8), 256>>>();
    k_crit      <<<dim3(B / 64, NAG), 256, SMEM_CRIT>>>(a, Bc1, Wc2, Bc2, out);
}

// round 16
// speedup vs baseline: 4.3684x; 1.0183x over previous
#include <cuda_runtime.h>
#include <cuda_fp16.h>
#include <math.h>
#include <stdint.h>

#define FULLMASK 0xffffffffu

constexpr int NAG  = 8;
constexpr int B    = 16384;
constexpr int SD   = 64;
constexpr int AD   = 16;
constexpr int KSA  = 80;
constexpr int HID  = 128;
constexpr int HEADS= 4;
constexpr int D    = 32;
constexpr float EPS = 1e-5f;

// -------- scratch --------
__device__ __align__(16) float g_part [NAG * 16 * KSA];
__device__ __align__(16) float g_partq[NAG * 16 * KSA];
__device__ __align__(16) __half g_se [(size_t)NAG * B * HID];   // fp16 FRAGMENT-ORDER 64-row tiles
__device__ __align__(16) __half g_key[(size_t)NAG * B * HID];   // fp16 row-major
__device__ __align__(16) __half g_val[(size_t)NAG * B * HID];
__device__ __align__(16) __half g_sel[(size_t)NAG * B * HID];
__device__ __align__(16) __half g_oth[(size_t)NAG * B * HID];   // fp16 row-major

// fragment-order fp16 weights
__device__ __align__(16) uint2 pWsa16[NAG][16 * 5 * 32];   // [(n8*5+ksh)*32+lane]
__device__ __align__(16) uint2 pWse16[NAG][16 * 4 * 32];   // [(n8*4+ksh)*32+lane]
__device__ __align__(16) uint2 pWk16 [8 * 16 * 32];        // [(n8*8+ksh)*32+lane]
__device__ __align__(16) uint2 pWv16 [8 * 16 * 32];
__device__ __align__(16) uint2 pWsel16[8 * 16 * 32];
__device__ __align__(16) uint2 pWc116[NAG][16 * 16 * 32];  // [(n8*16+ksh)*32+lane]

__device__ __forceinline__ float lrelu(float x) { return x > 0.f ? x : 0.01f * x; }

// pack (lo,hi) floats -> f16x2 (lo in low half)
__device__ __forceinline__ uint32_t h2(float lo, float hi) {
    uint32_t r; asm("cvt.rn.f16x2.f32 %0, %1, %2;" : "=r"(r) : "f"(hi), "f"(lo)); return r;
}
__device__ __forceinline__ void mma16(float4& d, const uint4 a, const uint2 b) {
    asm volatile(
        "mma.sync.aligned.m16n8k16.row.col.f32.f16.f16.f32 "
        "{%0,%1,%2,%3}, {%4,%5,%6,%7}, {%8,%9}, {%0,%1,%2,%3};"
        : "+f"(d.x), "+f"(d.y), "+f"(d.z), "+f"(d.w)
        : "r"(a.x), "r"(a.y), "r"(a.z), "r"(a.w), "r"(b.x), "r"(b.y));
}
__device__ __forceinline__ void cp16(void* smem_dst, const void* gsrc) {
    uint32_t sa = (uint32_t)__cvta_generic_to_shared(smem_dst);
    asm volatile("cp.async.cg.shared.global [%0], [%1], 16;" :: "r"(sa), "l"(gsrc));
}
#define CP_COMMIT()  asm volatile("cp.async.commit_group;")
#define CP_WAITG(n)  asm volatile("cp.async.wait_group " #n ";" ::: "memory")

// fp16 fragment-order A load (8-ksh tile): one LDS.128
__device__ __forceinline__ uint4 ldfrag16(const uint32_t* A16, int g16, int ksh, int lane) {
    return *(const uint4*)(A16 + (((g16 << 3) + ksh) << 7) + (lane << 2));
}
// store one (mi,j) accumulator's 4 values as fp16 fragment words (8-ksh tile)
__device__ __forceinline__ void st_frag16(uint32_t* A16, int g16, int n8, int tig, int g, float4 v) {
    int C = n8 * 8 + 2 * tig;
    int ksh = C >> 4;
    int co  = C & 15;
    int rego = (co >= 8) ? 2 : 0;
    int lanep = g * 4 + ((co & 7) >> 1);
    uint32_t* base = A16 + ((((g16 << 3) + ksh) << 5) + lanep) * 4;
    base[rego]     = h2(v.x, v.y);   // row R  : cols C,C+1
    base[rego + 1] = h2(v.z, v.w);   // row R+8
}

// ============================================================
// K0: prep (fp16 weight fragments) + BN partial stats, fused
// ============================================================
__global__ void __launch_bounds__(512)
k_prep_stats(const float* __restrict__ Wk, const float* __restrict__ Wv,
             const float* __restrict__ Wsel, const float* __restrict__ Wsa,
             const float* __restrict__ Wse, const float* __restrict__ Wc1,
             const float* __restrict__ s, const float* __restrict__ a)
{
    __shared__ float r1[512], r2[512];
    const int tid = threadIdx.x;

    if (blockIdx.x < 224) {
        int i = blockIdx.x * 512 + tid;
        if (i < 12288) {
            int which = i >> 12;
            int j = i & 4095;
            int n8 = j >> 8, ksh = (j >> 5) & 7, lane = j & 31;
            int g = lane >> 2, tig = lane & 3;
            int n = n8 * 8 + g, k0 = ksh * 16 + tig * 2;
            const float* W = which == 0 ? Wk : (which == 1 ? Wv : Wsel);
            const float* base = W + (n >> 5) * (HID * D) + (n & 31);
            uint2 v = make_uint2(h2(base[k0 * 32],       base[(k0 + 1) * 32]),
                                 h2(base[(k0 + 8) * 32], base[(k0 + 9) * 32]));
            (which == 0 ? pWk16 : which == 1 ? pWv16 : pWsel16)[j] = v;
            return;
        }
        int i2 = i - 12288;
        if (i2 < NAG * 2560) {
            int n = i2 / 2560, j = i2 % 2560;
            int n8 = j / 160, rem = j % 160;
            int ksh = rem >> 5, lane = rem & 31;
            int g = lane >> 2, tig = lane & 3;
            int nn = n8 * 8 + g, k0 = ksh * 16 + tig * 2;
            const float* W = Wsa + n * KSA * HID;
            pWsa16[n][j] = make_uint2(h2(W[k0 * HID + nn],       W[(k0 + 1) * HID + nn]),
                                      h2(W[(k0 + 8) * HID + nn], W[(k0 + 9) * HID + nn]));
            return;
        }
        int i3 = i2 - NAG * 2560;
        if (i3 < NAG * 2048) {
            int n = i3 >> 11, j = i3 & 2047;
            int n8 = j >> 7, ksh = (j >> 5) & 3, lane = j & 31;
            int g = lane >> 2, tig = lane & 3;
            int nn = n8 * 8 + g, k0 = ksh * 16 + tig * 2;
            const float* W = Wse + n * SD * HID;
            pWse16[n][j] = make_uint2(h2(W[k0 * HID + nn],       W[(k0 + 1) * HID + nn]),
                                      h2(W[(k0 + 8) * HID + nn], W[(k0 + 9) * HID + nn]));
            return;
        }
        int i4 = i3 - NAG * 2048;
        if (i4 < NAG * 8192) {
            int n = i4 >> 13, j = i4 & 8191;
            int lane = j & 31, ksh = (j >> 5) & 15, n8 = j >> 9;
            int g = lane >> 2, tig = lane & 3;
            int nn = n8 * 8 + g, k0 = ksh * 16 + tig * 2;
            const float* W = Wc1 + (size_t)n * 2 * HID * HID;
            pWc116[n][j] = make_uint2(h2(W[k0 * 128 + nn],       W[(k0 + 1) * 128 + nn]),
                                      h2(W[(k0 + 8) * 128 + nn], W[(k0 + 9) * 128 + nn]));
        }
        return;
    }

    const int bx = blockIdx.x - 224;
    const int n = bx >> 4, chunk = bx & 15;
    const size_t row0 = (size_t)n * B + chunk * 1024;
    float* part  = g_part  + (n * 16 + chunk) * KSA;
    float* partq = g_partq + (n * 16 + chunk) * KSA;

    {
        const int f = tid & 63, r0 = tid >> 6;
        float sum = 0.f, sq = 0.f;
        const float* p = s + (row0 + r0) * SD + f;
        #pragma unroll 4
        for (int st = 0; st < 128; st++) {
            float x = p[(size_t)st * 8 * SD];
            sum += x; sq += x * x;
        }
        r1[tid] = sum; r2[tid] = sq;
        __syncthreads();
        #pragma unroll
        for (int o = 4; o > 0; o >>= 1) {
            if (tid < o * 64) { r1[tid] += r1[tid + o * 64]; r2[tid] += r2[tid + o * 64]; }
            __syncthreads();
        }
        if (tid < 64) { part[tid] = r1[tid]; partq[tid] = r2[tid]; }
        __syncthreads();
    }
    {
        const int f = tid & 15, r0 = tid >> 4;
        float sum = 0.f, sq = 0.f;
        const float* p = a + (row0 + r0) * AD + f;
        #pragma unroll 4
        for (int st = 0; st < 32; st++) {
            float x = p[(size_t)st * 32 * AD];
            sum += x; sq += x * x;
        }
        r1[tid] = sum; r2[tid] = sq;
        __syncthreads();
        #pragma unroll
        for (int o = 16; o > 0; o >>= 1) {
            if (tid < o * 16) { r1[tid] += r1[tid + o * 16]; r2[tid] += r2[tid + o * 16]; }
            __syncthreads();
        }
        if (tid < 16) { part[64 + tid] = r1[tid]; partq[64 + tid] = r2[tid]; }
    }
}

// ============================================================
// K2: FUSED front, all fp16: enc -> sel -> kv (BN reduction inlined)
// ============================================================
constexpr int FR_OFF_AE   = 0;                            // 10240
constexpr int FR_OFF_A16  = 10240;                        // 16384
constexpr int FR_OFF_W    = 26624;                        // 73728
constexpr int FR_OFF_MISC = 100352;                       // 544 floats
constexpr int SMEM_FRONT  = 102528;

__global__ void __launch_bounds__(256, 2)
k_front(const float* __restrict__ s, const float* __restrict__ a,
        const float* __restrict__ Bsa, const float* __restrict__ Bse,
        const float* __restrict__ bv)
{
    extern __shared__ char smc[];
    uint32_t* uAe  = (uint32_t*)(smc + FR_OFF_AE);
    uint32_t* uA16 = (uint32_t*)(smc + FR_OFF_A16);
    uint2*    W    = (uint2*)(smc + FR_OFF_W);
    char*     Wc   = smc + FR_OFF_W;
    float*   bsa = (float*)(smc + FR_OFF_MISC);
    float*   bse = bsa + 128;
    float*   bvv = bse + 128;
    float*   mn  = bvv + 128;
    float*   rsd = mn + 80;

    const int n = blockIdx.y, tid = threadIdx.x;
    const size_t gr0 = (size_t)n * B + (size_t)blockIdx.x * 64;

    for (int c = tid; c < 2304; c += 256) {
        const char* src = (c < 1280) ? (const char*)pWsa16[n] + c * 16
                                     : (const char*)pWse16[n] + (c - 1280) * 16;
        cp16(Wc + c * 16, src);
    }
    CP_COMMIT();

    for (int i = tid; i < 128; i += 256) {
        bsa[i] = Bsa[n * HID + i];
        bse[i] = Bse[n * HID + i];
        bvv[i] = bv[i];
    }
    for (int i = tid; i < 80; i += 256) {
        float sum = 0.f, sq = 0.f;
        #pragma unroll
        for (int c = 0; c < 16; c++) {
            sum += g_part [(n * 16 + c) * KSA + i];
            sq  += g_partq[(n * 16 + c) * KSA + i];
        }
        float m = sum * (1.f / B);
        mn[i]  = m;
        rsd[i] = rsqrtf(sq * (1.f / B) - m * m + EPS);
    }
    __syncthreads();

    for (int i = tid; i < 64 * 20; i += 256) {
        int r = i / 20, c4 = i - r * 20;
        size_t row = gr0 + r;
        float4 v = (c4 < 16) ? ((const float4*)s)[row * 16 + c4]
                             : ((const float4*)a)[row * 4 + (c4 - 16)];
        int C = c4 * 4;
        float f0 = (v.x - mn[C])     * rsd[C];
        float f1 = (v.y - mn[C + 1]) * rsd[C + 1];
        float f2 = (v.z - mn[C + 2]) * rsd[C + 2];
        float f3 = (v.w - mn[C + 3]) * rsd[C + 3];
        int ksh = C >> 4, co = C & 15;
        int g16 = r >> 4, rr = r & 15;
        int comp = (rr >> 3) & 1, gp = rr & 7;
        int tig0 = (co & 7) >> 1;
        uint32_t* base = uAe + (((g16 * 5 + ksh) << 5) + (gp << 2) + tig0) * 4
                         + ((co >= 8) ? 2 : 0) + comp;
        base[0] = h2(f0, f1);
        base[4] = h2(f2, f3);
    }
    CP_WAITG(0);
    __syncthreads();

    const int w = tid >> 5, lane = tid & 31;
    const int rs_ = w & 1, t0 = w >> 1;
    const int g = lane >> 2, tig = lane & 3;

    // ---- Phase 1: enc ----
    float4 ae[2][4], as_[2][4];
    #pragma unroll
    for (int mi = 0; mi < 2; mi++)
        #pragma unroll
        for (int j = 0; j < 4; j++) { ae[mi][j] = make_float4(0,0,0,0); as_[mi][j] = make_float4(0,0,0,0); }

    #pragma unroll
    for (int ksh = 0; ksh < 5; ksh++) {
        uint4 fa0 = *(const uint4*)(uAe + (((rs_*2)   * 5 + ksh) << 7) + (lane << 2));
        uint4 fa1 = *(const uint4*)(uAe + (((rs_*2+1) * 5 + ksh) << 7) + (lane << 2));
        #pragma unroll
        for (int j = 0; j < 4; j++) {
            uint2 bb = W[((t0 * 4 + j) * 5 + ksh) * 32 + lane];
            mma16(ae[0][j], fa0, bb); mma16(ae[1][j], fa1, bb);
        }
        if (ksh < 4) {
            #pragma unroll
            for (int j = 0; j < 4; j++) {
                uint2 bb = W[2560 + ((t0 * 4 + j) * 4 + ksh) * 32 + lane];
                mma16(as_[0][j], fa0, bb); mma16(as_[1][j], fa1, bb);
            }
        }
    }
    __syncthreads();

    for (int c = tid; c < 2048; c += 256) cp16(Wc + c * 16, (const char*)pWsel16 + c * 16);
    CP_COMMIT();

    uint32_t* gseT = (uint32_t*)g_se + ((gr0 >> 6) << 12);
    #pragma unroll
    for (int mi = 0; mi < 2; mi++) {
        #pragma unroll
        for (int j = 0; j < 4; j++) {
            int c = t0 * 32 + j * 8 + 2 * tig;
            float b0e = bsa[c], b1e = bsa[c + 1];
            float b0s = bse[c], b1s = bse[c + 1];
            ae[mi][j]  = make_float4(lrelu(ae[mi][j].x + b0e), lrelu(ae[mi][j].y + b1e),
                                     lrelu(ae[mi][j].z + b0e), lrelu(ae[mi][j].w + b1e));
            as_[mi][j] = make_float4(lrelu(as_[mi][j].x + b0s), lrelu(as_[mi][j].y + b1s),
                                     lrelu(as_[mi][j].z + b0s), lrelu(as_[mi][j].w + b1s));
            st_frag16(uA16, rs_ * 2 + mi, t0 * 4 + j, tig, g, as_[mi][j]);
            st_frag16(gseT, rs_ * 2 + mi, t0 * 4 + j, tig, g, as_[mi][j]);
        }
    }
    CP_WAITG(0);
    __syncthreads();

    // ---- Phase 2: sel ----
    float4 ac[2][4], acv[2][4];
    #pragma unroll
    for (int mi = 0; mi < 2; mi++)
        #pragma unroll
        for (int j = 0; j < 4; j++) ac[mi][j] = make_float4(0,0,0,0);

    #pragma unroll
    for (int ksh = 0; ksh < 8; ksh++) {
        uint4 fa0 = ldfrag16(uA16, rs_ * 2,     ksh, lane);
        uint4 fa1 = ldfrag16(uA16, rs_ * 2 + 1, ksh, lane);
        #pragma unroll
        for (int j = 0; j < 4; j++) {
            uint2 bb = W[((t0 * 4 + j) * 8 + ksh) * 32 + lane];
            mma16(ac[0][j], fa0, bb); mma16(ac[1][j], fa1, bb);
        }
    }
    __syncthreads();

    for (int c = tid; c < 4096; c += 256) {
        const char* src = (c < 2048) ? (const char*)pWk16 + c * 16
                                     : (const char*)pWv16 + (c - 2048) * 16;
        cp16(Wc + c * 16, src);
    }
    CP_COMMIT();

    #pragma unroll
    for (int mi = 0; mi < 2; mi++) {
        #pragma unroll
        for (int j = 0; j < 4; j++) {
            int c = t0 * 32 + j * 8 + 2 * tig;
            size_t gr = gr0 + rs_ * 32 + mi * 16 + g;
            *(uint32_t*)&g_sel[gr * 128 + c]       = h2(ac[mi][j].x, ac[mi][j].y);
            *(uint32_t*)&g_sel[(gr + 8) * 128 + c] = h2(ac[mi][j].z, ac[mi][j].w);
            st_frag16(uA16, rs_ * 2 + mi, t0 * 4 + j, tig, g, ae[mi][j]);
        }
    }
    CP_WAITG(0);
    __syncthreads();

    // ---- Phase 3: key + val ----
    #pragma unroll
    for (int mi = 0; mi < 2; mi++)
        #pragma unroll
        for (int j = 0; j < 4; j++) { ac[mi][j] = make_float4(0,0,0,0); acv[mi][j] = make_float4(0,0,0,0); }

    #pragma unroll
    for (int ksh = 0; ksh < 8; ksh++) {
        uint4 fa0 = ldfrag16(uA16, rs_ * 2,     ksh, lane);
        uint4 fa1 = ldfrag16(uA16, rs_ * 2 + 1, ksh, lane);
        #pragma unroll
        for (int j = 0; j < 4; j++) {
            int bi = ((t0 * 4 + j) * 8 + ksh) * 32 + lane;
            uint2 bk = W[bi], bw = W[4096 + bi];
            mma16(ac[0][j],  fa0, bk); mma16(ac[1][j],  fa1, bk);
            mma16(acv[0][j], fa0, bw); mma16(acv[1][j], fa1, bw);
        }
    }

    #pragma unroll
    for (int mi = 0; mi < 2; mi++) {
        #pragma unroll
        for (int j = 0; j < 4; j++) {
            size_t gr = gr0 + rs_ * 32 + mi * 16 + g;
            int c = t0 * 32 + j * 8 + 2 * tig;
            *(uint32_t*)&g_key[gr * 128 + c]       = h2(ac[mi][j].x, ac[mi][j].y);
            *(uint32_t*)&g_key[(gr + 8) * 128 + c] = h2(ac[mi][j].z, ac[mi][j].w);
            float bb0 = bvv[c], bb1 = bvv[c + 1];
            *(uint32_t*)&g_val[gr * 128 + c]       = h2(lrelu(acv[mi][j].x + bb0), lrelu(acv[mi][j].y + bb1));
            *(uint32_t*)&g_val[(gr + 8) * 128 + c] = h2(lrelu(acv[mi][j].z + bb0), lrelu(acv[mi][j].w + bb1));
        }
    }
}

// ============================================================
// K3: attention — vectorized smem (float4 LDS/STS, register AV)
// ============================================================
constexpr int ASTR = 36;
__global__ void __launch_bounds__(256, 4)
k_attn()
{
    __shared__ float smem[8][3 * 8 * ASTR + 64];
    const int tid = threadIdx.x, warp = tid >> 5, lane = tid & 31;
    const int gid = blockIdx.x * 8 + warp;
    const int b = gid >> 2;
    const int p = gid & 3;

    float* selS = smem[warp];
    float* keyS = selS + 8 * ASTR;
    float* valS = keyS + 8 * ASTR;
    float* wS   = valS + 8 * ASTR;
    const float scale = 0.17677669529663687f;

    #pragma unroll
    for (int it = 0; it < 3; it++) {
        int idx = it * 32 + lane;
        int seg = idx >> 2, q4 = idx & 3;
        int arr = seg >> 3, i = seg & 7;
        const __half* gsrc = (arr == 0) ? g_sel : (arr == 1) ? g_key : g_val;
        uint4 v = *(const uint4*)(gsrc + ((size_t)i * B + b) * HID + p * D + q4 * 8);
        const __half2* hp = (const __half2*)&v;
        float2 f0 = __half22float2(hp[0]);
        float2 f1 = __half22float2(hp[1]);
        float2 f2 = __half22float2(hp[2]);
        float2 f3 = __half22float2(hp[3]);
        float* dst = selS + arr * (8 * ASTR) + i * ASTR + q4 * 8;
        *(float4*)dst       = make_float4(f0.x, f0.y, f1.x, f1.y);
        *(float4*)(dst + 4) = make_float4(f2.x, f2.y, f3.x, f3.y);
    }
    __syncwarp();

    const int i0 = lane >> 3, j = lane & 7;
    const float4* selR0 = (const float4*)(selS + i0 * ASTR);
    const float4* selR1 = (const float4*)(selS + (i0 + 4) * ASTR);
    const float4* keyR  = (const float4*)(keyS + j * ASTR);
    float acc0 = 0.f, acc1 = 0.f;
    #pragma unroll
    for (int d4 = 0; d4 < 8; d4++) {
        float4 kv = keyR[d4];
        float4 sa = selR0[d4], sb = selR1[d4];
        acc0 += sa.x * kv.x + sa.y * kv.y + sa.z * kv.z + sa.w * kv.w;
        acc1 += sb.x * kv.x + sb.y * kv.y + sb.z * kv.z + sb.w * kv.w;
    }
    acc0 *= scale; acc1 *= scale;
    if (i0 == j)     acc0 = -1e9f;
    if (i0 + 4 == j) acc1 = -1e9f;

    float m0 = acc0, m1 = acc1;
    #pragma unroll
    for (int o = 1; o < 8; o <<= 1) {
        m0 = fmaxf(m0, __shfl_xor_sync(FULLMASK, m0, o));
        m1 = fmaxf(m1, __shfl_xor_sync(FULLMASK, m1, o));
    }
    float e0 = __expf(acc0 - m0), e1 = __expf(acc1 - m1);
    float s0 = e0, s1 = e1;
    #pragma unroll
    for (int o = 1; o < 8; o <<= 1) {
        s0 += __shfl_xor_sync(FULLMASK, s0, o);
        s1 += __shfl_xor_sync(FULLMASK, s1, o);
    }
    wS[lane]      = __fdividef(e0, s0);
    wS[lane + 32] = __fdividef(e1, s1);
    __syncwarp();

    float v[8];
    #pragma unroll
    for (int jj = 0; jj < 8; jj++) v[jj] = valS[jj * ASTR + lane];
    #pragma unroll
    for (int ii = 0; ii < 8; ii++) {
        float4 wa = *(const float4*)(wS + ii * 8);
        float4 wb = *(const float4*)(wS + ii * 8 + 4);
        float o = wa.x * v[0] + wa.y * v[1] + wa.z * v[2] + wa.w * v[3]
                + wb.x * v[4] + wb.y * v[5] + wb.z * v[6] + wb.w * v[7];
        g_oth[((size_t)ii * B + b) * HID + p * D + lane] = __float2half_rn(o);
    }
}

// ============================================================
// K4: critic fp16 — TWO-GROUP staging (ph1 hidden under ph0 mma);
// selected-column layer 2
// ============================================================
constexpr int HSTR   = 132;   // f32 h stride
constexpr int OSTRU  = 68;    // ph1 A row stride in u32 (136 halves)
constexpr int CR_OFF_A   = 0;                             // 33792 (h reuses whole region)
constexpr int CR_OFF_B1  = 33792;                         // 2 x 32768
constexpr int CR_OFF_W2  = 99328;                         // 8448
constexpr int CR_OFF_B1S = 107776;
constexpr int CR_OFF_B2S = 108288;
constexpr int CR_OFF_AMX = 108352;
constexpr int SMEM_CRIT  = 108608;

__device__ __forceinline__ void crit_stageW16(uint2* B1, int buf, int ph, int n, int tid) {
    const uint2* base = pWc116[n];
    for (int cc = tid; cc < 2048; cc += 256) {
        int lanepair = cc & 15, ksl = (cc >> 4) & 7, n8 = cc >> 7;
        cp16(B1 + buf + (n8 * 8 + ksl) * 32 + lanepair * 2,
             base + ((n8 * 16 + ph * 8 + ksl) * 32 + lanepair * 2));
    }
}

__global__ void __launch_bounds__(256, 2)
k_crit(const float* __restrict__ a,
       const float* __restrict__ Bc1,
       const float* __restrict__ Wc2, const float* __restrict__ Bc2,
       float* __restrict__ out)
{
    extern __shared__ char smc[];
    uint32_t* uA = (uint32_t*)(smc + CR_OFF_A);
    uint32_t* uAo = uA + 4096;
    uint2*    B1 = (uint2*)(smc + CR_OFF_B1);
    float*    h  = (float*)(smc + CR_OFF_A);
    float*   w2t = (float*)(smc + CR_OFF_W2);
    float*   b1s = (float*)(smc + CR_OFF_B1S);
    float*   b2s = (float*)(smc + CR_OFF_B2S);
    int*     amx = (int*)(smc + CR_OFF_AMX);

    const int n = blockIdx.y, tid = threadIdx.x;
    const int w = tid >> 5, lane = tid & 31;
    const size_t row0 = (size_t)n * B + (size_t)blockIdx.x * 64;

    // group 1: ph0 needs (W1 half 0 + A_se)
    crit_stageW16(B1, 0, 0, n, tid);
    {
        const uint32_t* gseT = (const uint32_t*)g_se + ((row0 >> 6) << 12);
        for (int i = tid; i < 1024; i += 256) cp16(uA + i * 4, gseT + i * 4);
    }
    CP_COMMIT();
    // group 2: ph1 needs (W1 half 1 + A_oth) — stays in flight during ph0
    crit_stageW16(B1, 4096, 1, n, tid);
    for (int i = tid; i < 1024; i += 256) {
        int r = i >> 4, c = i & 15;
        cp16(uAo + r * OSTRU + c * 4,
             (const uint32_t*)g_oth + (row0 + r) * 64 + c * 4);
    }
    CP_COMMIT();

    // small fills overlap the async copies
    for (int i = tid; i < HID * AD; i += 256) {
        int k = i >> 4, o = i & 15;
        w2t[o * HSTR + k] = Wc2[n * HID * AD + k * AD + o];
    }
    if (tid < HID) b1s[tid] = Bc1[n * HID + tid];
    if (tid >= HID && tid < HID + AD) b2s[tid - HID] = Bc2[n * AD + (tid - HID)];
    if (tid < 64) {
        const float4* ap = (const float4*)(a + (row0 + tid) * AD);
        float4 q0 = ap[0], q1 = ap[1], q2 = ap[2], q3 = ap[3];
        float vals[16] = {q0.x,q0.y,q0.z,q0.w, q1.x,q1.y,q1.z,q1.w,
                          q2.x,q2.y,q2.z,q2.w, q3.x,q3.y,q3.z,q3.w};
        int bi = 0; float bvv = vals[0];
        #pragma unroll
        for (int i = 1; i < 16; i++) if (vals[i] > bvv) { bvv = vals[i]; bi = i; }
        amx[tid] = bi;
    }

    const int rs_ = w & 1, cq = w >> 1;
    const int g = lane >> 2, tig = lane & 3;

    float4 acc[2][4];
    #pragma unroll
    for (int mi = 0; mi < 2; mi++)
        #pragma unroll
        for (int j = 0; j < 4; j++) acc[mi][j] = make_float4(0,0,0,0);

    CP_WAITG(1);            // group 1 done; group 2 still in flight
    __syncthreads();

    // ---- ph0: se (fragment-order fp16) ----
    #pragma unroll
    for (int ksl = 0; ksl < 8; ksl++) {
        uint4 fa0 = ldfrag16(uA, rs_ * 2,     ksl, lane);
        uint4 fa1 = ldfrag16(uA, rs_ * 2 + 1, ksl, lane);
        #pragma unroll
        for (int j = 0; j < 4; j++) {
            uint2 bb = B1[((cq * 4 + j) * 8 + ksl) * 32 + lane];
            mma16(acc[0][j], fa0, bb); mma16(acc[1][j], fa1, bb);
        }
    }

    CP_WAITG(0);            // group 2 done
    __syncthreads();

    // ---- ph1: oth (row-major fp16) ----
    const int R0 = rs_ * 32 + g;
    #pragma unroll
    for (int ksl = 0; ksl < 8; ksl++) {
        uint4 fa0, fa1;
        {
            const uint32_t* b0 = uAo + R0 * OSTRU + ksl * 8 + tig;
            fa0 = make_uint4(b0[0], b0[8 * OSTRU], b0[4], b0[8 * OSTRU + 4]);
            const uint32_t* b1 = b0 + 16 * OSTRU;
            fa1 = make_uint4(b1[0], b1[8 * OSTRU], b1[4], b1[8 * OSTRU + 4]);
        }
        #pragma unroll
        for (int j = 0; j < 4; j++) {
            uint2 bb = B1[4096 + ((cq * 4 + j) * 8 + ksl) * 32 + lane];
            mma16(acc[0][j], fa0, bb); mma16(acc[1][j], fa1, bb);
        }
    }
    __syncthreads();        // all A reads done before h overwrites uA

    #pragma unroll
    for (int mi = 0; mi < 2; mi++) {
        #pragma unroll
        for (int j = 0; j < 4; j++) {
            int r = rs_ * 32 + mi * 16 + g;
            int c = cq * 32 + j * 8 + 2 * tig;
            float bb0 = b1s[c], bb1 = b1s[c + 1];
            *(float2*)&h[r * HSTR + c]       = make_float2(lrelu(acc[mi][j].x + bb0), lrelu(acc[mi][j].y + bb1));
            *(float2*)&h[(r + 8) * HSTR + c] = make_float2(lrelu(acc[mi][j].z + bb0), lrelu(acc[mi][j].w + bb1));
        }
    }
    __syncthreads();

    // layer 2: only the selected output column per row
    #pragma unroll
    for (int rr = 0; rr < 8; rr++) {
        const int r = w * 8 + rr;
        const int o = amx[r];
        float4 hv = *(const float4*)(h + r * HSTR + lane * 4);
        float4 wv = *(const float4*)(w2t + o * HSTR + lane * 4);
        float q = hv.x * wv.x + hv.y * wv.y + hv.z * wv.z + hv.w * wv.w;
        #pragma unroll
        for (int off = 16; off > 0; off >>= 1)
            q += __shfl_xor_sync(FULLMASK, q, off);
        if (lane == 0)
            out[(size_t)n * B + blockIdx.x * 64 + r] = q + b2s[o];
    }
}

// ============================================================
extern "C" void kernel_launch(void* const* d_in, const int* in_sizes, int n_in,
                              void* d_out, int out_size)
{
    const float* s    = (const float*)d_in[0];
    const float* a    = (const float*)d_in[1];
    const float* Wsa  = (const float*)d_in[2];
    const float* Bsa  = (const float*)d_in[3];
    const float* Wse  = (const float*)d_in[4];
    const float* Bse  = (const float*)d_in[5];
    const float* Wk   = (const float*)d_in[6];
    const float* Wsel = (const float*)d_in[7];
    const float* Wv   = (const float*)d_in[8];
    const float* bv   = (const float*)d_in[9];
    const float* Wc1  = (const float*)d_in[10];
    const float* Bc1  = (const float*)d_in[11];
    const float* Wc2  = (const float*)d_in[12];
    const float* Bc2  = (const float*)d_in[13];
    float* out = (float*)d_out;

    cudaFuncSetAttribute(k_front, cudaFuncAttributeMaxDynamicSharedMemorySize, SMEM_FRONT);
    cudaFuncSetAttribute(k_crit,  cudaFuncAttributeMaxDynamicSharedMemorySize, SMEM_CRIT);

    k_prep_stats<<<352, 512>>>(Wk, Wv, Wsel, Wsa, Wse, Wc1, s, a);
    k_front     <<<dim3(B / 64, NAG), 256, SMEM_FRONT>>>(s, a, Bsa, Bse, bv);
    k_attn      <<<dim3((HEADS * B) / 8), 256>>>();
    k_crit      <<<dim3(B / 64, NAG), 256, SMEM_CRIT>>>(a, Bc1, Wc2, Bc2, out);
}